// round 4
// baseline (speedup 1.0000x reference)
#include <cuda_runtime.h>
#include <math.h>

#define Bb 8
#define Nn 1024
#define Hh 1024
#define NHEADS 16
#define DHd 64
#define Mm (Bb*Nn)   // 8192

// Scratch (device globals: allocation-free rule)
__device__ float g_Q[(size_t)Bb*NHEADS*Nn*DHd];
__device__ float g_K[(size_t)Bb*NHEADS*Nn*DHd];
__device__ float g_V[(size_t)Bb*NHEADS*Nn*DHd];
__device__ float g_CTX[(size_t)Mm*Hh];
__device__ float g_Y[(size_t)Mm*Hh];

// ---------------------------------------------------------------------------
// GEMM: C = A[M=8192,K=1024] @ W[K=1024,N=1024] + bias (+resid)
// mode 0: store to head layout [B,h,N,dh], scaled by alpha (Q folds 1/8)
// mode 1: store row-major [M,H] with residual add
// Block tile 128x128, BK=16, 256 threads, 8x8 per thread.
// ---------------------------------------------------------------------------
__global__ void __launch_bounds__(256, 2) gemm_kernel(
    const float* __restrict__ A, const float* __restrict__ W,
    const float* __restrict__ bias, const float* __restrict__ resid,
    float* __restrict__ out, int mode, float alpha)
{
    __shared__ float As[16][132];
    __shared__ float Bs[16][132];

    const int tid = threadIdx.x;
    const int tx = tid & 15, ty = tid >> 4;
    const int rowBase = blockIdx.y * 128;
    const int colBase = blockIdx.x * 128;

    float acc[8][8];
#pragma unroll
    for (int i = 0; i < 8; i++)
#pragma unroll
        for (int j = 0; j < 8; j++) acc[i][j] = 0.f;

    for (int k0 = 0; k0 < 1024; k0 += 16) {
#pragma unroll
        for (int t = 0; t < 2; t++) {
            int f = tid + 256 * t;
            int ar = f >> 2, akq = (f & 3) << 2;
            float4 av = *(const float4*)(A + (size_t)(rowBase + ar) * 1024 + k0 + akq);
            As[akq + 0][ar] = av.x;
            As[akq + 1][ar] = av.y;
            As[akq + 2][ar] = av.z;
            As[akq + 3][ar] = av.w;
            int bkk = f >> 5, bc = (f & 31) << 2;
            *(float4*)&Bs[bkk][bc] =
                *(const float4*)(W + (size_t)(k0 + bkk) * 1024 + colBase + bc);
        }
        __syncthreads();
#pragma unroll
        for (int kk = 0; kk < 16; kk++) {
            float4 a0 = *(float4*)&As[kk][ty * 8];
            float4 a1 = *(float4*)&As[kk][ty * 8 + 4];
            float4 b0 = *(float4*)&Bs[kk][tx * 8];
            float4 b1 = *(float4*)&Bs[kk][tx * 8 + 4];
            float a[8] = {a0.x, a0.y, a0.z, a0.w, a1.x, a1.y, a1.z, a1.w};
            float b[8] = {b0.x, b0.y, b0.z, b0.w, b1.x, b1.y, b1.z, b1.w};
#pragma unroll
            for (int i = 0; i < 8; i++)
#pragma unroll
                for (int j = 0; j < 8; j++)
                    acc[i][j] = fmaf(a[i], b[j], acc[i][j]);
        }
        __syncthreads();
    }

    const int col0 = colBase + tx * 8;
    float4 bv0 = *(const float4*)(bias + col0);
    float4 bv1 = *(const float4*)(bias + col0 + 4);
    float bvv[8] = {bv0.x, bv0.y, bv0.z, bv0.w, bv1.x, bv1.y, bv1.z, bv1.w};

    if (mode == 0) {
        const int head = col0 >> 6;
        const int d0 = col0 & 63;
#pragma unroll
        for (int i = 0; i < 8; i++) {
            int row = rowBase + ty * 8 + i;
            int b_ = row >> 10, n_ = row & 1023;
            float* op = out + (((size_t)(b_ * NHEADS + head) * Nn + n_) * DHd + d0);
            float4 v0, v1;
            v0.x = (acc[i][0] + bvv[0]) * alpha;
            v0.y = (acc[i][1] + bvv[1]) * alpha;
            v0.z = (acc[i][2] + bvv[2]) * alpha;
            v0.w = (acc[i][3] + bvv[3]) * alpha;
            v1.x = (acc[i][4] + bvv[4]) * alpha;
            v1.y = (acc[i][5] + bvv[5]) * alpha;
            v1.z = (acc[i][6] + bvv[6]) * alpha;
            v1.w = (acc[i][7] + bvv[7]) * alpha;
            *(float4*)op = v0;
            *(float4*)(op + 4) = v1;
        }
    } else {
#pragma unroll
        for (int i = 0; i < 8; i++) {
            int row = rowBase + ty * 8 + i;
            const float* rp = resid + (size_t)row * 1024 + col0;
            float4 r0 = *(const float4*)rp;
            float4 r1 = *(const float4*)(rp + 4);
            float4 v0, v1;
            v0.x = acc[i][0] + bvv[0] + r0.x;
            v0.y = acc[i][1] + bvv[1] + r0.y;
            v0.z = acc[i][2] + bvv[2] + r0.z;
            v0.w = acc[i][3] + bvv[3] + r0.w;
            v1.x = acc[i][4] + bvv[4] + r1.x;
            v1.y = acc[i][5] + bvv[5] + r1.y;
            v1.z = acc[i][6] + bvv[6] + r1.z;
            v1.w = acc[i][7] + bvv[7] + r1.w;
            float* op = out + (size_t)row * 1024 + col0;
            *(float4*)op = v0;
            *(float4*)(op + 4) = v1;
        }
    }
}

// ---------------------------------------------------------------------------
// Flash-style attention. Block = (q-tile of 64, bh). 256 threads (16x16).
// Thread computes 4q x 4k scores, then 4q x 4d output columns.
// K stored d-major in smem with XOR swizzle (conflict-free LDS.128).
// Scale (1/8) already folded into Q. mask==0 -> -1e9 (matches reference).
// ---------------------------------------------------------------------------
#define ATTN_SMEM ((64*68 + 64*64 + 64*68 + 64*68) * 4)

__global__ void __launch_bounds__(256) attn_kernel(const int* __restrict__ mask)
{
    extern __shared__ float sm[];
    float* Qs  = sm;                 // [64][68]
    float* Kst = sm + 64 * 68;       // [64][64]  d-major, swizzled
    float* Vs  = Kst + 64 * 64;      // [64][68]
    float* Ss  = Vs + 64 * 68;       // [64][68]

    const int bh = blockIdx.y;
    const int b = bh >> 4;
    const int h = bh & 15;
    const int qBase = blockIdx.x * 64;
    const int tid = threadIdx.x;
    const int tx = tid & 15, ty = tid >> 4;

    const float* Qp = g_Q + (size_t)bh * Nn * DHd;
    const float* Kp = g_K + (size_t)bh * Nn * DHd;
    const float* Vp = g_V + (size_t)bh * Nn * DHd;
    const int*   mp = mask + (size_t)b * Nn * Nn;

#pragma unroll
    for (int t = 0; t < 4; t++) {
        int f = tid + 256 * t;
        int r = f >> 4, c = (f & 15) << 2;
        *(float4*)&Qs[r * 68 + c] =
            *(const float4*)(Qp + (size_t)(qBase + r) * DHd + c);
    }

    float m[4], l[4], o[4][4];
#pragma unroll
    for (int i = 0; i < 4; i++) {
        m[i] = -1e30f;
        l[i] = 0.f;
#pragma unroll
        for (int j = 0; j < 4; j++) o[i][j] = 0.f;
    }

    for (int kt = 0; kt < Nn; kt += 64) {
        __syncthreads();
        // Load K (transposed+swizzled) and V tiles
#pragma unroll
        for (int t = 0; t < 4; t++) {
            int f = tid + 256 * t;
            int r = f >> 4, c4 = f & 15;
            float4 kv = *(const float4*)(Kp + (size_t)(kt + r) * DHd + (c4 << 2));
            float4 vv = *(const float4*)(Vp + (size_t)(kt + r) * DHd + (c4 << 2));
            *(float4*)&Vs[r * 68 + (c4 << 2)] = vv;
            int kg = r >> 2, klo = r & 3;
            int sg = ((kg ^ c4) << 2) + klo;   // swizzle group by d-group (=c4)
            Kst[(c4 * 4 + 0) * 64 + sg] = kv.x;
            Kst[(c4 * 4 + 1) * 64 + sg] = kv.y;
            Kst[(c4 * 4 + 2) * 64 + sg] = kv.z;
            Kst[(c4 * 4 + 3) * 64 + sg] = kv.w;
        }
        __syncthreads();

        // S = Q K^T for thread's 4q x 4k
        float s[4][4];
#pragma unroll
        for (int i = 0; i < 4; i++)
#pragma unroll
            for (int j = 0; j < 4; j++) s[i][j] = 0.f;

#pragma unroll
        for (int d = 0; d < 64; d += 4) {
            int dg = d >> 2;
            float qf[4][4];
#pragma unroll
            for (int i = 0; i < 4; i++) {
                float4 q4 = *(float4*)&Qs[(ty * 4 + i) * 68 + d];
                qf[i][0] = q4.x; qf[i][1] = q4.y; qf[i][2] = q4.z; qf[i][3] = q4.w;
            }
            float kf[4][4];
#pragma unroll
            for (int dd = 0; dd < 4; dd++) {
                float4 k4 = *(float4*)&Kst[(d + dd) * 64 + ((tx ^ dg) << 2)];
                kf[dd][0] = k4.x; kf[dd][1] = k4.y; kf[dd][2] = k4.z; kf[dd][3] = k4.w;
            }
#pragma unroll
            for (int i = 0; i < 4; i++)
#pragma unroll
                for (int dd = 0; dd < 4; dd++)
#pragma unroll
                    for (int j = 0; j < 4; j++)
                        s[i][j] = fmaf(qf[i][dd], kf[dd][j], s[i][j]);
        }

        // mask + online softmax
#pragma unroll
        for (int i = 0; i < 4; i++) {
            int q = qBase + ty * 4 + i;
            int4 mv = *(const int4*)(mp + (size_t)q * Nn + kt + (tx << 2));
            if (mv.x == 0) s[i][0] = -1e9f;
            if (mv.y == 0) s[i][1] = -1e9f;
            if (mv.z == 0) s[i][2] = -1e9f;
            if (mv.w == 0) s[i][3] = -1e9f;

            float mx = fmaxf(fmaxf(s[i][0], s[i][1]), fmaxf(s[i][2], s[i][3]));
#pragma unroll
            for (int off = 1; off < 16; off <<= 1)
                mx = fmaxf(mx, __shfl_xor_sync(0xffffffffu, mx, off));
            float mn = fmaxf(m[i], mx);
            float corr = __expf(m[i] - mn);
            float p0 = __expf(s[i][0] - mn);
            float p1 = __expf(s[i][1] - mn);
            float p2 = __expf(s[i][2] - mn);
            float p3 = __expf(s[i][3] - mn);
            *(float4*)&Ss[(ty * 4 + i) * 68 + (tx << 2)] = make_float4(p0, p1, p2, p3);
            float rs = p0 + p1 + p2 + p3;
#pragma unroll
            for (int off = 1; off < 16; off <<= 1)
                rs += __shfl_xor_sync(0xffffffffu, rs, off);
            l[i] = l[i] * corr + rs;
            m[i] = mn;
#pragma unroll
            for (int j = 0; j < 4; j++) o[i][j] *= corr;
        }
        __syncthreads();

        // O += P V for thread's 4q x 4d
#pragma unroll
        for (int k = 0; k < 64; k += 4) {
            float sf[4][4];
#pragma unroll
            for (int i = 0; i < 4; i++) {
                float4 s4 = *(float4*)&Ss[(ty * 4 + i) * 68 + k];
                sf[i][0] = s4.x; sf[i][1] = s4.y; sf[i][2] = s4.z; sf[i][3] = s4.w;
            }
            float vf[4][4];
#pragma unroll
            for (int kk = 0; kk < 4; kk++) {
                float4 v4 = *(float4*)&Vs[(k + kk) * 68 + (tx << 2)];
                vf[kk][0] = v4.x; vf[kk][1] = v4.y; vf[kk][2] = v4.z; vf[kk][3] = v4.w;
            }
#pragma unroll
            for (int i = 0; i < 4; i++)
#pragma unroll
                for (int kk = 0; kk < 4; kk++)
#pragma unroll
                    for (int j = 0; j < 4; j++)
                        o[i][j] = fmaf(sf[i][kk], vf[kk][j], o[i][j]);
        }
    }

#pragma unroll
    for (int i = 0; i < 4; i++) {
        float inv = 1.f / l[i];
        int n_ = qBase + ty * 4 + i;
        float4 ov = make_float4(o[i][0] * inv, o[i][1] * inv, o[i][2] * inv, o[i][3] * inv);
        *(float4*)(g_CTX + ((size_t)(b * Nn + n_) * Hh) + h * DHd + (tx << 2)) = ov;
    }
}

// ---------------------------------------------------------------------------
// LayerNorm (eps=1e-12) over g_Y rows + gather the two per-batch rows.
// out layout: [ context_layer (8192*1024) | high_emo (8*1024) | perspective (8*1024) ]
// ---------------------------------------------------------------------------
__global__ void __launch_bounds__(256) ln_kernel(
    const float* __restrict__ gamma, const float* __restrict__ beta,
    const int* __restrict__ conv_len, float* __restrict__ out)
{
    const int row = blockIdx.x;
    const int tid = threadIdx.x;
    const float* yr = g_Y + (size_t)row * Hh;
    float4 x = *(const float4*)(yr + (tid << 2));

    __shared__ float red[8];
    __shared__ float mu_sh, rstd_sh;

    float s1 = x.x + x.y + x.z + x.w;
#pragma unroll
    for (int off = 16; off; off >>= 1) s1 += __shfl_xor_sync(0xffffffffu, s1, off);
    int w = tid >> 5, lane = tid & 31;
    if (lane == 0) red[w] = s1;
    __syncthreads();
    if (tid == 0) {
        float t = 0.f;
#pragma unroll
        for (int i = 0; i < 8; i++) t += red[i];
        mu_sh = t * (1.f / 1024.f);
    }
    __syncthreads();
    float mu = mu_sh;
    float d0 = x.x - mu, d1 = x.y - mu, d2 = x.z - mu, d3 = x.w - mu;
    float s2 = d0 * d0 + d1 * d1 + d2 * d2 + d3 * d3;
#pragma unroll
    for (int off = 16; off; off >>= 1) s2 += __shfl_xor_sync(0xffffffffu, s2, off);
    if (lane == 0) red[w] = s2;
    __syncthreads();
    if (tid == 0) {
        float t = 0.f;
#pragma unroll
        for (int i = 0; i < 8; i++) t += red[i];
        rstd_sh = rsqrtf(t * (1.f / 1024.f) + 1e-12f);
    }
    __syncthreads();
    float rstd = rstd_sh;

    float4 g = *(const float4*)(gamma + (tid << 2));
    float4 be = *(const float4*)(beta + (tid << 2));
    float4 r;
    r.x = d0 * rstd * g.x + be.x;
    r.y = d1 * rstd * g.y + be.y;
    r.z = d2 * rstd * g.z + be.z;
    r.w = d3 * rstd * g.w + be.w;
    *(float4*)(out + (size_t)row * Hh + (tid << 2)) = r;

    int b_ = row >> 10, n_ = row & 1023;
    int base = 6 * conv_len[b_];
    if (n_ == base + 3)   // high_emo_states
        *(float4*)(out + (size_t)Mm * Hh + (size_t)b_ * Hh + (tid << 2)) = r;
    if (n_ == base + 2)   // perspective_taking
        *(float4*)(out + (size_t)Mm * Hh + (size_t)Bb * Hh + (size_t)b_ * Hh + (tid << 2)) = r;
}

// ---------------------------------------------------------------------------
extern "C" void kernel_launch(void* const* d_in, const int* in_sizes, int n_in,
                              void* d_out, int out_size)
{
    const float* hidden    = (const float*)d_in[0];
    const int*   role_mask = (const int*)d_in[1];
    const int*   conv_len  = (const int*)d_in[2];
    const float* Wq = (const float*)d_in[3];
    const float* bq = (const float*)d_in[4];
    const float* Wk = (const float*)d_in[5];
    const float* bk = (const float*)d_in[6];
    const float* Wv = (const float*)d_in[7];
    const float* bv = (const float*)d_in[8];
    const float* Wo = (const float*)d_in[9];
    const float* bo = (const float*)d_in[10];
    const float* gamma = (const float*)d_in[11];
    const float* beta  = (const float*)d_in[12];
    float* out = (float*)d_out;

    float *Qp, *Kp, *Vp, *Cp, *Yp;
    cudaGetSymbolAddress((void**)&Qp, g_Q);
    cudaGetSymbolAddress((void**)&Kp, g_K);
    cudaGetSymbolAddress((void**)&Vp, g_V);
    cudaGetSymbolAddress((void**)&Cp, g_CTX);
    cudaGetSymbolAddress((void**)&Yp, g_Y);

    dim3 gg(Hh / 128, Mm / 128);
    gemm_kernel<<<gg, 256>>>(hidden, Wq, bq, nullptr, Qp, 0, 0.125f);
    gemm_kernel<<<gg, 256>>>(hidden, Wk, bk, nullptr, Kp, 0, 1.0f);
    gemm_kernel<<<gg, 256>>>(hidden, Wv, bv, nullptr, Vp, 0, 1.0f);

    cudaFuncSetAttribute(attn_kernel, cudaFuncAttributeMaxDynamicSharedMemorySize, ATTN_SMEM);
    attn_kernel<<<dim3(Nn / 64, Bb * NHEADS), 256, ATTN_SMEM>>>(role_mask);

    gemm_kernel<<<gg, 256>>>(Cp, Wo, bo, hidden, Yp, 1, 1.0f);
    ln_kernel<<<Mm, 256>>>(gamma, beta, conv_len, out);
}

// round 7
// speedup vs baseline: 1.6494x; 1.6494x over previous
#include <cuda_runtime.h>
#include <math.h>
#include <stdint.h>

#define Bb 8
#define Nn 1024
#define Hh 1024
#define NHEADS 16
#define DHd 64
#define Mm (Bb*Nn)   // 8192

// Scratch (device globals: allocation-free rule)
__device__ float g_Q[(size_t)Bb*NHEADS*Nn*DHd];
__device__ float g_K[(size_t)Bb*NHEADS*Nn*DHd];
__device__ float g_V[(size_t)Bb*NHEADS*Nn*DHd];
__device__ float g_CTX[(size_t)Mm*Hh];
__device__ float g_Y[(size_t)Mm*Hh];
__device__ float g_WqT[(size_t)Hh*Hh];
__device__ float g_WkT[(size_t)Hh*Hh];
__device__ float g_WvT[(size_t)Hh*Hh];
__device__ float g_WoT[(size_t)Hh*Hh];

// ===========================================================================
// tf32 helpers (arch-suffix-free PTX: works on plain sm_103 target)
// ===========================================================================
__device__ __forceinline__ uint32_t f2tf32(float f) {
    uint32_t u;
    asm("cvt.rna.tf32.f32 %0, %1;" : "=r"(u) : "f"(f));
    return u;
}

__device__ __forceinline__ void mma_tf32_16x8x8(
    float& c0, float& c1, float& c2, float& c3,
    uint32_t a0, uint32_t a1, uint32_t a2, uint32_t a3,
    uint32_t b0, uint32_t b1)
{
    asm volatile(
        "mma.sync.aligned.m16n8k8.row.col.f32.tf32.tf32.f32 "
        "{%0,%1,%2,%3}, {%4,%5,%6,%7}, {%8,%9}, {%0,%1,%2,%3};"
        : "+f"(c0), "+f"(c1), "+f"(c2), "+f"(c3)
        : "r"(a0), "r"(a1), "r"(a2), "r"(a3), "r"(b0), "r"(b1));
}

// ===========================================================================
// 32x32 transpose: out[n,k] = in[k,n]  (1024x1024)
// ===========================================================================
__global__ void __launch_bounds__(256) transpose1024(
    const float* __restrict__ in, float* __restrict__ out)
{
    __shared__ float t[32][33];
    int tx = threadIdx.x, ty = threadIdx.y;
    int xi = blockIdx.x * 32 + tx;
    int y0 = blockIdx.y * 32;
#pragma unroll
    for (int i = ty; i < 32; i += 8)
        t[i][tx] = in[(size_t)(y0 + i) * 1024 + xi];
    __syncthreads();
    int xo = y0 + tx;
    int yo0 = blockIdx.x * 32;
#pragma unroll
    for (int i = ty; i < 32; i += 8)
        out[(size_t)(yo0 + i) * 1024 + xo] = t[tx][i];
}

// ===========================================================================
// tf32 mma.sync GEMM: out = A[8192,1024] @ Bt[1024,1024]^T (+bias, +resid)
// CTA tile 128x128, BK=32. 8 warps, warp tile 64x32 (4 m16-tiles x 4 n8-tiles).
// A row-major frags, B col-major frags (Bt is [n][k] row-major = col-major B).
// mode 0: store head layout [B,h,N,dh], (acc+bias)*alpha
// mode 1: store row-major, acc+bias+resid
// ===========================================================================
#define SMS 36   // smem row stride (floats): bank = (4*row+col)%32, conflict-free

__global__ void __launch_bounds__(256) tf32_gemm_mma(
    const float* __restrict__ A, const float* __restrict__ Bt,
    const float* __restrict__ bias, const float* __restrict__ resid,
    float* __restrict__ out, int mode, float alpha)
{
    __shared__ uint32_t As[128 * SMS];
    __shared__ uint32_t Bs[128 * SMS];

    const int tid = threadIdx.x;
    const int lane = tid & 31, wid = tid >> 5;
    const int warpM = wid & 1;          // 2 along M
    const int warpN = wid >> 1;         // 4 along N
    const int gid = lane >> 2;          // 0..7
    const int q = lane & 3;             // 0..3
    const int rowBase = blockIdx.y * 128;
    const int colBase = blockIdx.x * 128;

    const float* Abase = A  + (size_t)rowBase * 1024;
    const float* Bbase = Bt + (size_t)colBase * 1024;

    float acc[4][4][4];
#pragma unroll
    for (int mt = 0; mt < 4; mt++)
#pragma unroll
        for (int nt = 0; nt < 4; nt++)
#pragma unroll
            for (int e = 0; e < 4; e++) acc[mt][nt][e] = 0.f;

    const int r_ = tid >> 3;            // 0..31? no: tid in 0..255, idx below
    (void)r_;

    float4 pa[4], pb[4];
    // load chunk 0
#pragma unroll
    for (int i = 0; i < 4; i++) {
        int idx = tid + 256 * i;
        int r = idx >> 3, g = idx & 7;
        pa[i] = *(const float4*)(Abase + (size_t)r * 1024 + g * 4);
        pb[i] = *(const float4*)(Bbase + (size_t)r * 1024 + g * 4);
    }
#pragma unroll
    for (int i = 0; i < 4; i++) {
        int idx = tid + 256 * i;
        int r = idx >> 3, g = idx & 7;
        uint32_t* pA = &As[r * SMS + g * 4];
        uint32_t* pB = &Bs[r * SMS + g * 4];
        pA[0] = f2tf32(pa[i].x); pA[1] = f2tf32(pa[i].y);
        pA[2] = f2tf32(pa[i].z); pA[3] = f2tf32(pa[i].w);
        pB[0] = f2tf32(pb[i].x); pB[1] = f2tf32(pb[i].y);
        pB[2] = f2tf32(pb[i].z); pB[3] = f2tf32(pb[i].w);
    }
    __syncthreads();

    for (int c = 0; c < 32; c++) {
        // prefetch next chunk to regs
        if (c < 31) {
            const float* An = Abase + (c + 1) * 32;
            const float* Bn = Bbase + (c + 1) * 32;
#pragma unroll
            for (int i = 0; i < 4; i++) {
                int idx = tid + 256 * i;
                int r = idx >> 3, g = idx & 7;
                pa[i] = *(const float4*)(An + (size_t)r * 1024 + g * 4);
                pb[i] = *(const float4*)(Bn + (size_t)r * 1024 + g * 4);
            }
        }
        // compute 4 k8-steps from smem
#pragma unroll
        for (int ks = 0; ks < 4; ks++) {
            const int c0 = ks * 8 + q;
            uint32_t af[4][4];
#pragma unroll
            for (int mt = 0; mt < 4; mt++) {
                int r0 = warpM * 64 + mt * 16 + gid;
                af[mt][0] = As[r0 * SMS + c0];
                af[mt][1] = As[(r0 + 8) * SMS + c0];
                af[mt][2] = As[r0 * SMS + c0 + 4];
                af[mt][3] = As[(r0 + 8) * SMS + c0 + 4];
            }
            uint32_t bf[4][2];
#pragma unroll
            for (int nt = 0; nt < 4; nt++) {
                int n0 = warpN * 32 + nt * 8 + gid;
                bf[nt][0] = Bs[n0 * SMS + ks * 8 + q];
                bf[nt][1] = Bs[n0 * SMS + ks * 8 + q + 4];
            }
#pragma unroll
            for (int mt = 0; mt < 4; mt++)
#pragma unroll
                for (int nt = 0; nt < 4; nt++)
                    mma_tf32_16x8x8(acc[mt][nt][0], acc[mt][nt][1],
                                    acc[mt][nt][2], acc[mt][nt][3],
                                    af[mt][0], af[mt][1], af[mt][2], af[mt][3],
                                    bf[nt][0], bf[nt][1]);
        }
        __syncthreads();
        if (c < 31) {
#pragma unroll
            for (int i = 0; i < 4; i++) {
                int idx = tid + 256 * i;
                int r = idx >> 3, g = idx & 7;
                uint32_t* pA = &As[r * SMS + g * 4];
                uint32_t* pB = &Bs[r * SMS + g * 4];
                pA[0] = f2tf32(pa[i].x); pA[1] = f2tf32(pa[i].y);
                pA[2] = f2tf32(pa[i].z); pA[3] = f2tf32(pa[i].w);
                pB[0] = f2tf32(pb[i].x); pB[1] = f2tf32(pb[i].y);
                pB[2] = f2tf32(pb[i].z); pB[3] = f2tf32(pb[i].w);
            }
            __syncthreads();
        }
    }

    // Epilogue: each (mt,nt) tile: rows row0,row0+8; cols gcol,gcol+1 (float2)
#pragma unroll
    for (int mt = 0; mt < 4; mt++) {
        const int row0 = rowBase + warpM * 64 + mt * 16 + gid;
        const int row1 = row0 + 8;
#pragma unroll
        for (int nt = 0; nt < 4; nt++) {
            const int gcol = colBase + warpN * 32 + nt * 8 + 2 * q;
            const float b0 = bias[gcol], b1 = bias[gcol + 1];
            if (mode == 0) {
                const int head = gcol >> 6, d0 = gcol & 63;
#pragma unroll
                for (int rr = 0; rr < 2; rr++) {
                    const int row = rr ? row1 : row0;
                    const int b_ = row >> 10, n_ = row & 1023;
                    float* op = out + (((size_t)(b_ * NHEADS + head) * Nn + n_) * DHd + d0);
                    float2 v;
                    v.x = (acc[mt][nt][rr * 2 + 0] + b0) * alpha;
                    v.y = (acc[mt][nt][rr * 2 + 1] + b1) * alpha;
                    *(float2*)op = v;
                }
            } else {
#pragma unroll
                for (int rr = 0; rr < 2; rr++) {
                    const int row = rr ? row1 : row0;
                    const float2 rv = *(const float2*)(resid + (size_t)row * 1024 + gcol);
                    float2 v;
                    v.x = acc[mt][nt][rr * 2 + 0] + b0 + rv.x;
                    v.y = acc[mt][nt][rr * 2 + 1] + b1 + rv.y;
                    *(float2*)(out + (size_t)row * 1024 + gcol) = v;
                }
            }
        }
    }
}

// ---------------------------------------------------------------------------
// Flash-style attention (unchanged). Block = (q-tile of 64, bh). 256 threads.
// ---------------------------------------------------------------------------
#define ATTN_SMEM ((64*68 + 64*64 + 64*68 + 64*68) * 4)

__global__ void __launch_bounds__(256) attn_kernel(const int* __restrict__ mask)
{
    extern __shared__ float sm[];
    float* Qs  = sm;                 // [64][68]
    float* Kst = sm + 64 * 68;       // [64][64]  d-major, swizzled
    float* Vs  = Kst + 64 * 64;      // [64][68]
    float* Ss  = Vs + 64 * 68;       // [64][68]

    const int bh = blockIdx.y;
    const int b = bh >> 4;
    const int h = bh & 15;
    const int qBase = blockIdx.x * 64;
    const int tid = threadIdx.x;
    const int tx = tid & 15, ty = tid >> 4;

    const float* Qp = g_Q + (size_t)bh * Nn * DHd;
    const float* Kp = g_K + (size_t)bh * Nn * DHd;
    const float* Vp = g_V + (size_t)bh * Nn * DHd;
    const int*   mp = mask + (size_t)b * Nn * Nn;

#pragma unroll
    for (int t = 0; t < 4; t++) {
        int f = tid + 256 * t;
        int r = f >> 4, c = (f & 15) << 2;
        *(float4*)&Qs[r * 68 + c] =
            *(const float4*)(Qp + (size_t)(qBase + r) * DHd + c);
    }

    float m[4], l[4], o[4][4];
#pragma unroll
    for (int i = 0; i < 4; i++) {
        m[i] = -1e30f;
        l[i] = 0.f;
#pragma unroll
        for (int j = 0; j < 4; j++) o[i][j] = 0.f;
    }

    for (int kt = 0; kt < Nn; kt += 64) {
        __syncthreads();
#pragma unroll
        for (int t = 0; t < 4; t++) {
            int f = tid + 256 * t;
            int r = f >> 4, c4 = f & 15;
            float4 kv = *(const float4*)(Kp + (size_t)(kt + r) * DHd + (c4 << 2));
            float4 vv = *(const float4*)(Vp + (size_t)(kt + r) * DHd + (c4 << 2));
            *(float4*)&Vs[r * 68 + (c4 << 2)] = vv;
            int kg = r >> 2, klo = r & 3;
            int sg = ((kg ^ c4) << 2) + klo;
            Kst[(c4 * 4 + 0) * 64 + sg] = kv.x;
            Kst[(c4 * 4 + 1) * 64 + sg] = kv.y;
            Kst[(c4 * 4 + 2) * 64 + sg] = kv.z;
            Kst[(c4 * 4 + 3) * 64 + sg] = kv.w;
        }
        __syncthreads();

        float s[4][4];
#pragma unroll
        for (int i = 0; i < 4; i++)
#pragma unroll
            for (int j = 0; j < 4; j++) s[i][j] = 0.f;

#pragma unroll
        for (int d = 0; d < 64; d += 4) {
            int dg = d >> 2;
            float qf[4][4];
#pragma unroll
            for (int i = 0; i < 4; i++) {
                float4 q4 = *(float4*)&Qs[(ty * 4 + i) * 68 + d];
                qf[i][0] = q4.x; qf[i][1] = q4.y; qf[i][2] = q4.z; qf[i][3] = q4.w;
            }
            float kf[4][4];
#pragma unroll
            for (int dd = 0; dd < 4; dd++) {
                float4 k4 = *(float4*)&Kst[(d + dd) * 64 + ((tx ^ dg) << 2)];
                kf[dd][0] = k4.x; kf[dd][1] = k4.y; kf[dd][2] = k4.z; kf[dd][3] = k4.w;
            }
#pragma unroll
            for (int i = 0; i < 4; i++)
#pragma unroll
                for (int dd = 0; dd < 4; dd++)
#pragma unroll
                    for (int j = 0; j < 4; j++)
                        s[i][j] = fmaf(qf[i][dd], kf[dd][j], s[i][j]);
        }

#pragma unroll
        for (int i = 0; i < 4; i++) {
            int q = qBase + ty * 4 + i;
            int4 mv = *(const int4*)(mp + (size_t)q * Nn + kt + (tx << 2));
            if (mv.x == 0) s[i][0] = -1e9f;
            if (mv.y == 0) s[i][1] = -1e9f;
            if (mv.z == 0) s[i][2] = -1e9f;
            if (mv.w == 0) s[i][3] = -1e9f;

            float mx = fmaxf(fmaxf(s[i][0], s[i][1]), fmaxf(s[i][2], s[i][3]));
#pragma unroll
            for (int off = 1; off < 16; off <<= 1)
                mx = fmaxf(mx, __shfl_xor_sync(0xffffffffu, mx, off));
            float mn = fmaxf(m[i], mx);
            float corr = __expf(m[i] - mn);
            float p0 = __expf(s[i][0] - mn);
            float p1 = __expf(s[i][1] - mn);
            float p2 = __expf(s[i][2] - mn);
            float p3 = __expf(s[i][3] - mn);
            *(float4*)&Ss[(ty * 4 + i) * 68 + (tx << 2)] = make_float4(p0, p1, p2, p3);
            float rs = p0 + p1 + p2 + p3;
#pragma unroll
            for (int off = 1; off < 16; off <<= 1)
                rs += __shfl_xor_sync(0xffffffffu, rs, off);
            l[i] = l[i] * corr + rs;
            m[i] = mn;
#pragma unroll
            for (int j = 0; j < 4; j++) o[i][j] *= corr;
        }
        __syncthreads();

#pragma unroll
        for (int k = 0; k < 64; k += 4) {
            float sf[4][4];
#pragma unroll
            for (int i = 0; i < 4; i++) {
                float4 s4 = *(float4*)&Ss[(ty * 4 + i) * 68 + k];
                sf[i][0] = s4.x; sf[i][1] = s4.y; sf[i][2] = s4.z; sf[i][3] = s4.w;
            }
            float vf[4][4];
#pragma unroll
            for (int kk = 0; kk < 4; kk++) {
                float4 v4 = *(float4*)&Vs[(k + kk) * 68 + (tx << 2)];
                vf[kk][0] = v4.x; vf[kk][1] = v4.y; vf[kk][2] = v4.z; vf[kk][3] = v4.w;
            }
#pragma unroll
            for (int i = 0; i < 4; i++)
#pragma unroll
                for (int kk = 0; kk < 4; kk++)
#pragma unroll
                    for (int j = 0; j < 4; j++)
                        o[i][j] = fmaf(sf[i][kk], vf[kk][j], o[i][j]);
        }
    }

#pragma unroll
    for (int i = 0; i < 4; i++) {
        float inv = 1.f / l[i];
        int n_ = qBase + ty * 4 + i;
        float4 ov = make_float4(o[i][0] * inv, o[i][1] * inv, o[i][2] * inv, o[i][3] * inv);
        *(float4*)(g_CTX + ((size_t)(b * Nn + n_) * Hh) + h * DHd + (tx << 2)) = ov;
    }
}

// ---------------------------------------------------------------------------
// LayerNorm (eps=1e-12) over g_Y rows + gather the two per-batch rows.
// ---------------------------------------------------------------------------
__global__ void __launch_bounds__(256) ln_kernel(
    const float* __restrict__ gamma, const float* __restrict__ beta,
    const int* __restrict__ conv_len, float* __restrict__ out)
{
    const int row = blockIdx.x;
    const int tid = threadIdx.x;
    const float* yr = g_Y + (size_t)row * Hh;
    float4 x = *(const float4*)(yr + (tid << 2));

    __shared__ float red[8];
    __shared__ float mu_sh, rstd_sh;

    float s1 = x.x + x.y + x.z + x.w;
#pragma unroll
    for (int off = 16; off; off >>= 1) s1 += __shfl_xor_sync(0xffffffffu, s1, off);
    int w = tid >> 5, lane = tid & 31;
    if (lane == 0) red[w] = s1;
    __syncthreads();
    if (tid == 0) {
        float t = 0.f;
#pragma unroll
        for (int i = 0; i < 8; i++) t += red[i];
        mu_sh = t * (1.f / 1024.f);
    }
    __syncthreads();
    float mu = mu_sh;
    float d0 = x.x - mu, d1 = x.y - mu, d2 = x.z - mu, d3 = x.w - mu;
    float s2 = d0 * d0 + d1 * d1 + d2 * d2 + d3 * d3;
#pragma unroll
    for (int off = 16; off; off >>= 1) s2 += __shfl_xor_sync(0xffffffffu, s2, off);
    if (lane == 0) red[w] = s2;
    __syncthreads();
    if (tid == 0) {
        float t = 0.f;
#pragma unroll
        for (int i = 0; i < 8; i++) t += red[i];
        rstd_sh = rsqrtf(t * (1.f / 1024.f) + 1e-12f);
    }
    __syncthreads();
    float rstd = rstd_sh;

    float4 g = *(const float4*)(gamma + (tid << 2));
    float4 be = *(const float4*)(beta + (tid << 2));
    float4 r;
    r.x = d0 * rstd * g.x + be.x;
    r.y = d1 * rstd * g.y + be.y;
    r.z = d2 * rstd * g.z + be.z;
    r.w = d3 * rstd * g.w + be.w;
    *(float4*)(out + (size_t)row * Hh + (tid << 2)) = r;

    int b_ = row >> 10, n_ = row & 1023;
    int base = 6 * conv_len[b_];
    if (n_ == base + 3)
        *(float4*)(out + (size_t)Mm * Hh + (size_t)b_ * Hh + (tid << 2)) = r;
    if (n_ == base + 2)
        *(float4*)(out + (size_t)Mm * Hh + (size_t)Bb * Hh + (size_t)b_ * Hh + (tid << 2)) = r;
}

// ---------------------------------------------------------------------------
extern "C" void kernel_launch(void* const* d_in, const int* in_sizes, int n_in,
                              void* d_out, int out_size)
{
    const float* hidden    = (const float*)d_in[0];
    const int*   role_mask = (const int*)d_in[1];
    const int*   conv_len  = (const int*)d_in[2];
    const float* Wq = (const float*)d_in[3];
    const float* bq = (const float*)d_in[4];
    const float* Wk = (const float*)d_in[5];
    const float* bk = (const float*)d_in[6];
    const float* Wv = (const float*)d_in[7];
    const float* bv = (const float*)d_in[8];
    const float* Wo = (const float*)d_in[9];
    const float* bo = (const float*)d_in[10];
    const float* gamma = (const float*)d_in[11];
    const float* beta  = (const float*)d_in[12];
    float* out = (float*)d_out;

    float *Qp, *Kp, *Vp, *Cp, *Yp, *WqT, *WkT, *WvT, *WoT;
    cudaGetSymbolAddress((void**)&Qp, g_Q);
    cudaGetSymbolAddress((void**)&Kp, g_K);
    cudaGetSymbolAddress((void**)&Vp, g_V);
    cudaGetSymbolAddress((void**)&Cp, g_CTX);
    cudaGetSymbolAddress((void**)&Yp, g_Y);
    cudaGetSymbolAddress((void**)&WqT, g_WqT);
    cudaGetSymbolAddress((void**)&WkT, g_WkT);
    cudaGetSymbolAddress((void**)&WvT, g_WvT);
    cudaGetSymbolAddress((void**)&WoT, g_WoT);

    dim3 tb(32, 8), tg(32, 32);
    transpose1024<<<tg, tb>>>(Wq, WqT);
    transpose1024<<<tg, tb>>>(Wk, WkT);
    transpose1024<<<tg, tb>>>(Wv, WvT);
    transpose1024<<<tg, tb>>>(Wo, WoT);

    dim3 gg(Hh / 128, Mm / 128);
    tf32_gemm_mma<<<gg, 256>>>(hidden, WqT, bq, nullptr, Qp, 0, 0.125f);
    tf32_gemm_mma<<<gg, 256>>>(hidden, WkT, bk, nullptr, Kp, 0, 1.0f);
    tf32_gemm_mma<<<gg, 256>>>(hidden, WvT, bv, nullptr, Vp, 0, 1.0f);

    cudaFuncSetAttribute(attn_kernel, cudaFuncAttributeMaxDynamicSharedMemorySize, ATTN_SMEM);
    attn_kernel<<<dim3(Nn / 64, Bb * NHEADS), 256, ATTN_SMEM>>>(role_mask);

    tf32_gemm_mma<<<gg, 256>>>(Cp, WoT, bo, hidden, Yp, 1, 1.0f);
    ln_kernel<<<Mm, 256>>>(gamma, beta, conv_len, out);
}

// round 8
// speedup vs baseline: 2.4480x; 1.4842x over previous
#include <cuda_runtime.h>
#include <math.h>
#include <stdint.h>

#define Bb 8
#define Nn 1024
#define Hh 1024
#define NHEADS 16
#define DHd 64
#define Mm (Bb*Nn)   // 8192

// Scratch (device globals: allocation-free rule)
__device__ float g_Q[(size_t)Bb*NHEADS*Nn*DHd];
__device__ float g_K[(size_t)Bb*NHEADS*Nn*DHd];
__device__ float g_V[(size_t)Bb*NHEADS*Nn*DHd];
__device__ float g_CTX[(size_t)Mm*Hh];
__device__ float g_Y[(size_t)Mm*Hh];

// ===========================================================================
// tf32 helpers (arch-suffix-free PTX: works on plain sm_103 target)
// ===========================================================================
__device__ __forceinline__ uint32_t f2tf32(float f) {
    uint32_t u;
    asm("cvt.rna.tf32.f32 %0, %1;" : "=r"(u) : "f"(f));
    return u;
}

__device__ __forceinline__ void mma_tf32_16x8x8(
    float& c0, float& c1, float& c2, float& c3,
    uint32_t a0, uint32_t a1, uint32_t a2, uint32_t a3,
    uint32_t b0, uint32_t b1)
{
    asm volatile(
        "mma.sync.aligned.m16n8k8.row.col.f32.tf32.tf32.f32 "
        "{%0,%1,%2,%3}, {%4,%5,%6,%7}, {%8,%9}, {%0,%1,%2,%3};"
        : "+f"(c0), "+f"(c1), "+f"(c2), "+f"(c3)
        : "r"(a0), "r"(a1), "r"(a2), "r"(a3), "r"(b0), "r"(b1));
}

// ===========================================================================
// tf32 mma.sync GEMM: out = A[8192,1024] @ W[1024,1024] (+bias, +resid)
// CTA tile 128x128, BK=32. 8 warps, warp tile 64x32 (4 m16 x 4 n8).
// W read directly (row-major [k][n]) -> no pre-transpose needed.
// mode 0: store head layout [B,h,N,dh], (acc+bias)*alpha
// mode 1: store row-major, acc+bias+resid
// ===========================================================================
#define SMSA 36    // As stride: fragment banks 4*gid+q -> conflict-free
#define SMSB 136   // Bs stride: fragment banks 8*q+gid -> conflict-free

__global__ void __launch_bounds__(256) tf32_gemm_mma(
    const float* __restrict__ A, const float* __restrict__ W,
    const float* __restrict__ bias, const float* __restrict__ resid,
    float* __restrict__ out, int mode, float alpha)
{
    __shared__ uint32_t As[128 * SMSA];
    __shared__ uint32_t Bs[32 * SMSB];

    const int tid = threadIdx.x;
    const int lane = tid & 31, wid = tid >> 5;
    const int warpM = wid & 1;          // 2 along M
    const int warpN = wid >> 1;         // 4 along N
    const int gid = lane >> 2;          // 0..7
    const int q = lane & 3;             // 0..3
    const int rowBase = blockIdx.y * 128;
    const int colBase = blockIdx.x * 128;

    const float* Abase = A + (size_t)rowBase * 1024;

    float acc[4][4][4];
#pragma unroll
    for (int mt = 0; mt < 4; mt++)
#pragma unroll
        for (int nt = 0; nt < 4; nt++)
#pragma unroll
            for (int e = 0; e < 4; e++) acc[mt][nt][e] = 0.f;

    float4 pa[4], pb[4];
    // load chunk 0
#pragma unroll
    for (int i = 0; i < 4; i++) {
        int idx = tid + 256 * i;
        int r = idx >> 3, g = idx & 7;
        pa[i] = *(const float4*)(Abase + (size_t)r * 1024 + g * 4);
        int rb = idx >> 5, cb = idx & 31;
        pb[i] = *(const float4*)(W + (size_t)rb * 1024 + colBase + cb * 4);
    }
#pragma unroll
    for (int i = 0; i < 4; i++) {
        int idx = tid + 256 * i;
        int r = idx >> 3, g = idx & 7;
        uint32_t* pA = &As[r * SMSA + g * 4];
        pA[0] = f2tf32(pa[i].x); pA[1] = f2tf32(pa[i].y);
        pA[2] = f2tf32(pa[i].z); pA[3] = f2tf32(pa[i].w);
        int rb = idx >> 5, cb = idx & 31;
        uint32_t* pB = &Bs[rb * SMSB + cb * 4];
        pB[0] = f2tf32(pb[i].x); pB[1] = f2tf32(pb[i].y);
        pB[2] = f2tf32(pb[i].z); pB[3] = f2tf32(pb[i].w);
    }
    __syncthreads();

    for (int c = 0; c < 32; c++) {
        // prefetch next chunk to regs
        if (c < 31) {
            const float* An = Abase + (c + 1) * 32;
            const float* Wn = W + (size_t)(c + 1) * 32 * 1024 + colBase;
#pragma unroll
            for (int i = 0; i < 4; i++) {
                int idx = tid + 256 * i;
                int r = idx >> 3, g = idx & 7;
                pa[i] = *(const float4*)(An + (size_t)r * 1024 + g * 4);
                int rb = idx >> 5, cb = idx & 31;
                pb[i] = *(const float4*)(Wn + (size_t)rb * 1024 + cb * 4);
            }
        }
        // compute 4 k8-steps from smem
#pragma unroll
        for (int ks = 0; ks < 4; ks++) {
            const int c0 = ks * 8 + q;
            uint32_t af[4][4];
#pragma unroll
            for (int mt = 0; mt < 4; mt++) {
                int r0 = warpM * 64 + mt * 16 + gid;
                af[mt][0] = As[r0 * SMSA + c0];
                af[mt][1] = As[(r0 + 8) * SMSA + c0];
                af[mt][2] = As[r0 * SMSA + c0 + 4];
                af[mt][3] = As[(r0 + 8) * SMSA + c0 + 4];
            }
            uint32_t bf[4][2];
#pragma unroll
            for (int nt = 0; nt < 4; nt++) {
                int n0 = warpN * 32 + nt * 8 + gid;
                bf[nt][0] = Bs[(ks * 8 + q) * SMSB + n0];
                bf[nt][1] = Bs[(ks * 8 + q + 4) * SMSB + n0];
            }
#pragma unroll
            for (int mt = 0; mt < 4; mt++)
#pragma unroll
                for (int nt = 0; nt < 4; nt++)
                    mma_tf32_16x8x8(acc[mt][nt][0], acc[mt][nt][1],
                                    acc[mt][nt][2], acc[mt][nt][3],
                                    af[mt][0], af[mt][1], af[mt][2], af[mt][3],
                                    bf[nt][0], bf[nt][1]);
        }
        __syncthreads();
        if (c < 31) {
#pragma unroll
            for (int i = 0; i < 4; i++) {
                int idx = tid + 256 * i;
                int r = idx >> 3, g = idx & 7;
                uint32_t* pA = &As[r * SMSA + g * 4];
                pA[0] = f2tf32(pa[i].x); pA[1] = f2tf32(pa[i].y);
                pA[2] = f2tf32(pa[i].z); pA[3] = f2tf32(pa[i].w);
                int rb = idx >> 5, cb = idx & 31;
                uint32_t* pB = &Bs[rb * SMSB + cb * 4];
                pB[0] = f2tf32(pb[i].x); pB[1] = f2tf32(pb[i].y);
                pB[2] = f2tf32(pb[i].z); pB[3] = f2tf32(pb[i].w);
            }
            __syncthreads();
        }
    }

    // Epilogue: rows row0,row0+8; cols gcol,gcol+1 (float2)
#pragma unroll
    for (int mt = 0; mt < 4; mt++) {
        const int row0 = rowBase + warpM * 64 + mt * 16 + gid;
        const int row1 = row0 + 8;
#pragma unroll
        for (int nt = 0; nt < 4; nt++) {
            const int gcol = colBase + warpN * 32 + nt * 8 + 2 * q;
            const float b0 = bias[gcol], b1 = bias[gcol + 1];
            if (mode == 0) {
                const int head = gcol >> 6, d0 = gcol & 63;
#pragma unroll
                for (int rr = 0; rr < 2; rr++) {
                    const int row = rr ? row1 : row0;
                    const int b_ = row >> 10, n_ = row & 1023;
                    float* op = out + (((size_t)(b_ * NHEADS + head) * Nn + n_) * DHd + d0);
                    float2 v;
                    v.x = (acc[mt][nt][rr * 2 + 0] + b0) * alpha;
                    v.y = (acc[mt][nt][rr * 2 + 1] + b1) * alpha;
                    *(float2*)op = v;
                }
            } else {
#pragma unroll
                for (int rr = 0; rr < 2; rr++) {
                    const int row = rr ? row1 : row0;
                    const float2 rv = *(const float2*)(resid + (size_t)row * 1024 + gcol);
                    float2 v;
                    v.x = acc[mt][nt][rr * 2 + 0] + b0 + rv.x;
                    v.y = acc[mt][nt][rr * 2 + 1] + b1 + rv.y;
                    *(float2*)(out + (size_t)row * 1024 + gcol) = v;
                }
            }
        }
    }
}

// ===========================================================================
// Tensor-core flash attention. CTA = 128 threads (4 warps), q-tile 64.
// Warp w owns q-rows [w*16, w*16+16) -> softmax is warp-local (4-lane shfl).
// S = Q K^T via m16n8k8 tf32; P through smem as tf32 bits; O += P V.
// Strides: Q/K/P 68 (banks 4*gid+q), V 72 (banks 8*q+gid) -> conflict-free.
// ===========================================================================
#define QS_STR 68
#define VS_STR 72
#define ATTN_SMEM ((64*QS_STR*3 + 64*VS_STR) * 4)   // Qs,Ks,MPs + Vs = 70656B

__global__ void __launch_bounds__(128) attn_mma(const int* __restrict__ mask)
{
    extern __shared__ uint32_t smu[];
    uint32_t* Qs = smu;                    // [64][68] tf32
    uint32_t* Ks = Qs + 64 * QS_STR;       // [64][68] tf32 (k-pos rows, d cols)
    uint32_t* Vs = Ks + 64 * QS_STR;       // [64][72] tf32 (k-pos rows, d cols)
    float*   MPs = (float*)(Vs + 64 * VS_STR);  // [64][68] mask, then P (tf32 bits)

    const int bh = blockIdx.y;
    const int b = bh >> 4;
    const int h = bh & 15;
    const int qBase = blockIdx.x * 64;
    const int tid = threadIdx.x;
    const int lane = tid & 31, wid = tid >> 5;
    const int gid = lane >> 2, q = lane & 3;
    const int r0 = wid * 16 + gid;         // this thread's first local q-row
    const int r1 = r0 + 8;

    const float* Qp = g_Q + (size_t)bh * Nn * DHd;
    const float* Kp = g_K + (size_t)bh * Nn * DHd;
    const float* Vp = g_V + (size_t)bh * Nn * DHd;
    const int*   mp = mask + (size_t)b * Nn * Nn;

    // Load Q tile (64x64) as tf32
#pragma unroll
    for (int i = 0; i < 8; i++) {
        int idx = tid + 128 * i;
        int r = idx >> 4, c4 = idx & 15;
        float4 v = *(const float4*)(Qp + (size_t)(qBase + r) * DHd + c4 * 4);
        uint32_t* p = &Qs[r * QS_STR + c4 * 4];
        p[0] = f2tf32(v.x); p[1] = f2tf32(v.y); p[2] = f2tf32(v.z); p[3] = f2tf32(v.w);
    }

    float m0 = -1e30f, m1 = -1e30f, l0 = 0.f, l1 = 0.f;
    float o[8][4];
#pragma unroll
    for (int nt = 0; nt < 8; nt++)
#pragma unroll
        for (int e = 0; e < 4; e++) o[nt][e] = 0.f;

    for (int kt = 0; kt < Nn; kt += 64) {
        __syncthreads();
        // Load K, V, mask tiles
#pragma unroll
        for (int i = 0; i < 8; i++) {
            int idx = tid + 128 * i;
            int r = idx >> 4, c4 = idx & 15;
            float4 kv = *(const float4*)(Kp + (size_t)(kt + r) * DHd + c4 * 4);
            float4 vv = *(const float4*)(Vp + (size_t)(kt + r) * DHd + c4 * 4);
            uint32_t* pk = &Ks[r * QS_STR + c4 * 4];
            pk[0] = f2tf32(kv.x); pk[1] = f2tf32(kv.y); pk[2] = f2tf32(kv.z); pk[3] = f2tf32(kv.w);
            uint32_t* pv = &Vs[r * VS_STR + c4 * 4];
            pv[0] = f2tf32(vv.x); pv[1] = f2tf32(vv.y); pv[2] = f2tf32(vv.z); pv[3] = f2tf32(vv.w);
            int4 mv = *(const int4*)(mp + (size_t)(qBase + r) * Nn + kt + c4 * 4);
            float4 mf = make_float4((float)mv.x, (float)mv.y, (float)mv.z, (float)mv.w);
            *(float4*)&MPs[r * QS_STR + c4 * 4] = mf;
        }
        __syncthreads();

        // S = Q K^T : 8 n8-tiles, 8 k-steps
        float s[8][4];
#pragma unroll
        for (int nt = 0; nt < 8; nt++)
#pragma unroll
            for (int e = 0; e < 4; e++) s[nt][e] = 0.f;

#pragma unroll
        for (int ks = 0; ks < 8; ks++) {
            const int c0 = ks * 8 + q;
            uint32_t a0 = Qs[r0 * QS_STR + c0];
            uint32_t a1 = Qs[r1 * QS_STR + c0];
            uint32_t a2 = Qs[r0 * QS_STR + c0 + 4];
            uint32_t a3 = Qs[r1 * QS_STR + c0 + 4];
#pragma unroll
            for (int nt = 0; nt < 8; nt++) {
                int np = nt * 8 + gid;
                uint32_t b0 = Ks[np * QS_STR + c0];
                uint32_t b1 = Ks[np * QS_STR + c0 + 4];
                mma_tf32_16x8x8(s[nt][0], s[nt][1], s[nt][2], s[nt][3],
                                a0, a1, a2, a3, b0, b1);
            }
        }

        // mask (replace with -1e9 where mask==0)
#pragma unroll
        for (int nt = 0; nt < 8; nt++) {
            float2 mv0 = *(float2*)&MPs[r0 * QS_STR + nt * 8 + 2 * q];
            float2 mv1 = *(float2*)&MPs[r1 * QS_STR + nt * 8 + 2 * q];
            s[nt][0] = (mv0.x != 0.f) ? s[nt][0] : -1e9f;
            s[nt][1] = (mv0.y != 0.f) ? s[nt][1] : -1e9f;
            s[nt][2] = (mv1.x != 0.f) ? s[nt][2] : -1e9f;
            s[nt][3] = (mv1.y != 0.f) ? s[nt][3] : -1e9f;
        }

        // online softmax (rows r0, r1) — reduce over 4 q-lanes
        float mx0 = -1e30f, mx1 = -1e30f;
#pragma unroll
        for (int nt = 0; nt < 8; nt++) {
            mx0 = fmaxf(mx0, fmaxf(s[nt][0], s[nt][1]));
            mx1 = fmaxf(mx1, fmaxf(s[nt][2], s[nt][3]));
        }
        mx0 = fmaxf(mx0, __shfl_xor_sync(0xffffffffu, mx0, 1));
        mx0 = fmaxf(mx0, __shfl_xor_sync(0xffffffffu, mx0, 2));
        mx1 = fmaxf(mx1, __shfl_xor_sync(0xffffffffu, mx1, 1));
        mx1 = fmaxf(mx1, __shfl_xor_sync(0xffffffffu, mx1, 2));
        float mn0 = fmaxf(m0, mx0), mn1 = fmaxf(m1, mx1);
        float corr0 = __expf(m0 - mn0), corr1 = __expf(m1 - mn1);

        float rs0 = 0.f, rs1 = 0.f;
#pragma unroll
        for (int nt = 0; nt < 8; nt++) {
            float p0 = __expf(s[nt][0] - mn0);
            float p1 = __expf(s[nt][1] - mn0);
            float p2 = __expf(s[nt][2] - mn1);
            float p3 = __expf(s[nt][3] - mn1);
            rs0 += p0 + p1;
            rs1 += p2 + p3;
            // store P as tf32 bit patterns (read back as mma A-operand)
            float2 w0, w1;
            w0.x = __uint_as_float(f2tf32(p0)); w0.y = __uint_as_float(f2tf32(p1));
            w1.x = __uint_as_float(f2tf32(p2)); w1.y = __uint_as_float(f2tf32(p3));
            *(float2*)&MPs[r0 * QS_STR + nt * 8 + 2 * q] = w0;
            *(float2*)&MPs[r1 * QS_STR + nt * 8 + 2 * q] = w1;
        }
        rs0 += __shfl_xor_sync(0xffffffffu, rs0, 1);
        rs0 += __shfl_xor_sync(0xffffffffu, rs0, 2);
        rs1 += __shfl_xor_sync(0xffffffffu, rs1, 1);
        rs1 += __shfl_xor_sync(0xffffffffu, rs1, 2);
        l0 = l0 * corr0 + rs0;
        l1 = l1 * corr1 + rs1;
        m0 = mn0; m1 = mn1;
#pragma unroll
        for (int nt = 0; nt < 8; nt++) {
            o[nt][0] *= corr0; o[nt][1] *= corr0;
            o[nt][2] *= corr1; o[nt][3] *= corr1;
        }
        __syncwarp();

        // O += P V : A = P rows (warp-local), B = V[kpos][d]
#pragma unroll
        for (int ks = 0; ks < 8; ks++) {
            const int c0 = ks * 8 + q;
            uint32_t a0 = __float_as_uint(MPs[r0 * QS_STR + c0]);
            uint32_t a1 = __float_as_uint(MPs[r1 * QS_STR + c0]);
            uint32_t a2 = __float_as_uint(MPs[r0 * QS_STR + c0 + 4]);
            uint32_t a3 = __float_as_uint(MPs[r1 * QS_STR + c0 + 4]);
#pragma unroll
            for (int nt = 0; nt < 8; nt++) {
                int nd = nt * 8 + gid;
                uint32_t b0 = Vs[(ks * 8 + q) * VS_STR + nd];
                uint32_t b1 = Vs[(ks * 8 + q + 4) * VS_STR + nd];
                mma_tf32_16x8x8(o[nt][0], o[nt][1], o[nt][2], o[nt][3],
                                a0, a1, a2, a3, b0, b1);
            }
        }
    }

    // normalize + store to g_CTX [b][n][h*64+d]
    const float inv0 = 1.f / l0, inv1 = 1.f / l1;
    float* cbase = g_CTX + ((size_t)(b * Nn + qBase) * Hh) + h * DHd;
#pragma unroll
    for (int nt = 0; nt < 8; nt++) {
        const int d0 = nt * 8 + 2 * q;
        float2 v0, v1;
        v0.x = o[nt][0] * inv0; v0.y = o[nt][1] * inv0;
        v1.x = o[nt][2] * inv1; v1.y = o[nt][3] * inv1;
        *(float2*)(cbase + (size_t)r0 * Hh + d0) = v0;
        *(float2*)(cbase + (size_t)r1 * Hh + d0) = v1;
    }
}

// ---------------------------------------------------------------------------
// LayerNorm (eps=1e-12) over g_Y rows + gather the two per-batch rows.
// ---------------------------------------------------------------------------
__global__ void __launch_bounds__(256) ln_kernel(
    const float* __restrict__ gamma, const float* __restrict__ beta,
    const int* __restrict__ conv_len, float* __restrict__ out)
{
    const int row = blockIdx.x;
    const int tid = threadIdx.x;
    const float* yr = g_Y + (size_t)row * Hh;
    float4 x = *(const float4*)(yr + (tid << 2));

    __shared__ float red[8];
    __shared__ float mu_sh, rstd_sh;

    float s1 = x.x + x.y + x.z + x.w;
#pragma unroll
    for (int off = 16; off; off >>= 1) s1 += __shfl_xor_sync(0xffffffffu, s1, off);
    int w = tid >> 5, lane = tid & 31;
    if (lane == 0) red[w] = s1;
    __syncthreads();
    if (tid == 0) {
        float t = 0.f;
#pragma unroll
        for (int i = 0; i < 8; i++) t += red[i];
        mu_sh = t * (1.f / 1024.f);
    }
    __syncthreads();
    float mu = mu_sh;
    float d0 = x.x - mu, d1 = x.y - mu, d2 = x.z - mu, d3 = x.w - mu;
    float s2 = d0 * d0 + d1 * d1 + d2 * d2 + d3 * d3;
#pragma unroll
    for (int off = 16; off; off >>= 1) s2 += __shfl_xor_sync(0xffffffffu, s2, off);
    if (lane == 0) red[w] = s2;
    __syncthreads();
    if (tid == 0) {
        float t = 0.f;
#pragma unroll
        for (int i = 0; i < 8; i++) t += red[i];
        rstd_sh = rsqrtf(t * (1.f / 1024.f) + 1e-12f);
    }
    __syncthreads();
    float rstd = rstd_sh;

    float4 g = *(const float4*)(gamma + (tid << 2));
    float4 be = *(const float4*)(beta + (tid << 2));
    float4 r;
    r.x = d0 * rstd * g.x + be.x;
    r.y = d1 * rstd * g.y + be.y;
    r.z = d2 * rstd * g.z + be.z;
    r.w = d3 * rstd * g.w + be.w;
    *(float4*)(out + (size_t)row * Hh + (tid << 2)) = r;

    int b_ = row >> 10, n_ = row & 1023;
    int base = 6 * conv_len[b_];
    if (n_ == base + 3)
        *(float4*)(out + (size_t)Mm * Hh + (size_t)b_ * Hh + (tid << 2)) = r;
    if (n_ == base + 2)
        *(float4*)(out + (size_t)Mm * Hh + (size_t)Bb * Hh + (size_t)b_ * Hh + (tid << 2)) = r;
}

// ---------------------------------------------------------------------------
extern "C" void kernel_launch(void* const* d_in, const int* in_sizes, int n_in,
                              void* d_out, int out_size)
{
    const float* hidden    = (const float*)d_in[0];
    const int*   role_mask = (const int*)d_in[1];
    const int*   conv_len  = (const int*)d_in[2];
    const float* Wq = (const float*)d_in[3];
    const float* bq = (const float*)d_in[4];
    const float* Wk = (const float*)d_in[5];
    const float* bk = (const float*)d_in[6];
    const float* Wv = (const float*)d_in[7];
    const float* bv = (const float*)d_in[8];
    const float* Wo = (const float*)d_in[9];
    const float* bo = (const float*)d_in[10];
    const float* gamma = (const float*)d_in[11];
    const float* beta  = (const float*)d_in[12];
    float* out = (float*)d_out;

    float *Qp, *Kp, *Vp, *Cp, *Yp;
    cudaGetSymbolAddress((void**)&Qp, g_Q);
    cudaGetSymbolAddress((void**)&Kp, g_K);
    cudaGetSymbolAddress((void**)&Vp, g_V);
    cudaGetSymbolAddress((void**)&Cp, g_CTX);
    cudaGetSymbolAddress((void**)&Yp, g_Y);

    dim3 gg(Hh / 128, Mm / 128);
    tf32_gemm_mma<<<gg, 256>>>(hidden, Wq, bq, nullptr, Qp, 0, 0.125f);
    tf32_gemm_mma<<<gg, 256>>>(hidden, Wk, bk, nullptr, Kp, 0, 1.0f);
    tf32_gemm_mma<<<gg, 256>>>(hidden, Wv, bv, nullptr, Vp, 0, 1.0f);

    cudaFuncSetAttribute(attn_mma, cudaFuncAttributeMaxDynamicSharedMemorySize, ATTN_SMEM);
    attn_mma<<<dim3(Nn / 64, Bb * NHEADS), 128, ATTN_SMEM>>>(role_mask);

    tf32_gemm_mma<<<gg, 256>>>(Cp, Wo, bo, hidden, Yp, 1, 1.0f);
    ln_kernel<<<Mm, 256>>>(gamma, beta, conv_len, out);
}

// round 11
// speedup vs baseline: 2.7983x; 1.1431x over previous
#include <cuda_runtime.h>
#include <math.h>
#include <stdint.h>

#define Bb 8
#define Nn 1024
#define Hh 1024
#define NHEADS 16
#define DHd 64
#define Mm (Bb*Nn)   // 8192

// Scratch (device globals: allocation-free rule)
__device__ float g_Q[(size_t)Bb*NHEADS*Nn*DHd];
__device__ float g_K[(size_t)Bb*NHEADS*Nn*DHd];
__device__ float g_V[(size_t)Bb*NHEADS*Nn*DHd];
__device__ float g_CTX[(size_t)Mm*Hh];
__device__ float g_Y[(size_t)Mm*Hh];

// ===========================================================================
// helpers (arch-suffix-free PTX: works on plain sm_103 target)
// ===========================================================================
__device__ __forceinline__ uint32_t smem_to_u32(const void* p) {
    uint32_t a;
    asm("{ .reg .u64 t; cvta.to.shared.u64 t, %1; cvt.u32.u64 %0, t; }"
        : "=r"(a) : "l"(p));
    return a;
}
__device__ __forceinline__ void cp_async16(uint32_t dst, const void* src) {
    asm volatile("cp.async.ca.shared.global [%0], [%1], 16;" :: "r"(dst), "l"(src));
}
#define CP_COMMIT() asm volatile("cp.async.commit_group;")

// mma tf32: raw fp32 bits fed directly (HW uses the tf32 subset of the bits)
__device__ __forceinline__ void mma_tf32_16x8x8(
    float& c0, float& c1, float& c2, float& c3,
    uint32_t a0, uint32_t a1, uint32_t a2, uint32_t a3,
    uint32_t b0, uint32_t b1)
{
    asm volatile(
        "mma.sync.aligned.m16n8k8.row.col.f32.tf32.tf32.f32 "
        "{%0,%1,%2,%3}, {%4,%5,%6,%7}, {%8,%9}, {%0,%1,%2,%3};"
        : "+f"(c0), "+f"(c1), "+f"(c2), "+f"(c3)
        : "r"(a0), "r"(a1), "r"(a2), "r"(a3), "r"(b0), "r"(b1));
}

// ===========================================================================
// tf32 mma.sync GEMM with cp.async double buffering.
// out = A[8192,1024] @ W[1024,1024] (+bias, +resid)
// CTA tile 128x128, BK=32, 8 warps (warp tile 64x32 = 4 m16 x 4 n8).
// mode 0: store head layout [B,h,N,dh], (acc+bias)*alpha
// mode 1: store row-major, acc+bias+resid
// ===========================================================================
#define SMSA 36
#define SMSB 136
#define A_STAGE (128*SMSA)
#define B_STAGE (32*SMSB)
#define GEMM_SMEM ((2*A_STAGE + 2*B_STAGE)*4)   // 71680 B

__global__ void __launch_bounds__(256) tf32_gemm_mma(
    const float* __restrict__ A, const float* __restrict__ W,
    const float* __restrict__ bias, const float* __restrict__ resid,
    float* __restrict__ out, int mode, float alpha)
{
    extern __shared__ uint32_t gsm[];
    const uint32_t smb = smem_to_u32(gsm);

    const int tid = threadIdx.x;
    const int lane = tid & 31, wid = tid >> 5;
    const int warpM = wid & 1;
    const int warpN = wid >> 1;
    const int gid = lane >> 2;
    const int q = lane & 3;
    const int rowBase = blockIdx.y * 128;
    const int colBase = blockIdx.x * 128;

    const float* Abase = A + (size_t)rowBase * 1024;

    auto issue = [&](int c, int s) {
#pragma unroll
        for (int i = 0; i < 4; i++) {
            int idx = tid + 256 * i;
            int r = idx >> 3, g = idx & 7;
            cp_async16(smb + (uint32_t)(s * A_STAGE + r * SMSA + g * 4) * 4,
                       Abase + (size_t)r * 1024 + c * 32 + g * 4);
        }
#pragma unroll
        for (int i = 0; i < 4; i++) {
            int idx = tid + 256 * i;
            int r = idx >> 5, gg = idx & 31;
            cp_async16(smb + (uint32_t)(2 * A_STAGE + s * B_STAGE + r * SMSB + gg * 4) * 4,
                       W + (size_t)(c * 32 + r) * 1024 + colBase + gg * 4);
        }
        CP_COMMIT();
    };

    float acc[4][4][4];
#pragma unroll
    for (int mt = 0; mt < 4; mt++)
#pragma unroll
        for (int nt = 0; nt < 4; nt++)
#pragma unroll
            for (int e = 0; e < 4; e++) acc[mt][nt][e] = 0.f;

    issue(0, 0);
    issue(1, 1);

    for (int c = 0; c < 32; c++) {
        if (c < 31) asm volatile("cp.async.wait_group 1;");
        else        asm volatile("cp.async.wait_group 0;");
        __syncthreads();

        const uint32_t* As = gsm + (c & 1) * A_STAGE;
        const uint32_t* Bs = gsm + 2 * A_STAGE + (c & 1) * B_STAGE;

#pragma unroll
        for (int ks = 0; ks < 4; ks++) {
            const int c0 = ks * 8 + q;
            uint32_t af[4][4];
#pragma unroll
            for (int mt = 0; mt < 4; mt++) {
                int r0 = warpM * 64 + mt * 16 + gid;
                af[mt][0] = As[r0 * SMSA + c0];
                af[mt][1] = As[(r0 + 8) * SMSA + c0];
                af[mt][2] = As[r0 * SMSA + c0 + 4];
                af[mt][3] = As[(r0 + 8) * SMSA + c0 + 4];
            }
            uint32_t bf[4][2];
#pragma unroll
            for (int nt = 0; nt < 4; nt++) {
                int n0 = warpN * 32 + nt * 8 + gid;
                bf[nt][0] = Bs[(ks * 8 + q) * SMSB + n0];
                bf[nt][1] = Bs[(ks * 8 + q + 4) * SMSB + n0];
            }
#pragma unroll
            for (int mt = 0; mt < 4; mt++)
#pragma unroll
                for (int nt = 0; nt < 4; nt++)
                    mma_tf32_16x8x8(acc[mt][nt][0], acc[mt][nt][1],
                                    acc[mt][nt][2], acc[mt][nt][3],
                                    af[mt][0], af[mt][1], af[mt][2], af[mt][3],
                                    bf[nt][0], bf[nt][1]);
        }
        __syncthreads();
        if (c + 2 < 32) issue(c + 2, c & 1);
    }

    // Epilogue: rows row0,row0+8; cols gcol,gcol+1 (float2)
#pragma unroll
    for (int mt = 0; mt < 4; mt++) {
        const int row0 = rowBase + warpM * 64 + mt * 16 + gid;
        const int row1 = row0 + 8;
#pragma unroll
        for (int nt = 0; nt < 4; nt++) {
            const int gcol = colBase + warpN * 32 + nt * 8 + 2 * q;
            const float b0 = bias[gcol], b1 = bias[gcol + 1];
            if (mode == 0) {
                const int head = gcol >> 6, d0 = gcol & 63;
#pragma unroll
                for (int rr = 0; rr < 2; rr++) {
                    const int row = rr ? row1 : row0;
                    const int b_ = row >> 10, n_ = row & 1023;
                    float* op = out + (((size_t)(b_ * NHEADS + head) * Nn + n_) * DHd + d0);
                    float2 v;
                    v.x = (acc[mt][nt][rr * 2 + 0] + b0) * alpha;
                    v.y = (acc[mt][nt][rr * 2 + 1] + b1) * alpha;
                    *(float2*)op = v;
                }
            } else {
#pragma unroll
                for (int rr = 0; rr < 2; rr++) {
                    const int row = rr ? row1 : row0;
                    const float2 rv = *(const float2*)(resid + (size_t)row * 1024 + gcol);
                    float2 v;
                    v.x = acc[mt][nt][rr * 2 + 0] + b0 + rv.x;
                    v.y = acc[mt][nt][rr * 2 + 1] + b1 + rv.y;
                    *(float2*)(out + (size_t)row * 1024 + gcol) = v;
                }
            }
        }
    }
}

// ===========================================================================
// Tensor-core flash attention. CTA = 128 threads (4 warps), q-tile 128.
// Warp w owns q-rows [w*32, w*32+32) = 2 m16 tiles -> K/V fragment reads
// amortized over 2x MMAs. Softmax warp-local (4-lane shfl). No cvt anywhere
// (raw fp32 bits as tf32). Mask loaded straight into fragments from global.
// ===========================================================================
#define QS_STR 68
#define VS_STR 72
#define ATTN_SMEM ((128*QS_STR + 64*QS_STR + 64*VS_STR + 128*QS_STR)*4)  // 105472B

__global__ void __launch_bounds__(128) attn_mma(const int* __restrict__ mask)
{
    extern __shared__ uint32_t smu[];
    uint32_t* Qs = smu;                         // [128][68]
    uint32_t* Ks = Qs + 128 * QS_STR;           // [64][68]   (kpos rows, d cols)
    uint32_t* Vs = Ks + 64 * QS_STR;            // [64][72]   (kpos rows, d cols)
    uint32_t* Ps = Vs + 64 * VS_STR;            // [128][68]  P values (fp32 bits)

    const int bh = blockIdx.y;
    const int b = bh >> 4;
    const int h = bh & 15;
    const int qBase = blockIdx.x * 128;
    const int tid = threadIdx.x;
    const int lane = tid & 31, wid = tid >> 5;
    const int gid = lane >> 2, q = lane & 3;

    const float* Qp = g_Q + (size_t)bh * Nn * DHd;
    const float* Kp = g_K + (size_t)bh * Nn * DHd;
    const float* Vp = g_V + (size_t)bh * Nn * DHd;
    const int*   mp = mask + (size_t)b * Nn * Nn;

    // Load Q tile (128x64), raw bits
#pragma unroll
    for (int i = 0; i < 16; i++) {
        int idx = tid + 128 * i;
        int r = idx >> 4, c4 = idx & 15;
        float4 v = *(const float4*)(Qp + (size_t)(qBase + r) * DHd + c4 * 4);
        *(float4*)&Qs[r * QS_STR + c4 * 4] = v;
    }

    float mreg[4], lreg[4];          // [mt*2 + rr]
#pragma unroll
    for (int i = 0; i < 4; i++) { mreg[i] = -1e30f; lreg[i] = 0.f; }
    float o[2][8][4];
#pragma unroll
    for (int mt = 0; mt < 2; mt++)
#pragma unroll
        for (int nt = 0; nt < 8; nt++)
#pragma unroll
            for (int e = 0; e < 4; e++) o[mt][nt][e] = 0.f;

    for (int kt = 0; kt < Nn; kt += 64) {
        __syncthreads();
#pragma unroll
        for (int i = 0; i < 8; i++) {
            int idx = tid + 128 * i;
            int r = idx >> 4, c4 = idx & 15;
            float4 kv = *(const float4*)(Kp + (size_t)(kt + r) * DHd + c4 * 4);
            float4 vv = *(const float4*)(Vp + (size_t)(kt + r) * DHd + c4 * 4);
            *(float4*)&Ks[r * QS_STR + c4 * 4] = kv;
            *(float4*)&Vs[r * VS_STR + c4 * 4] = vv;
        }
        __syncthreads();

        // ---- S = Q K^T ----
        float s[2][8][4];
#pragma unroll
        for (int mt = 0; mt < 2; mt++)
#pragma unroll
            for (int nt = 0; nt < 8; nt++)
#pragma unroll
                for (int e = 0; e < 4; e++) s[mt][nt][e] = 0.f;

#pragma unroll
        for (int ks = 0; ks < 8; ks++) {
            const int c0 = ks * 8 + q;
            uint32_t a[2][4];
#pragma unroll
            for (int mt = 0; mt < 2; mt++) {
                int r0 = wid * 32 + mt * 16 + gid;
                a[mt][0] = Qs[r0 * QS_STR + c0];
                a[mt][1] = Qs[(r0 + 8) * QS_STR + c0];
                a[mt][2] = Qs[r0 * QS_STR + c0 + 4];
                a[mt][3] = Qs[(r0 + 8) * QS_STR + c0 + 4];
            }
#pragma unroll
            for (int nt = 0; nt < 8; nt++) {
                int np = nt * 8 + gid;
                uint32_t b0 = Ks[np * QS_STR + c0];
                uint32_t b1 = Ks[np * QS_STR + c0 + 4];
                mma_tf32_16x8x8(s[0][nt][0], s[0][nt][1], s[0][nt][2], s[0][nt][3],
                                a[0][0], a[0][1], a[0][2], a[0][3], b0, b1);
                mma_tf32_16x8x8(s[1][nt][0], s[1][nt][1], s[1][nt][2], s[1][nt][3],
                                a[1][0], a[1][1], a[1][2], a[1][3], b0, b1);
            }
        }

        // ---- mask + online softmax per mt ----
#pragma unroll
        for (int mt = 0; mt < 2; mt++) {
            const int rloc = wid * 32 + mt * 16 + gid;
            const int rg0 = qBase + rloc;
            float mx0 = -1e30f, mx1 = -1e30f;
#pragma unroll
            for (int nt = 0; nt < 8; nt++) {
                const int col = kt + nt * 8 + 2 * q;
                int2 mA = *(const int2*)(mp + (size_t)rg0 * Nn + col);
                int2 mB = *(const int2*)(mp + (size_t)(rg0 + 8) * Nn + col);
                s[mt][nt][0] = mA.x ? s[mt][nt][0] : -1e9f;
                s[mt][nt][1] = mA.y ? s[mt][nt][1] : -1e9f;
                s[mt][nt][2] = mB.x ? s[mt][nt][2] : -1e9f;
                s[mt][nt][3] = mB.y ? s[mt][nt][3] : -1e9f;
                mx0 = fmaxf(mx0, fmaxf(s[mt][nt][0], s[mt][nt][1]));
                mx1 = fmaxf(mx1, fmaxf(s[mt][nt][2], s[mt][nt][3]));
            }
            mx0 = fmaxf(mx0, __shfl_xor_sync(0xffffffffu, mx0, 1));
            mx0 = fmaxf(mx0, __shfl_xor_sync(0xffffffffu, mx0, 2));
            mx1 = fmaxf(mx1, __shfl_xor_sync(0xffffffffu, mx1, 1));
            mx1 = fmaxf(mx1, __shfl_xor_sync(0xffffffffu, mx1, 2));
            const float mn0 = fmaxf(mreg[mt * 2 + 0], mx0);
            const float mn1 = fmaxf(mreg[mt * 2 + 1], mx1);
            const float corr0 = __expf(mreg[mt * 2 + 0] - mn0);
            const float corr1 = __expf(mreg[mt * 2 + 1] - mn1);

            float rs0 = 0.f, rs1 = 0.f;
#pragma unroll
            for (int nt = 0; nt < 8; nt++) {
                float p0 = __expf(s[mt][nt][0] - mn0);
                float p1 = __expf(s[mt][nt][1] - mn0);
                float p2 = __expf(s[mt][nt][2] - mn1);
                float p3 = __expf(s[mt][nt][3] - mn1);
                rs0 += p0 + p1;
                rs1 += p2 + p3;
                *(float2*)((float*)&Ps[rloc * QS_STR + nt * 8 + 2 * q]) = make_float2(p0, p1);
                *(float2*)((float*)&Ps[(rloc + 8) * QS_STR + nt * 8 + 2 * q]) = make_float2(p2, p3);
            }
            rs0 += __shfl_xor_sync(0xffffffffu, rs0, 1);
            rs0 += __shfl_xor_sync(0xffffffffu, rs0, 2);
            rs1 += __shfl_xor_sync(0xffffffffu, rs1, 1);
            rs1 += __shfl_xor_sync(0xffffffffu, rs1, 2);
            lreg[mt * 2 + 0] = lreg[mt * 2 + 0] * corr0 + rs0;
            lreg[mt * 2 + 1] = lreg[mt * 2 + 1] * corr1 + rs1;
            mreg[mt * 2 + 0] = mn0;
            mreg[mt * 2 + 1] = mn1;
#pragma unroll
            for (int nt = 0; nt < 8; nt++) {
                o[mt][nt][0] *= corr0; o[mt][nt][1] *= corr0;
                o[mt][nt][2] *= corr1; o[mt][nt][3] *= corr1;
            }
        }
        __syncwarp();

        // ---- O += P V ----
#pragma unroll
        for (int ks = 0; ks < 8; ks++) {
            const int c0 = ks * 8 + q;
            uint32_t a[2][4];
#pragma unroll
            for (int mt = 0; mt < 2; mt++) {
                int r0 = wid * 32 + mt * 16 + gid;
                a[mt][0] = Ps[r0 * QS_STR + c0];
                a[mt][1] = Ps[(r0 + 8) * QS_STR + c0];
                a[mt][2] = Ps[r0 * QS_STR + c0 + 4];
                a[mt][3] = Ps[(r0 + 8) * QS_STR + c0 + 4];
            }
#pragma unroll
            for (int nt = 0; nt < 8; nt++) {
                int nd = nt * 8 + gid;
                uint32_t b0 = Vs[(ks * 8 + q) * VS_STR + nd];
                uint32_t b1 = Vs[(ks * 8 + q + 4) * VS_STR + nd];
                mma_tf32_16x8x8(o[0][nt][0], o[0][nt][1], o[0][nt][2], o[0][nt][3],
                                a[0][0], a[0][1], a[0][2], a[0][3], b0, b1);
                mma_tf32_16x8x8(o[1][nt][0], o[1][nt][1], o[1][nt][2], o[1][nt][3],
                                a[1][0], a[1][1], a[1][2], a[1][3], b0, b1);
            }
        }
    }

    // normalize + store to g_CTX [b][n][h*64+d]
    float* cbase = g_CTX + ((size_t)(b * Nn + qBase) * Hh) + h * DHd;
#pragma unroll
    for (int mt = 0; mt < 2; mt++) {
        const int r0 = wid * 32 + mt * 16 + gid;
        const int r1 = r0 + 8;
        const float inv0 = 1.f / lreg[mt * 2 + 0];
        const float inv1 = 1.f / lreg[mt * 2 + 1];
#pragma unroll
        for (int nt = 0; nt < 8; nt++) {
            const int d0 = nt * 8 + 2 * q;
            float2 v0, v1;
            v0.x = o[mt][nt][0] * inv0; v0.y = o[mt][nt][1] * inv0;
            v1.x = o[mt][nt][2] * inv1; v1.y = o[mt][nt][3] * inv1;
            *(float2*)(cbase + (size_t)r0 * Hh + d0) = v0;
            *(float2*)(cbase + (size_t)r1 * Hh + d0) = v1;
        }
    }
}

// ---------------------------------------------------------------------------
// LayerNorm (eps=1e-12) over g_Y rows + gather the two per-batch rows.
// ---------------------------------------------------------------------------
__global__ void __launch_bounds__(256) ln_kernel(
    const float* __restrict__ gamma, const float* __restrict__ beta,
    const int* __restrict__ conv_len, float* __restrict__ out)
{
    const int row = blockIdx.x;
    const int tid = threadIdx.x;
    const float* yr = g_Y + (size_t)row * Hh;
    float4 x = *(const float4*)(yr + (tid << 2));

    __shared__ float red[8];
    __shared__ float mu_sh, rstd_sh;

    float s1 = x.x + x.y + x.z + x.w;
#pragma unroll
    for (int off = 16; off; off >>= 1) s1 += __shfl_xor_sync(0xffffffffu, s1, off);
    int w = tid >> 5, lane = tid & 31;
    if (lane == 0) red[w] = s1;
    __syncthreads();
    if (tid == 0) {
        float t = 0.f;
#pragma unroll
        for (int i = 0; i < 8; i++) t += red[i];
        mu_sh = t * (1.f / 1024.f);
    }
    __syncthreads();
    float mu = mu_sh;
    float d0 = x.x - mu, d1 = x.y - mu, d2 = x.z - mu, d3 = x.w - mu;
    float s2 = d0 * d0 + d1 * d1 + d2 * d2 + d3 * d3;
#pragma unroll
    for (int off = 16; off; off >>= 1) s2 += __shfl_xor_sync(0xffffffffu, s2, off);
    if (lane == 0) red[w] = s2;
    __syncthreads();
    if (tid == 0) {
        float t = 0.f;
#pragma unroll
        for (int i = 0; i < 8; i++) t += red[i];
        rstd_sh = rsqrtf(t * (1.f / 1024.f) + 1e-12f);
    }
    __syncthreads();
    float rstd = rstd_sh;

    float4 g = *(const float4*)(gamma + (tid << 2));
    float4 be = *(const float4*)(beta + (tid << 2));
    float4 r;
    r.x = d0 * rstd * g.x + be.x;
    r.y = d1 * rstd * g.y + be.y;
    r.z = d2 * rstd * g.z + be.z;
    r.w = d3 * rstd * g.w + be.w;
    *(float4*)(out + (size_t)row * Hh + (tid << 2)) = r;

    int b_ = row >> 10, n_ = row & 1023;
    int base = 6 * conv_len[b_];
    if (n_ == base + 3)
        *(float4*)(out + (size_t)Mm * Hh + (size_t)b_ * Hh + (tid << 2)) = r;
    if (n_ == base + 2)
        *(float4*)(out + (size_t)Mm * Hh + (size_t)Bb * Hh + (size_t)b_ * Hh + (tid << 2)) = r;
}

// ---------------------------------------------------------------------------
extern "C" void kernel_launch(void* const* d_in, const int* in_sizes, int n_in,
                              void* d_out, int out_size)
{
    const float* hidden    = (const float*)d_in[0];
    const int*   role_mask = (const int*)d_in[1];
    const int*   conv_len  = (const int*)d_in[2];
    const float* Wq = (const float*)d_in[3];
    const float* bq = (const float*)d_in[4];
    const float* Wk = (const float*)d_in[5];
    const float* bk = (const float*)d_in[6];
    const float* Wv = (const float*)d_in[7];
    const float* bv = (const float*)d_in[8];
    const float* Wo = (const float*)d_in[9];
    const float* bo = (const float*)d_in[10];
    const float* gamma = (const float*)d_in[11];
    const float* beta  = (const float*)d_in[12];
    float* out = (float*)d_out;

    float *Qp, *Kp, *Vp, *Cp, *Yp;
    cudaGetSymbolAddress((void**)&Qp, g_Q);
    cudaGetSymbolAddress((void**)&Kp, g_K);
    cudaGetSymbolAddress((void**)&Vp, g_V);
    cudaGetSymbolAddress((void**)&Cp, g_CTX);
    cudaGetSymbolAddress((void**)&Yp, g_Y);

    cudaFuncSetAttribute(tf32_gemm_mma, cudaFuncAttributeMaxDynamicSharedMemorySize, GEMM_SMEM);
    cudaFuncSetAttribute(attn_mma, cudaFuncAttributeMaxDynamicSharedMemorySize, ATTN_SMEM);

    dim3 gg(Hh / 128, Mm / 128);
    tf32_gemm_mma<<<gg, 256, GEMM_SMEM>>>(hidden, Wq, bq, nullptr, Qp, 0, 0.125f);
    tf32_gemm_mma<<<gg, 256, GEMM_SMEM>>>(hidden, Wk, bk, nullptr, Kp, 0, 1.0f);
    tf32_gemm_mma<<<gg, 256, GEMM_SMEM>>>(hidden, Wv, bv, nullptr, Vp, 0, 1.0f);

    attn_mma<<<dim3(Nn / 128, Bb * NHEADS), 128, ATTN_SMEM>>>(role_mask);

    tf32_gemm_mma<<<gg, 256, GEMM_SMEM>>>(Cp, Wo, bo, hidden, Yp, 1, 1.0f);
    ln_kernel<<<Mm, 256>>>(gamma, beta, conv_len, out);
}

// round 12
// speedup vs baseline: 3.2662x; 1.1672x over previous
#include <cuda_runtime.h>
#include <math.h>
#include <stdint.h>

#define Bb 8
#define Nn 1024
#define Hh 1024
#define NHEADS 16
#define DHd 64
#define Mm (Bb*Nn)   // 8192

// Scratch (device globals: allocation-free rule)
__device__ float g_Q[(size_t)Bb*NHEADS*Nn*DHd];
__device__ float g_K[(size_t)Bb*NHEADS*Nn*DHd];
__device__ float g_V[(size_t)Bb*NHEADS*Nn*DHd];
__device__ float g_CTX[(size_t)Mm*Hh];
__device__ float g_Y[(size_t)Mm*Hh];
__device__ uint32_t g_MBITS[(size_t)Bb*Nn*32];   // bit-packed role_mask

// ===========================================================================
// helpers (arch-suffix-free PTX: works on plain sm_103 target)
// ===========================================================================
__device__ __forceinline__ uint32_t smem_to_u32(const void* p) {
    uint32_t a;
    asm("{ .reg .u64 t; cvta.to.shared.u64 t, %1; cvt.u32.u64 %0, t; }"
        : "=r"(a) : "l"(p));
    return a;
}
__device__ __forceinline__ void cp_async16(uint32_t dst, const void* src) {
    asm volatile("cp.async.ca.shared.global [%0], [%1], 16;" :: "r"(dst), "l"(src));
}
#define CP_COMMIT() asm volatile("cp.async.commit_group;")

// mma tf32: raw fp32 bits fed directly (HW uses the tf32 subset of the bits)
__device__ __forceinline__ void mma_tf32_16x8x8(
    float& c0, float& c1, float& c2, float& c3,
    uint32_t a0, uint32_t a1, uint32_t a2, uint32_t a3,
    uint32_t b0, uint32_t b1)
{
    asm volatile(
        "mma.sync.aligned.m16n8k8.row.col.f32.tf32.tf32.f32 "
        "{%0,%1,%2,%3}, {%4,%5,%6,%7}, {%8,%9}, {%0,%1,%2,%3};"
        : "+f"(c0), "+f"(c1), "+f"(c2), "+f"(c3)
        : "r"(a0), "r"(a1), "r"(a2), "r"(a3), "r"(b0), "r"(b1));
}

// ===========================================================================
// Pack role_mask into bits: g_MBITS[row*32 + w] bit j = (mask[row*1024+w*32+j]!=0)
// ===========================================================================
__global__ void __launch_bounds__(256) pack_mask(const int* __restrict__ mask)
{
    const int lane = threadIdx.x & 31;
    const size_t task = (size_t)blockIdx.x * 8 + (threadIdx.x >> 5);
    const size_t row = task >> 5;
    const int wcol = (int)(task & 31);
    int v = mask[row * 1024 + wcol * 32 + lane];
    uint32_t bits = __ballot_sync(0xffffffffu, v != 0);
    if (lane == 0) g_MBITS[row * 32 + wcol] = bits;
}

// ===========================================================================
// tf32 mma.sync GEMM with cp.async double buffering (unchanged from R11).
// ===========================================================================
#define SMSA 36
#define SMSB 136
#define A_STAGE (128*SMSA)
#define B_STAGE (32*SMSB)
#define GEMM_SMEM ((2*A_STAGE + 2*B_STAGE)*4)   // 71680 B

__global__ void __launch_bounds__(256) tf32_gemm_mma(
    const float* __restrict__ A, const float* __restrict__ W,
    const float* __restrict__ bias, const float* __restrict__ resid,
    float* __restrict__ out, int mode, float alpha)
{
    extern __shared__ uint32_t gsm[];
    const uint32_t smb = smem_to_u32(gsm);

    const int tid = threadIdx.x;
    const int lane = tid & 31, wid = tid >> 5;
    const int warpM = wid & 1;
    const int warpN = wid >> 1;
    const int gid = lane >> 2;
    const int q = lane & 3;
    const int rowBase = blockIdx.y * 128;
    const int colBase = blockIdx.x * 128;

    const float* Abase = A + (size_t)rowBase * 1024;

    auto issue = [&](int c, int s) {
#pragma unroll
        for (int i = 0; i < 4; i++) {
            int idx = tid + 256 * i;
            int r = idx >> 3, g = idx & 7;
            cp_async16(smb + (uint32_t)(s * A_STAGE + r * SMSA + g * 4) * 4,
                       Abase + (size_t)r * 1024 + c * 32 + g * 4);
        }
#pragma unroll
        for (int i = 0; i < 4; i++) {
            int idx = tid + 256 * i;
            int r = idx >> 5, gg = idx & 31;
            cp_async16(smb + (uint32_t)(2 * A_STAGE + s * B_STAGE + r * SMSB + gg * 4) * 4,
                       W + (size_t)(c * 32 + r) * 1024 + colBase + gg * 4);
        }
        CP_COMMIT();
    };

    float acc[4][4][4];
#pragma unroll
    for (int mt = 0; mt < 4; mt++)
#pragma unroll
        for (int nt = 0; nt < 4; nt++)
#pragma unroll
            for (int e = 0; e < 4; e++) acc[mt][nt][e] = 0.f;

    issue(0, 0);
    issue(1, 1);

    for (int c = 0; c < 32; c++) {
        if (c < 31) asm volatile("cp.async.wait_group 1;");
        else        asm volatile("cp.async.wait_group 0;");
        __syncthreads();

        const uint32_t* As = gsm + (c & 1) * A_STAGE;
        const uint32_t* Bs = gsm + 2 * A_STAGE + (c & 1) * B_STAGE;

#pragma unroll
        for (int ks = 0; ks < 4; ks++) {
            const int c0 = ks * 8 + q;
            uint32_t af[4][4];
#pragma unroll
            for (int mt = 0; mt < 4; mt++) {
                int r0 = warpM * 64 + mt * 16 + gid;
                af[mt][0] = As[r0 * SMSA + c0];
                af[mt][1] = As[(r0 + 8) * SMSA + c0];
                af[mt][2] = As[r0 * SMSA + c0 + 4];
                af[mt][3] = As[(r0 + 8) * SMSA + c0 + 4];
            }
            uint32_t bf[4][2];
#pragma unroll
            for (int nt = 0; nt < 4; nt++) {
                int n0 = warpN * 32 + nt * 8 + gid;
                bf[nt][0] = Bs[(ks * 8 + q) * SMSB + n0];
                bf[nt][1] = Bs[(ks * 8 + q + 4) * SMSB + n0];
            }
#pragma unroll
            for (int mt = 0; mt < 4; mt++)
#pragma unroll
                for (int nt = 0; nt < 4; nt++)
                    mma_tf32_16x8x8(acc[mt][nt][0], acc[mt][nt][1],
                                    acc[mt][nt][2], acc[mt][nt][3],
                                    af[mt][0], af[mt][1], af[mt][2], af[mt][3],
                                    bf[nt][0], bf[nt][1]);
        }
        __syncthreads();
        if (c + 2 < 32) issue(c + 2, c & 1);
    }

#pragma unroll
    for (int mt = 0; mt < 4; mt++) {
        const int row0 = rowBase + warpM * 64 + mt * 16 + gid;
        const int row1 = row0 + 8;
#pragma unroll
        for (int nt = 0; nt < 4; nt++) {
            const int gcol = colBase + warpN * 32 + nt * 8 + 2 * q;
            const float b0 = bias[gcol], b1 = bias[gcol + 1];
            if (mode == 0) {
                const int head = gcol >> 6, d0 = gcol & 63;
#pragma unroll
                for (int rr = 0; rr < 2; rr++) {
                    const int row = rr ? row1 : row0;
                    const int b_ = row >> 10, n_ = row & 1023;
                    float* op = out + (((size_t)(b_ * NHEADS + head) * Nn + n_) * DHd + d0);
                    float2 v;
                    v.x = (acc[mt][nt][rr * 2 + 0] + b0) * alpha;
                    v.y = (acc[mt][nt][rr * 2 + 1] + b1) * alpha;
                    *(float2*)op = v;
                }
            } else {
#pragma unroll
                for (int rr = 0; rr < 2; rr++) {
                    const int row = rr ? row1 : row0;
                    const float2 rv = *(const float2*)(resid + (size_t)row * 1024 + gcol);
                    float2 v;
                    v.x = acc[mt][nt][rr * 2 + 0] + b0 + rv.x;
                    v.y = acc[mt][nt][rr * 2 + 1] + b1 + rv.y;
                    *(float2*)(out + (size_t)row * 1024 + gcol) = v;
                }
            }
        }
    }
}

// ===========================================================================
// Tensor-core flash attention v3.
// 4 warps, q-tile 128 (warp owns 32 q-rows = 2 m16 tiles).
// - K/V double-buffered via cp.async (2 stages) -> global latency hidden
// - P never touches smem: C-frag -> A-frag via quad shuffles
// - mask from bit-packed g_MBITS (4x LDG.64 per tile, prefetched pre-MMA)
// ===========================================================================
#define QS_STR 68
#define VS_STR 72
#define KSTG (64*QS_STR)
#define VSTG (64*VS_STR)
#define ATTN_SMEM ((128*QS_STR + 2*KSTG + 2*VSTG)*4)   // 106496 B

__global__ void __launch_bounds__(128, 2) attn_mma(void)
{
    extern __shared__ uint32_t smu[];
    uint32_t* Qs  = smu;                       // [128][68]
    uint32_t* KsB = Qs + 128 * QS_STR;         // 2 stages [64][68]
    uint32_t* VsB = KsB + 2 * KSTG;            // 2 stages [64][72]
    const uint32_t smb = smem_to_u32(smu);
    const uint32_t ksOff = (uint32_t)(128 * QS_STR) * 4;
    const uint32_t vsOff = ksOff + (uint32_t)(2 * KSTG) * 4;

    const int bh = blockIdx.y;
    const int b = bh >> 4;
    const int h = bh & 15;
    const int qBase = blockIdx.x * 128;
    const int tid = threadIdx.x;
    const int lane = tid & 31, wid = tid >> 5;
    const int gid = lane >> 2, q = lane & 3;

    const float* Qp = g_Q + (size_t)bh * Nn * DHd;
    const float* Kp = g_K + (size_t)bh * Nn * DHd;
    const float* Vp = g_V + (size_t)bh * Nn * DHd;
    const uint32_t* mb = g_MBITS + ((size_t)b << 15);   // b*1024*32

    auto issue_kv = [&](int kt, int s) {
#pragma unroll
        for (int i = 0; i < 8; i++) {
            int idx = tid + 128 * i;
            int r = idx >> 4, c4 = idx & 15;
            cp_async16(smb + ksOff + (uint32_t)(s * KSTG + r * QS_STR + c4 * 4) * 4,
                       Kp + (size_t)(kt + r) * DHd + c4 * 4);
            cp_async16(smb + vsOff + (uint32_t)(s * VSTG + r * VS_STR + c4 * 4) * 4,
                       Vp + (size_t)(kt + r) * DHd + c4 * 4);
        }
        CP_COMMIT();
    };

    // Load Q tile (128x64), raw bits
#pragma unroll
    for (int i = 0; i < 16; i++) {
        int idx = tid + 128 * i;
        int r = idx >> 4, c4 = idx & 15;
        float4 v = *(const float4*)(Qp + (size_t)(qBase + r) * DHd + c4 * 4);
        *(float4*)&Qs[r * QS_STR + c4 * 4] = v;
    }

    issue_kv(0, 0);
    issue_kv(64, 1);

    float mreg[4], lreg[4];          // [mt*2 + rr]
#pragma unroll
    for (int i = 0; i < 4; i++) { mreg[i] = -1e30f; lreg[i] = 0.f; }
    float o[2][8][4];
#pragma unroll
    for (int mt = 0; mt < 2; mt++)
#pragma unroll
        for (int nt = 0; nt < 8; nt++)
#pragma unroll
            for (int e = 0; e < 4; e++) o[mt][nt][e] = 0.f;

    const int srcA = (lane & 0x1c) | (q >> 1);
    const int srcB = srcA + 2;
    const bool qodd = (q & 1);

    for (int t = 0; t < 16; t++) {
        if (t < 15) asm volatile("cp.async.wait_group 1;");
        else        asm volatile("cp.async.wait_group 0;");
        __syncthreads();

        const uint32_t* Ks = KsB + (t & 1) * KSTG;
        const uint32_t* Vs = VsB + (t & 1) * VSTG;

        // prefetch mask words (bit-packed): 4 rows x 2 words
        uint2 mw[4];
#pragma unroll
        for (int mt = 0; mt < 2; mt++) {
            const int rloc = wid * 32 + mt * 16 + gid;
            mw[mt * 2 + 0] = *(const uint2*)(mb + (size_t)(qBase + rloc) * 32 + t * 2);
            mw[mt * 2 + 1] = *(const uint2*)(mb + (size_t)(qBase + rloc + 8) * 32 + t * 2);
        }

        // ---- S = Q K^T ----
        float s[2][8][4];
#pragma unroll
        for (int mt = 0; mt < 2; mt++)
#pragma unroll
            for (int nt = 0; nt < 8; nt++)
#pragma unroll
                for (int e = 0; e < 4; e++) s[mt][nt][e] = 0.f;

#pragma unroll
        for (int ks = 0; ks < 8; ks++) {
            const int c0 = ks * 8 + q;
            uint32_t a[2][4];
#pragma unroll
            for (int mt = 0; mt < 2; mt++) {
                int r0 = wid * 32 + mt * 16 + gid;
                a[mt][0] = Qs[r0 * QS_STR + c0];
                a[mt][1] = Qs[(r0 + 8) * QS_STR + c0];
                a[mt][2] = Qs[r0 * QS_STR + c0 + 4];
                a[mt][3] = Qs[(r0 + 8) * QS_STR + c0 + 4];
            }
#pragma unroll
            for (int nt = 0; nt < 8; nt++) {
                int np = nt * 8 + gid;
                uint32_t b0 = Ks[np * QS_STR + c0];
                uint32_t b1 = Ks[np * QS_STR + c0 + 4];
                mma_tf32_16x8x8(s[0][nt][0], s[0][nt][1], s[0][nt][2], s[0][nt][3],
                                a[0][0], a[0][1], a[0][2], a[0][3], b0, b1);
                mma_tf32_16x8x8(s[1][nt][0], s[1][nt][1], s[1][nt][2], s[1][nt][3],
                                a[1][0], a[1][1], a[1][2], a[1][3], b0, b1);
            }
        }

        // ---- mask + online softmax per mt (exp'd P stays in s regs) ----
#pragma unroll
        for (int mt = 0; mt < 2; mt++) {
            const uint2 w0 = mw[mt * 2 + 0];   // row gid
            const uint2 w1 = mw[mt * 2 + 1];   // row gid+8
            float mx0 = -1e30f, mx1 = -1e30f;
#pragma unroll
            for (int nt = 0; nt < 8; nt++) {
                const int sh = (nt & 3) * 8 + 2 * q;
                const uint32_t wa = (nt < 4) ? w0.x : w0.y;
                const uint32_t wb = (nt < 4) ? w1.x : w1.y;
                s[mt][nt][0] = ((wa >> sh) & 1u)       ? s[mt][nt][0] : -1e9f;
                s[mt][nt][1] = ((wa >> (sh + 1)) & 1u) ? s[mt][nt][1] : -1e9f;
                s[mt][nt][2] = ((wb >> sh) & 1u)       ? s[mt][nt][2] : -1e9f;
                s[mt][nt][3] = ((wb >> (sh + 1)) & 1u) ? s[mt][nt][3] : -1e9f;
                mx0 = fmaxf(mx0, fmaxf(s[mt][nt][0], s[mt][nt][1]));
                mx1 = fmaxf(mx1, fmaxf(s[mt][nt][2], s[mt][nt][3]));
            }
            mx0 = fmaxf(mx0, __shfl_xor_sync(0xffffffffu, mx0, 1));
            mx0 = fmaxf(mx0, __shfl_xor_sync(0xffffffffu, mx0, 2));
            mx1 = fmaxf(mx1, __shfl_xor_sync(0xffffffffu, mx1, 1));
            mx1 = fmaxf(mx1, __shfl_xor_sync(0xffffffffu, mx1, 2));
            const float mn0 = fmaxf(mreg[mt * 2 + 0], mx0);
            const float mn1 = fmaxf(mreg[mt * 2 + 1], mx1);
            const float corr0 = __expf(mreg[mt * 2 + 0] - mn0);
            const float corr1 = __expf(mreg[mt * 2 + 1] - mn1);

            float rs0 = 0.f, rs1 = 0.f;
#pragma unroll
            for (int nt = 0; nt < 8; nt++) {
                s[mt][nt][0] = __expf(s[mt][nt][0] - mn0);
                s[mt][nt][1] = __expf(s[mt][nt][1] - mn0);
                s[mt][nt][2] = __expf(s[mt][nt][2] - mn1);
                s[mt][nt][3] = __expf(s[mt][nt][3] - mn1);
                rs0 += s[mt][nt][0] + s[mt][nt][1];
                rs1 += s[mt][nt][2] + s[mt][nt][3];
            }
            rs0 += __shfl_xor_sync(0xffffffffu, rs0, 1);
            rs0 += __shfl_xor_sync(0xffffffffu, rs0, 2);
            rs1 += __shfl_xor_sync(0xffffffffu, rs1, 1);
            rs1 += __shfl_xor_sync(0xffffffffu, rs1, 2);
            lreg[mt * 2 + 0] = lreg[mt * 2 + 0] * corr0 + rs0;
            lreg[mt * 2 + 1] = lreg[mt * 2 + 1] * corr1 + rs1;
            mreg[mt * 2 + 0] = mn0;
            mreg[mt * 2 + 1] = mn1;
#pragma unroll
            for (int nt = 0; nt < 8; nt++) {
                o[mt][nt][0] *= corr0; o[mt][nt][1] *= corr0;
                o[mt][nt][2] *= corr1; o[mt][nt][3] *= corr1;
            }
        }

        // ---- O += P V : A-frags built from s regs via quad shuffles ----
#pragma unroll
        for (int ks = 0; ks < 8; ks++) {
            uint32_t a[2][4];
#pragma unroll
            for (int mt = 0; mt < 2; mt++) {
                float e0 = __shfl_sync(0xffffffffu, s[mt][ks][0], srcA);
                float o0 = __shfl_sync(0xffffffffu, s[mt][ks][1], srcA);
                float e1 = __shfl_sync(0xffffffffu, s[mt][ks][2], srcA);
                float o1 = __shfl_sync(0xffffffffu, s[mt][ks][3], srcA);
                float e2 = __shfl_sync(0xffffffffu, s[mt][ks][0], srcB);
                float o2 = __shfl_sync(0xffffffffu, s[mt][ks][1], srcB);
                float e3 = __shfl_sync(0xffffffffu, s[mt][ks][2], srcB);
                float o3 = __shfl_sync(0xffffffffu, s[mt][ks][3], srcB);
                a[mt][0] = __float_as_uint(qodd ? o0 : e0);
                a[mt][1] = __float_as_uint(qodd ? o1 : e1);
                a[mt][2] = __float_as_uint(qodd ? o2 : e2);
                a[mt][3] = __float_as_uint(qodd ? o3 : e3);
            }
#pragma unroll
            for (int nt = 0; nt < 8; nt++) {
                int nd = nt * 8 + gid;
                uint32_t b0 = Vs[(ks * 8 + q) * VS_STR + nd];
                uint32_t b1 = Vs[(ks * 8 + q + 4) * VS_STR + nd];
                mma_tf32_16x8x8(o[0][nt][0], o[0][nt][1], o[0][nt][2], o[0][nt][3],
                                a[0][0], a[0][1], a[0][2], a[0][3], b0, b1);
                mma_tf32_16x8x8(o[1][nt][0], o[1][nt][1], o[1][nt][2], o[1][nt][3],
                                a[1][0], a[1][1], a[1][2], a[1][3], b0, b1);
            }
        }

        __syncthreads();
        if (t + 2 < 16) issue_kv((t + 2) * 64, t & 1);
    }

    // normalize + store to g_CTX [b][n][h*64+d]
    float* cbase = g_CTX + ((size_t)(b * Nn + qBase) * Hh) + h * DHd;
#pragma unroll
    for (int mt = 0; mt < 2; mt++) {
        const int r0 = wid * 32 + mt * 16 + gid;
        const int r1 = r0 + 8;
        const float inv0 = 1.f / lreg[mt * 2 + 0];
        const float inv1 = 1.f / lreg[mt * 2 + 1];
#pragma unroll
        for (int nt = 0; nt < 8; nt++) {
            const int d0 = nt * 8 + 2 * q;
            float2 v0, v1;
            v0.x = o[mt][nt][0] * inv0; v0.y = o[mt][nt][1] * inv0;
            v1.x = o[mt][nt][2] * inv1; v1.y = o[mt][nt][3] * inv1;
            *(float2*)(cbase + (size_t)r0 * Hh + d0) = v0;
            *(float2*)(cbase + (size_t)r1 * Hh + d0) = v1;
        }
    }
}

// ---------------------------------------------------------------------------
// LayerNorm (eps=1e-12) over g_Y rows + gather the two per-batch rows.
// ---------------------------------------------------------------------------
__global__ void __launch_bounds__(256) ln_kernel(
    const float* __restrict__ gamma, const float* __restrict__ beta,
    const int* __restrict__ conv_len, float* __restrict__ out)
{
    const int row = blockIdx.x;
    const int tid = threadIdx.x;
    const float* yr = g_Y + (size_t)row * Hh;
    float4 x = *(const float4*)(yr + (tid << 2));

    __shared__ float red[8];
    __shared__ float mu_sh, rstd_sh;

    float s1 = x.x + x.y + x.z + x.w;
#pragma unroll
    for (int off = 16; off; off >>= 1) s1 += __shfl_xor_sync(0xffffffffu, s1, off);
    int w = tid >> 5, lane = tid & 31;
    if (lane == 0) red[w] = s1;
    __syncthreads();
    if (tid == 0) {
        float t = 0.f;
#pragma unroll
        for (int i = 0; i < 8; i++) t += red[i];
        mu_sh = t * (1.f / 1024.f);
    }
    __syncthreads();
    float mu = mu_sh;
    float d0 = x.x - mu, d1 = x.y - mu, d2 = x.z - mu, d3 = x.w - mu;
    float s2 = d0 * d0 + d1 * d1 + d2 * d2 + d3 * d3;
#pragma unroll
    for (int off = 16; off; off >>= 1) s2 += __shfl_xor_sync(0xffffffffu, s2, off);
    if (lane == 0) red[w] = s2;
    __syncthreads();
    if (tid == 0) {
        float t = 0.f;
#pragma unroll
        for (int i = 0; i < 8; i++) t += red[i];
        rstd_sh = rsqrtf(t * (1.f / 1024.f) + 1e-12f);
    }
    __syncthreads();
    float rstd = rstd_sh;

    float4 g = *(const float4*)(gamma + (tid << 2));
    float4 be = *(const float4*)(beta + (tid << 2));
    float4 r;
    r.x = d0 * rstd * g.x + be.x;
    r.y = d1 * rstd * g.y + be.y;
    r.z = d2 * rstd * g.z + be.z;
    r.w = d3 * rstd * g.w + be.w;
    *(float4*)(out + (size_t)row * Hh + (tid << 2)) = r;

    int b_ = row >> 10, n_ = row & 1023;
    int base = 6 * conv_len[b_];
    if (n_ == base + 3)
        *(float4*)(out + (size_t)Mm * Hh + (size_t)b_ * Hh + (tid << 2)) = r;
    if (n_ == base + 2)
        *(float4*)(out + (size_t)Mm * Hh + (size_t)Bb * Hh + (size_t)b_ * Hh + (tid << 2)) = r;
}

// ---------------------------------------------------------------------------
extern "C" void kernel_launch(void* const* d_in, const int* in_sizes, int n_in,
                              void* d_out, int out_size)
{
    const float* hidden    = (const float*)d_in[0];
    const int*   role_mask = (const int*)d_in[1];
    const int*   conv_len  = (const int*)d_in[2];
    const float* Wq = (const float*)d_in[3];
    const float* bq = (const float*)d_in[4];
    const float* Wk = (const float*)d_in[5];
    const float* bk = (const float*)d_in[6];
    const float* Wv = (const float*)d_in[7];
    const float* bv = (const float*)d_in[8];
    const float* Wo = (const float*)d_in[9];
    const float* bo = (const float*)d_in[10];
    const float* gamma = (const float*)d_in[11];
    const float* beta  = (const float*)d_in[12];
    float* out = (float*)d_out;

    float *Qp, *Kp, *Vp, *Cp, *Yp;
    cudaGetSymbolAddress((void**)&Qp, g_Q);
    cudaGetSymbolAddress((void**)&Kp, g_K);
    cudaGetSymbolAddress((void**)&Vp, g_V);
    cudaGetSymbolAddress((void**)&Cp, g_CTX);
    cudaGetSymbolAddress((void**)&Yp, g_Y);

    cudaFuncSetAttribute(tf32_gemm_mma, cudaFuncAttributeMaxDynamicSharedMemorySize, GEMM_SMEM);
    cudaFuncSetAttribute(attn_mma, cudaFuncAttributeMaxDynamicSharedMemorySize, ATTN_SMEM);

    pack_mask<<<32768, 256>>>(role_mask);

    dim3 gg(Hh / 128, Mm / 128);
    tf32_gemm_mma<<<gg, 256, GEMM_SMEM>>>(hidden, Wq, bq, nullptr, Qp, 0, 0.125f);
    tf32_gemm_mma<<<gg, 256, GEMM_SMEM>>>(hidden, Wk, bk, nullptr, Kp, 0, 1.0f);
    tf32_gemm_mma<<<gg, 256, GEMM_SMEM>>>(hidden, Wv, bv, nullptr, Vp, 0, 1.0f);

    attn_mma<<<dim3(Nn / 128, Bb * NHEADS), 128, ATTN_SMEM>>>();

    tf32_gemm_mma<<<gg, 256, GEMM_SMEM>>>(Cp, Wo, bo, hidden, Yp, 1, 1.0f);
    ln_kernel<<<Mm, 256>>>(gamma, beta, conv_len, out);
}

// round 14
// speedup vs baseline: 3.2856x; 1.0059x over previous
#include <cuda_runtime.h>
#include <math.h>
#include <stdint.h>

#define Bb 8
#define Nn 1024
#define Hh 1024
#define NHEADS 16
#define DHd 64
#define Mm (Bb*Nn)   // 8192

// Scratch (device globals: allocation-free rule)
__device__ float g_Q[(size_t)Bb*NHEADS*Nn*DHd];
__device__ float g_K[(size_t)Bb*NHEADS*Nn*DHd];
__device__ float g_V[(size_t)Bb*NHEADS*Nn*DHd];
__device__ float g_CTX[(size_t)Mm*Hh];
__device__ float g_Y[(size_t)Mm*Hh];
__device__ uint32_t g_MBITS[(size_t)Bb*Nn*32];   // bit-packed role_mask

// ===========================================================================
// helpers (arch-suffix-free PTX: works on plain sm_103 target)
// ===========================================================================
__device__ __forceinline__ uint32_t smem_to_u32(const void* p) {
    uint32_t a;
    asm("{ .reg .u64 t; cvta.to.shared.u64 t, %1; cvt.u32.u64 %0, t; }"
        : "=r"(a) : "l"(p));
    return a;
}
__device__ __forceinline__ void cp_async16(uint32_t dst, const void* src) {
    asm volatile("cp.async.ca.shared.global [%0], [%1], 16;" :: "r"(dst), "l"(src));
}
#define CP_COMMIT() asm volatile("cp.async.commit_group;")

// ldmatrix x4: a 8x4 tf32 tile == 8x8 b16 tile bit-wise; lane i gets [i/4][i%4]
__device__ __forceinline__ void ldsm_x4(uint32_t& r0, uint32_t& r1,
                                        uint32_t& r2, uint32_t& r3, uint32_t addr)
{
    asm volatile("ldmatrix.sync.aligned.m8n8.x4.shared.b16 {%0,%1,%2,%3}, [%4];"
        : "=r"(r0), "=r"(r1), "=r"(r2), "=r"(r3) : "r"(addr));
}

// mma tf32: raw fp32 bits fed directly (HW uses the tf32 subset of the bits)
__device__ __forceinline__ void mma_tf32_16x8x8(
    float& c0, float& c1, float& c2, float& c3,
    uint32_t a0, uint32_t a1, uint32_t a2, uint32_t a3,
    uint32_t b0, uint32_t b1)
{
    asm volatile(
        "mma.sync.aligned.m16n8k8.row.col.f32.tf32.tf32.f32 "
        "{%0,%1,%2,%3}, {%4,%5,%6,%7}, {%8,%9}, {%0,%1,%2,%3};"
        : "+f"(c0), "+f"(c1), "+f"(c2), "+f"(c3)
        : "r"(a0), "r"(a1), "r"(a2), "r"(a3), "r"(b0), "r"(b1));
}

// ===========================================================================
// Pack role_mask into bits
// ===========================================================================
__global__ void __launch_bounds__(256) pack_mask(const int* __restrict__ mask)
{
    const int lane = threadIdx.x & 31;
    const size_t task = (size_t)blockIdx.x * 8 + (threadIdx.x >> 5);
    const size_t row = task >> 5;
    const int wcol = (int)(task & 31);
    int v = mask[row * 1024 + wcol * 32 + lane];
    uint32_t bits = __ballot_sync(0xffffffffu, v != 0);
    if (lane == 0) g_MBITS[row * 32 + wcol] = bits;
}

// ===========================================================================
// tf32 mma.sync GEMM, 3-stage cp.async pipeline, ldmatrix A-fragments.
// mode 0: fused QKV — blockIdx.z selects (W,bias,out), alpha=0.125 for z==0,
//         store head layout [B,h,N,dh].
// mode 1: single GEMM (Wa/ba/oa), store row-major with +bias+resid.
// ===========================================================================
#define SMSA 36
#define SMSB 136
#define A_STAGE (128*SMSA)
#define B_STAGE (32*SMSB)
#define NSTAGE 3
#define GEMM_SMEM (NSTAGE*(A_STAGE + B_STAGE)*4)   // 107520 B

__global__ void __launch_bounds__(256) tf32_gemm_mma(
    const float* __restrict__ A,
    const float* __restrict__ Wa, const float* __restrict__ Wb, const float* __restrict__ Wc,
    const float* __restrict__ ba, const float* __restrict__ bb, const float* __restrict__ bc,
    float* __restrict__ oa, float* __restrict__ ob, float* __restrict__ oc,
    const float* __restrict__ resid, int mode)
{
    extern __shared__ uint32_t gsm[];
    const uint32_t smb = smem_to_u32(gsm);

    const int tid = threadIdx.x;
    const int lane = tid & 31, wid = tid >> 5;
    const int warpM = wid & 1;
    const int warpN = wid >> 1;
    const int gid = lane >> 2;
    const int q = lane & 3;
    const int rowBase = blockIdx.y * 128;
    const int colBase = blockIdx.x * 128;

    const float* W; const float* bias; float* out; float alpha;
    if (mode == 0) {
        if (blockIdx.z == 0)      { W = Wa; bias = ba; out = oa; alpha = 0.125f; }
        else if (blockIdx.z == 1) { W = Wb; bias = bb; out = ob; alpha = 1.0f; }
        else                      { W = Wc; bias = bc; out = oc; alpha = 1.0f; }
    } else { W = Wa; bias = ba; out = oa; alpha = 1.0f; }

    const float* Abase = A + (size_t)rowBase * 1024;

    auto issue = [&](int c, int s) {
#pragma unroll
        for (int i = 0; i < 4; i++) {
            int idx = tid + 256 * i;
            int r = idx >> 3, g = idx & 7;
            cp_async16(smb + (uint32_t)(s * A_STAGE + r * SMSA + g * 4) * 4,
                       Abase + (size_t)r * 1024 + c * 32 + g * 4);
        }
#pragma unroll
        for (int i = 0; i < 4; i++) {
            int idx = tid + 256 * i;
            int r = idx >> 5, gg = idx & 31;
            cp_async16(smb + (uint32_t)(NSTAGE * A_STAGE + s * B_STAGE + r * SMSB + gg * 4) * 4,
                       W + (size_t)(c * 32 + r) * 1024 + colBase + gg * 4);
        }
        CP_COMMIT();
    };

    float acc[4][4][4];
#pragma unroll
    for (int mt = 0; mt < 4; mt++)
#pragma unroll
        for (int nt = 0; nt < 4; nt++)
#pragma unroll
            for (int e = 0; e < 4; e++) acc[mt][nt][e] = 0.f;

    issue(0, 0);
    issue(1, 1);
    issue(2, 2);

    // ldmatrix lane mapping for A-fragments (a0..a3 tiles)
    const int lrow = ((lane >> 3) & 1) * 8 + (lane & 7);
    const int lcol = (lane >> 4) * 4;

    int st = 0;
    for (int c = 0; c < 32; c++) {
        if (c < 30)      asm volatile("cp.async.wait_group 2;");
        else if (c == 30) asm volatile("cp.async.wait_group 1;");
        else             asm volatile("cp.async.wait_group 0;");
        __syncthreads();

        const uint32_t* Bs = gsm + NSTAGE * A_STAGE + st * B_STAGE;
        const uint32_t aBase = smb +
            (uint32_t)(st * A_STAGE + (warpM * 64 + lrow) * SMSA + lcol) * 4;

#pragma unroll
        for (int ks = 0; ks < 4; ks++) {
            uint32_t af[4][4];
#pragma unroll
            for (int mt = 0; mt < 4; mt++)
                ldsm_x4(af[mt][0], af[mt][1], af[mt][2], af[mt][3],
                        aBase + (uint32_t)(mt * 16 * SMSA + ks * 8) * 4);
            uint32_t bf[4][2];
#pragma unroll
            for (int nt = 0; nt < 4; nt++) {
                int n0 = warpN * 32 + nt * 8 + gid;
                bf[nt][0] = Bs[(ks * 8 + q) * SMSB + n0];
                bf[nt][1] = Bs[(ks * 8 + q + 4) * SMSB + n0];
            }
#pragma unroll
            for (int mt = 0; mt < 4; mt++)
#pragma unroll
                for (int nt = 0; nt < 4; nt++)
                    mma_tf32_16x8x8(acc[mt][nt][0], acc[mt][nt][1],
                                    acc[mt][nt][2], acc[mt][nt][3],
                                    af[mt][0], af[mt][1], af[mt][2], af[mt][3],
                                    bf[nt][0], bf[nt][1]);
        }
        __syncthreads();
        if (c + 3 < 32) issue(c + 3, st);
        st = (st == 2) ? 0 : st + 1;
    }

#pragma unroll
    for (int mt = 0; mt < 4; mt++) {
        const int row0 = rowBase + warpM * 64 + mt * 16 + gid;
        const int row1 = row0 + 8;
#pragma unroll
        for (int nt = 0; nt < 4; nt++) {
            const int gcol = colBase + warpN * 32 + nt * 8 + 2 * q;
            const float b0 = bias[gcol], b1 = bias[gcol + 1];
            if (mode == 0) {
                const int head = gcol >> 6, d0 = gcol & 63;
#pragma unroll
                for (int rr = 0; rr < 2; rr++) {
                    const int row = rr ? row1 : row0;
                    const int b_ = row >> 10, n_ = row & 1023;
                    float* op = out + (((size_t)(b_ * NHEADS + head) * Nn + n_) * DHd + d0);
                    float2 v;
                    v.x = (acc[mt][nt][rr * 2 + 0] + b0) * alpha;
                    v.y = (acc[mt][nt][rr * 2 + 1] + b1) * alpha;
                    *(float2*)op = v;
                }
            } else {
#pragma unroll
                for (int rr = 0; rr < 2; rr++) {
                    const int row = rr ? row1 : row0;
                    const float2 rv = *(const float2*)(resid + (size_t)row * 1024 + gcol);
                    float2 v;
                    v.x = acc[mt][nt][rr * 2 + 0] + b0 + rv.x;
                    v.y = acc[mt][nt][rr * 2 + 1] + b1 + rv.y;
                    *(float2*)(out + (size_t)row * 1024 + gcol) = v;
                }
            }
        }
    }
}

// ===========================================================================
// Tensor-core flash attention v4: ldmatrix Q/K fragments (4x fewer ld instrs),
// K/V cp.async double buffer, P via quad shuffles, bit-packed mask.
// ===========================================================================
#define QS_STR 68
#define VS_STR 72
#define KSTG (64*QS_STR)
#define VSTG (64*VS_STR)
#define ATTN_SMEM ((128*QS_STR + 2*KSTG + 2*VSTG)*4)   // 106496 B

__global__ void __launch_bounds__(128, 2) attn_mma(void)
{
    extern __shared__ uint32_t smu[];
    uint32_t* Qs  = smu;                       // [128][68]
    const uint32_t smb = smem_to_u32(smu);
    const uint32_t ksOff = (uint32_t)(128 * QS_STR) * 4;
    const uint32_t vsOff = ksOff + (uint32_t)(2 * KSTG) * 4;
    uint32_t* VsB = smu + 128 * QS_STR + 2 * KSTG;

    const int bh = blockIdx.y;
    const int b = bh >> 4;
    const int h = bh & 15;
    const int qBase = blockIdx.x * 128;
    const int tid = threadIdx.x;
    const int lane = tid & 31, wid = tid >> 5;
    const int gid = lane >> 2, q = lane & 3;

    const float* Qp = g_Q + (size_t)bh * Nn * DHd;
    const float* Kp = g_K + (size_t)bh * Nn * DHd;
    const float* Vp = g_V + (size_t)bh * Nn * DHd;
    const uint32_t* mb = g_MBITS + ((size_t)b << 15);   // b*1024*32

    auto issue_kv = [&](int kt, int s) {
#pragma unroll
        for (int i = 0; i < 8; i++) {
            int idx = tid + 128 * i;
            int r = idx >> 4, c4 = idx & 15;
            cp_async16(smb + ksOff + (uint32_t)(s * KSTG + r * QS_STR + c4 * 4) * 4,
                       Kp + (size_t)(kt + r) * DHd + c4 * 4);
            cp_async16(smb + vsOff + (uint32_t)(s * VSTG + r * VS_STR + c4 * 4) * 4,
                       Vp + (size_t)(kt + r) * DHd + c4 * 4);
        }
        CP_COMMIT();
    };

    // Load Q tile (128x64), raw bits
#pragma unroll
    for (int i = 0; i < 16; i++) {
        int idx = tid + 128 * i;
        int r = idx >> 4, c4 = idx & 15;
        float4 v = *(const float4*)(Qp + (size_t)(qBase + r) * DHd + c4 * 4);
        *(float4*)&Qs[r * QS_STR + c4 * 4] = v;
    }

    issue_kv(0, 0);
    issue_kv(64, 1);

    float mreg[4], lreg[4];          // [mt*2 + rr]
#pragma unroll
    for (int i = 0; i < 4; i++) { mreg[i] = -1e30f; lreg[i] = 0.f; }
    float o[2][8][4];
#pragma unroll
    for (int mt = 0; mt < 2; mt++)
#pragma unroll
        for (int nt = 0; nt < 8; nt++)
#pragma unroll
            for (int e = 0; e < 4; e++) o[mt][nt][e] = 0.f;

    // shuffle sources for C-frag -> A-frag (P matrix)
    const int srcA = (lane & 0x1c) | (q >> 1);
    const int srcB = srcA + 2;
    const bool qodd = (q & 1);

    // ldmatrix lane mappings
    const int lrow = ((lane >> 3) & 1) * 8 + (lane & 7);   // A-pattern (Q)
    const int lcol = (lane >> 4) * 4;
    const int krow = ((lane >> 4) & 1) * 8 + (lane & 7);   // K-pattern (2 nt x 2 cols)
    const int kcol = ((lane >> 3) & 1) * 4;
    const uint32_t qB = smb + (uint32_t)((wid * 32 + lrow) * QS_STR + lcol) * 4;

    for (int t = 0; t < 16; t++) {
        if (t < 15) asm volatile("cp.async.wait_group 1;");
        else        asm volatile("cp.async.wait_group 0;");
        __syncthreads();

        const uint32_t kB = smb + ksOff +
            (uint32_t)((t & 1) * KSTG + krow * QS_STR + kcol) * 4;
        const uint32_t* Vs = VsB + (t & 1) * VSTG;

        // prefetch mask words (bit-packed): 4 rows x 2 words
        uint2 mw[4];
#pragma unroll
        for (int mt = 0; mt < 2; mt++) {
            const int rloc = wid * 32 + mt * 16 + gid;
            mw[mt * 2 + 0] = *(const uint2*)(mb + (size_t)(qBase + rloc) * 32 + t * 2);
            mw[mt * 2 + 1] = *(const uint2*)(mb + (size_t)(qBase + rloc + 8) * 32 + t * 2);
        }

        // ---- S = Q K^T ----
        float s[2][8][4];
#pragma unroll
        for (int mt = 0; mt < 2; mt++)
#pragma unroll
            for (int nt = 0; nt < 8; nt++)
#pragma unroll
                for (int e = 0; e < 4; e++) s[mt][nt][e] = 0.f;

#pragma unroll
        for (int ks = 0; ks < 8; ks++) {
            uint32_t a[2][4];
#pragma unroll
            for (int mt = 0; mt < 2; mt++)
                ldsm_x4(a[mt][0], a[mt][1], a[mt][2], a[mt][3],
                        qB + (uint32_t)(mt * 16 * QS_STR + ks * 8) * 4);
#pragma unroll
            for (int ntp = 0; ntp < 4; ntp++) {
                uint32_t b0, b1, b2, b3;   // b0,b1: nt=2ntp ; b2,b3: nt=2ntp+1
                ldsm_x4(b0, b1, b2, b3,
                        kB + (uint32_t)(ntp * 16 * QS_STR + ks * 8) * 4);
                mma_tf32_16x8x8(s[0][2*ntp][0], s[0][2*ntp][1], s[0][2*ntp][2], s[0][2*ntp][3],
                                a[0][0], a[0][1], a[0][2], a[0][3], b0, b1);
                mma_tf32_16x8x8(s[1][2*ntp][0], s[1][2*ntp][1], s[1][2*ntp][2], s[1][2*ntp][3],
                                a[1][0], a[1][1], a[1][2], a[1][3], b0, b1);
                mma_tf32_16x8x8(s[0][2*ntp+1][0], s[0][2*ntp+1][1], s[0][2*ntp+1][2], s[0][2*ntp+1][3],
                                a[0][0], a[0][1], a[0][2], a[0][3], b2, b3);
                mma_tf32_16x8x8(s[1][2*ntp+1][0], s[1][2*ntp+1][1], s[1][2*ntp+1][2], s[1][2*ntp+1][3],
                                a[1][0], a[1][1], a[1][2], a[1][3], b2, b3);
            }
        }

        // ---- mask + online softmax per mt (exp'd P stays in s regs) ----
#pragma unroll
        for (int mt = 0; mt < 2; mt++) {
            const uint2 w0 = mw[mt * 2 + 0];
            const uint2 w1 = mw[mt * 2 + 1];
            float mx0 = -1e30f, mx1 = -1e30f;
#pragma unroll
            for (int nt = 0; nt < 8; nt++) {
                const int sh = (nt & 3) * 8 + 2 * q;
                const uint32_t wa = (nt < 4) ? w0.x : w0.y;
                const uint32_t wb = (nt < 4) ? w1.x : w1.y;
                s[mt][nt][0] = ((wa >> sh) & 1u)       ? s[mt][nt][0] : -1e9f;
                s[mt][nt][1] = ((wa >> (sh + 1)) & 1u) ? s[mt][nt][1] : -1e9f;
                s[mt][nt][2] = ((wb >> sh) & 1u)       ? s[mt][nt][2] : -1e9f;
                s[mt][nt][3] = ((wb >> (sh + 1)) & 1u) ? s[mt][nt][3] : -1e9f;
                mx0 = fmaxf(mx0, fmaxf(s[mt][nt][0], s[mt][nt][1]));
                mx1 = fmaxf(mx1, fmaxf(s[mt][nt][2], s[mt][nt][3]));
            }
            mx0 = fmaxf(mx0, __shfl_xor_sync(0xffffffffu, mx0, 1));
            mx0 = fmaxf(mx0, __shfl_xor_sync(0xffffffffu, mx0, 2));
            mx1 = fmaxf(mx1, __shfl_xor_sync(0xffffffffu, mx1, 1));
            mx1 = fmaxf(mx1, __shfl_xor_sync(0xffffffffu, mx1, 2));
            const float mn0 = fmaxf(mreg[mt * 2 + 0], mx0);
            const float mn1 = fmaxf(mreg[mt * 2 + 1], mx1);
            const float corr0 = __expf(mreg[mt * 2 + 0] - mn0);
            const float corr1 = __expf(mreg[mt * 2 + 1] - mn1);

            float rs0 = 0.f, rs1 = 0.f;
#pragma unroll
            for (int nt = 0; nt < 8; nt++) {
                s[mt][nt][0] = __expf(s[mt][nt][0] - mn0);
                s[mt][nt][1] = __expf(s[mt][nt][1] - mn0);
                s[mt][nt][2] = __expf(s[mt][nt][2] - mn1);
                s[mt][nt][3] = __expf(s[mt][nt][3] - mn1);
                rs0 += s[mt][nt][0] + s[mt][nt][1];
                rs1 += s[mt][nt][2] + s[mt][nt][3];
            }
            rs0 += __shfl_xor_sync(0xffffffffu, rs0, 1);
            rs0 += __shfl_xor_sync(0xffffffffu, rs0, 2);
            rs1 += __shfl_xor_sync(0xffffffffu, rs1, 1);
            rs1 += __shfl_xor_sync(0xffffffffu, rs1, 2);
            lreg[mt * 2 + 0] = lreg[mt * 2 + 0] * corr0 + rs0;
            lreg[mt * 2 + 1] = lreg[mt * 2 + 1] * corr1 + rs1;
            mreg[mt * 2 + 0] = mn0;
            mreg[mt * 2 + 1] = mn1;
#pragma unroll
            for (int nt = 0; nt < 8; nt++) {
                o[mt][nt][0] *= corr0; o[mt][nt][1] *= corr0;
                o[mt][nt][2] *= corr1; o[mt][nt][3] *= corr1;
            }
        }

        // ---- O += P V : A-frags built from s regs via quad shuffles ----
#pragma unroll
        for (int ks = 0; ks < 8; ks++) {
            uint32_t a[2][4];
#pragma unroll
            for (int mt = 0; mt < 2; mt++) {
                float e0 = __shfl_sync(0xffffffffu, s[mt][ks][0], srcA);
                float o0 = __shfl_sync(0xffffffffu, s[mt][ks][1], srcA);
                float e1 = __shfl_sync(0xffffffffu, s[mt][ks][2], srcA);
                float o1 = __shfl_sync(0xffffffffu, s[mt][ks][3], srcA);
                float e2 = __shfl_sync(0xffffffffu, s[mt][ks][0], srcB);
                float o2 = __shfl_sync(0xffffffffu, s[mt][ks][1], srcB);
                float e3 = __shfl_sync(0xffffffffu, s[mt][ks][2], srcB);
                float o3 = __shfl_sync(0xffffffffu, s[mt][ks][3], srcB);
                a[mt][0] = __float_as_uint(qodd ? o0 : e0);
                a[mt][1] = __float_as_uint(qodd ? o1 : e1);
                a[mt][2] = __float_as_uint(qodd ? o2 : e2);
                a[mt][3] = __float_as_uint(qodd ? o3 : e3);
            }
#pragma unroll
            for (int nt = 0; nt < 8; nt++) {
                int nd = nt * 8 + gid;
                uint32_t b0 = Vs[(ks * 8 + q) * VS_STR + nd];
                uint32_t b1 = Vs[(ks * 8 + q + 4) * VS_STR + nd];
                mma_tf32_16x8x8(o[0][nt][0], o[0][nt][1], o[0][nt][2], o[0][nt][3],
                                a[0][0], a[0][1], a[0][2], a[0][3], b0, b1);
                mma_tf32_16x8x8(o[1][nt][0], o[1][nt][1], o[1][nt][2], o[1][nt][3],
                                a[1][0], a[1][1], a[1][2], a[1][3], b0, b1);
            }
        }

        __syncthreads();
        if (t + 2 < 16) issue_kv((t + 2) * 64, t & 1);
    }

    // normalize + store to g_CTX [b][n][h*64+d]
    float* cbase = g_CTX + ((size_t)(b * Nn + qBase) * Hh) + h * DHd;
#pragma unroll
    for (int mt = 0; mt < 2; mt++) {
        const int r0 = wid * 32 + mt * 16 + gid;
        const int r1 = r0 + 8;
        const float inv0 = 1.f / lreg[mt * 2 + 0];
        const float inv1 = 1.f / lreg[mt * 2 + 1];
#pragma unroll
        for (int nt = 0; nt < 8; nt++) {
            const int d0 = nt * 8 + 2 * q;
            float2 v0, v1;
            v0.x = o[mt][nt][0] * inv0; v0.y = o[mt][nt][1] * inv0;
            v1.x = o[mt][nt][2] * inv1; v1.y = o[mt][nt][3] * inv1;
            *(float2*)(cbase + (size_t)r0 * Hh + d0) = v0;
            *(float2*)(cbase + (size_t)r1 * Hh + d0) = v1;
        }
    }
}

// ---------------------------------------------------------------------------
// LayerNorm (eps=1e-12) over g_Y rows + gather the two per-batch rows.
// ---------------------------------------------------------------------------
__global__ void __launch_bounds__(256) ln_kernel(
    const float* __restrict__ gamma, const float* __restrict__ beta,
    const int* __restrict__ conv_len, float* __restrict__ out)
{
    const int row = blockIdx.x;
    const int tid = threadIdx.x;
    const float* yr = g_Y + (size_t)row * Hh;
    float4 x = *(const float4*)(yr + (tid << 2));

    __shared__ float red[8];
    __shared__ float mu_sh, rstd_sh;

    float s1 = x.x + x.y + x.z + x.w;
#pragma unroll
    for (int off = 16; off; off >>= 1) s1 += __shfl_xor_sync(0xffffffffu, s1, off);
    int w = tid >> 5, lane = tid & 31;
    if (lane == 0) red[w] = s1;
    __syncthreads();
    if (tid == 0) {
        float t = 0.f;
#pragma unroll
        for (int i = 0; i < 8; i++) t += red[i];
        mu_sh = t * (1.f / 1024.f);
    }
    __syncthreads();
    float mu = mu_sh;
    float d0 = x.x - mu, d1 = x.y - mu, d2 = x.z - mu, d3 = x.w - mu;
    float s2 = d0 * d0 + d1 * d1 + d2 * d2 + d3 * d3;
#pragma unroll
    for (int off = 16; off; off >>= 1) s2 += __shfl_xor_sync(0xffffffffu, s2, off);
    if (lane == 0) red[w] = s2;
    __syncthreads();
    if (tid == 0) {
        float t = 0.f;
#pragma unroll
        for (int i = 0; i < 8; i++) t += red[i];
        rstd_sh = rsqrtf(t * (1.f / 1024.f) + 1e-12f);
    }
    __syncthreads();
    float rstd = rstd_sh;

    float4 g = *(const float4*)(gamma + (tid << 2));
    float4 be = *(const float4*)(beta + (tid << 2));
    float4 r;
    r.x = d0 * rstd * g.x + be.x;
    r.y = d1 * rstd * g.y + be.y;
    r.z = d2 * rstd * g.z + be.z;
    r.w = d3 * rstd * g.w + be.w;
    *(float4*)(out + (size_t)row * Hh + (tid << 2)) = r;

    int b_ = row >> 10, n_ = row & 1023;
    int base = 6 * conv_len[b_];
    if (n_ == base + 3)
        *(float4*)(out + (size_t)Mm * Hh + (size_t)b_ * Hh + (tid << 2)) = r;
    if (n_ == base + 2)
        *(float4*)(out + (size_t)Mm * Hh + (size_t)Bb * Hh + (size_t)b_ * Hh + (tid << 2)) = r;
}

// ---------------------------------------------------------------------------
extern "C" void kernel_launch(void* const* d_in, const int* in_sizes, int n_in,
                              void* d_out, int out_size)
{
    const float* hidden    = (const float*)d_in[0];
    const int*   role_mask = (const int*)d_in[1];
    const int*   conv_len  = (const int*)d_in[2];
    const float* Wq = (const float*)d_in[3];
    const float* bq = (const float*)d_in[4];
    const float* Wk = (const float*)d_in[5];
    const float* bk = (const float*)d_in[6];
    const float* Wv = (const float*)d_in[7];
    const float* bv = (const float*)d_in[8];
    const float* Wo = (const float*)d_in[9];
    const float* bo = (const float*)d_in[10];
    const float* gamma = (const float*)d_in[11];
    const float* beta  = (const float*)d_in[12];
    float* out = (float*)d_out;

    float *Qp, *Kp, *Vp, *Cp, *Yp;
    cudaGetSymbolAddress((void**)&Qp, g_Q);
    cudaGetSymbolAddress((void**)&Kp, g_K);
    cudaGetSymbolAddress((void**)&Vp, g_V);
    cudaGetSymbolAddress((void**)&Cp, g_CTX);
    cudaGetSymbolAddress((void**)&Yp, g_Y);

    cudaFuncSetAttribute(tf32_gemm_mma, cudaFuncAttributeMaxDynamicSharedMemorySize, GEMM_SMEM);
    cudaFuncSetAttribute(attn_mma, cudaFuncAttributeMaxDynamicSharedMemorySize, ATTN_SMEM);

    pack_mask<<<32768, 256>>>(role_mask);

    // fused QKV: z selects weight/bias/output
    tf32_gemm_mma<<<dim3(8, 64, 3), 256, GEMM_SMEM>>>(
        hidden, Wq, Wk, Wv, bq, bk, bv, Qp, Kp, Vp, nullptr, 0);

    attn_mma<<<dim3(Nn / 128, Bb * NHEADS), 128, ATTN_SMEM>>>();

    tf32_gemm_mma<<<dim3(8, 64, 1), 256, GEMM_SMEM>>>(
        Cp, Wo, Wo, Wo, bo, bo, bo, Yp, Yp, Yp, hidden, 1);

    ln_kernel<<<Mm, 256>>>(gamma, beta, conv_len, out);
}

// round 15
// speedup vs baseline: 4.7717x; 1.4523x over previous
#include <cuda_runtime.h>
#include <cuda_fp16.h>
#include <math.h>
#include <stdint.h>

#define Bb 8
#define Nn 1024
#define Hh 1024
#define NHEADS 16
#define DHd 64
#define Mm (Bb*Nn)   // 8192

// Scratch (device globals: allocation-free rule)
__device__ __half g_H16[(size_t)Mm*Hh];          // hidden fp16
__device__ __half g_WqT[(size_t)Hh*Hh];          // W^T fp16 [n][k]
__device__ __half g_WkT[(size_t)Hh*Hh];
__device__ __half g_WvT[(size_t)Hh*Hh];
__device__ __half g_WoT[(size_t)Hh*Hh];
__device__ __half g_Q[(size_t)Bb*NHEADS*Nn*DHd];
__device__ __half g_K[(size_t)Bb*NHEADS*Nn*DHd];
__device__ __half g_V[(size_t)Bb*NHEADS*Nn*DHd];
__device__ __half g_CTX[(size_t)Mm*Hh];
__device__ float  g_Y[(size_t)Mm*Hh];
__device__ uint32_t g_MBITS[(size_t)Bb*Nn*32];   // bit-packed role_mask

// ===========================================================================
// helpers (arch-suffix-free PTX)
// ===========================================================================
__device__ __forceinline__ uint32_t smem_to_u32(const void* p) {
    uint32_t a;
    asm("{ .reg .u64 t; cvta.to.shared.u64 t, %1; cvt.u32.u64 %0, t; }"
        : "=r"(a) : "l"(p));
    return a;
}
__device__ __forceinline__ void cp_async16(uint32_t dst, const void* src) {
    asm volatile("cp.async.ca.shared.global [%0], [%1], 16;" :: "r"(dst), "l"(src));
}
#define CP_COMMIT() asm volatile("cp.async.commit_group;")

__device__ __forceinline__ void ldsm_x4(uint32_t& r0, uint32_t& r1,
                                        uint32_t& r2, uint32_t& r3, uint32_t addr)
{
    asm volatile("ldmatrix.sync.aligned.m8n8.x4.shared.b16 {%0,%1,%2,%3}, [%4];"
        : "=r"(r0), "=r"(r1), "=r"(r2), "=r"(r3) : "r"(addr));
}
__device__ __forceinline__ void ldsm_x4t(uint32_t& r0, uint32_t& r1,
                                         uint32_t& r2, uint32_t& r3, uint32_t addr)
{
    asm volatile("ldmatrix.sync.aligned.m8n8.x4.trans.shared.b16 {%0,%1,%2,%3}, [%4];"
        : "=r"(r0), "=r"(r1), "=r"(r2), "=r"(r3) : "r"(addr));
}

// fp16 mma, fp32 accumulate: m16n8k16
__device__ __forceinline__ void mma_f16(
    float& c0, float& c1, float& c2, float& c3,
    uint32_t a0, uint32_t a1, uint32_t a2, uint32_t a3,
    uint32_t b0, uint32_t b1)
{
    asm volatile(
        "mma.sync.aligned.m16n8k16.row.col.f32.f16.f16.f32 "
        "{%0,%1,%2,%3}, {%4,%5,%6,%7}, {%8,%9}, {%0,%1,%2,%3};"
        : "+f"(c0), "+f"(c1), "+f"(c2), "+f"(c3)
        : "r"(a0), "r"(a1), "r"(a2), "r"(a3), "r"(b0), "r"(b1));
}
__device__ __forceinline__ uint32_t packh2(float x, float y) {
    __half2 h = __float22half2_rn(make_float2(x, y));
    return *(uint32_t*)&h;
}

// ===========================================================================
// Pre-pass kernels
// ===========================================================================
__global__ void __launch_bounds__(256) pack_mask(const int* __restrict__ mask)
{
    const int lane = threadIdx.x & 31;
    const size_t task = (size_t)blockIdx.x * 8 + (threadIdx.x >> 5);
    const size_t row = task >> 5;
    const int wcol = (int)(task & 31);
    int v = mask[row * 1024 + wcol * 32 + lane];
    uint32_t bits = __ballot_sync(0xffffffffu, v != 0);
    if (lane == 0) g_MBITS[row * 32 + wcol] = bits;
}

__global__ void __launch_bounds__(256) conv_hidden(const float* __restrict__ in)
{
    size_t i = ((size_t)blockIdx.x * 256 + threadIdx.x) * 8;
    float4 a = *(const float4*)(in + i);
    float4 b = *(const float4*)(in + i + 4);
    __half2 h[4];
    h[0] = __float22half2_rn(make_float2(a.x, a.y));
    h[1] = __float22half2_rn(make_float2(a.z, a.w));
    h[2] = __float22half2_rn(make_float2(b.x, b.y));
    h[3] = __float22half2_rn(make_float2(b.z, b.w));
    *(float4*)(g_H16 + i) = *(float4*)h;
}

// transpose + convert: Wt[n][k] = (half)W[k][n]; z selects which W
__global__ void __launch_bounds__(256) convT_w(
    const float* __restrict__ W0, const float* __restrict__ W1,
    const float* __restrict__ W2, const float* __restrict__ W3)
{
    __shared__ float t[32][33];
    const float* in;
    __half* out;
    if (blockIdx.z == 0)      { in = W0; out = g_WqT; }
    else if (blockIdx.z == 1) { in = W1; out = g_WkT; }
    else if (blockIdx.z == 2) { in = W2; out = g_WvT; }
    else                      { in = W3; out = g_WoT; }
    int tx = threadIdx.x, ty = threadIdx.y;
    int xi = blockIdx.x * 32 + tx;
    int y0 = blockIdx.y * 32;
#pragma unroll
    for (int i = ty; i < 32; i += 8)
        t[i][tx] = in[(size_t)(y0 + i) * 1024 + xi];
    __syncthreads();
    int xo = y0 + tx;
    int yo0 = blockIdx.x * 32;
#pragma unroll
    for (int i = ty; i < 32; i += 8)
        out[(size_t)(yo0 + i) * 1024 + xo] = __float2half(t[tx][i]);
}

// ===========================================================================
// fp16 mma GEMM: out = A[8192,1024] @ Wt^T (+bias, +resid)
// A fp16 [m][k], B fp16 [n][k] (pre-transposed). CTA 128x128, BK=32,
// 8 warps (warp tile 64x32). 3-stage cp.async. All fragments via ldmatrix.
// mode 0: fused QKV (blockIdx.z selects), out fp16 head layout, alpha on z=0
// mode 1: out fp32 row-major + bias + resid
// ===========================================================================
#define SMS 20          // smem row stride in words (= 40 fp16 = 80 B)
#define A_STAGE (128*SMS)
#define B_STAGE (128*SMS)
#define NSTAGE 3
#define GEMM_SMEM (NSTAGE*(A_STAGE + B_STAGE)*4)   // 61440 B

__global__ void __launch_bounds__(256) f16_gemm(
    const __half* __restrict__ A,
    const __half* __restrict__ Wta, const __half* __restrict__ Wtb, const __half* __restrict__ Wtc,
    const float* __restrict__ ba, const float* __restrict__ bb, const float* __restrict__ bc,
    void* __restrict__ oa, void* __restrict__ ob, void* __restrict__ oc,
    const float* __restrict__ resid, int mode)
{
    extern __shared__ uint32_t gsm[];
    const uint32_t smb = smem_to_u32(gsm);

    const int tid = threadIdx.x;
    const int lane = tid & 31, wid = tid >> 5;
    const int warpM = wid & 1;
    const int warpN = wid >> 1;
    const int gid = lane >> 2;
    const int q = lane & 3;
    const int rowBase = blockIdx.y * 128;
    const int colBase = blockIdx.x * 128;

    const __half* Wt; const float* bias; void* out; float alpha;
    if (mode == 0) {
        if (blockIdx.z == 0)      { Wt = Wta; bias = ba; out = oa; alpha = 0.125f; }
        else if (blockIdx.z == 1) { Wt = Wtb; bias = bb; out = ob; alpha = 1.0f; }
        else                      { Wt = Wtc; bias = bc; out = oc; alpha = 1.0f; }
    } else { Wt = Wta; bias = ba; out = oa; alpha = 1.0f; }

    const __half* Abase = A + (size_t)rowBase * 1024;
    const __half* Bbase = Wt + (size_t)colBase * 1024;

    auto issue = [&](int c, int s) {
#pragma unroll
        for (int i = 0; i < 2; i++) {
            int idx = tid + 256 * i;
            int r = idx >> 2, g = idx & 3;
            cp_async16(smb + (uint32_t)(s * A_STAGE + r * SMS) * 4 + g * 16,
                       Abase + (size_t)r * 1024 + c * 32 + g * 8);
        }
#pragma unroll
        for (int i = 0; i < 2; i++) {
            int idx = tid + 256 * i;
            int r = idx >> 2, g = idx & 3;
            cp_async16(smb + (uint32_t)(NSTAGE * A_STAGE + s * B_STAGE + r * SMS) * 4 + g * 16,
                       Bbase + (size_t)r * 1024 + c * 32 + g * 8);
        }
        CP_COMMIT();
    };

    float acc[4][4][4];
#pragma unroll
    for (int mt = 0; mt < 4; mt++)
#pragma unroll
        for (int nt = 0; nt < 4; nt++)
#pragma unroll
            for (int e = 0; e < 4; e++) acc[mt][nt][e] = 0.f;

    issue(0, 0);
    issue(1, 1);
    issue(2, 2);

    // ldmatrix lane mapping:
    // A (x4: rows0-7, rows8-15, cols+8 pair): row=(l&7)+((l>>3)&1)*8, colb=(l>>4)*16
    const int arow = (lane & 7) + ((lane >> 3) & 1) * 8;
    const int acolb = (lane >> 4) * 16;
    // B (x4: [n rows | k+8 cols | n+8 rows]): row=(l&7)+((l>>4)&1)*8, colb=((l>>3)&1)*16
    const int brow = (lane & 7) + ((lane >> 4) & 1) * 8;
    const int bcolb = ((lane >> 3) & 1) * 16;

    int st = 0;
    for (int c = 0; c < 32; c++) {
        if (c < 30)       asm volatile("cp.async.wait_group 2;");
        else if (c == 30) asm volatile("cp.async.wait_group 1;");
        else              asm volatile("cp.async.wait_group 0;");
        __syncthreads();

        const uint32_t aB = smb + (uint32_t)(st * A_STAGE + (warpM * 64 + arow) * SMS) * 4 + acolb;
        const uint32_t bB = smb + (uint32_t)(NSTAGE * A_STAGE + st * B_STAGE
                                             + (warpN * 32 + brow) * SMS) * 4 + bcolb;

#pragma unroll
        for (int ks = 0; ks < 2; ks++) {
            uint32_t af[4][4];
#pragma unroll
            for (int mt = 0; mt < 4; mt++)
                ldsm_x4(af[mt][0], af[mt][1], af[mt][2], af[mt][3],
                        aB + mt * 16 * (SMS * 4) + ks * 32);
            uint32_t bf[4][2];
#pragma unroll
            for (int ntp = 0; ntp < 2; ntp++)
                ldsm_x4(bf[2 * ntp][0], bf[2 * ntp][1], bf[2 * ntp + 1][0], bf[2 * ntp + 1][1],
                        bB + ntp * 16 * (SMS * 4) + ks * 32);
#pragma unroll
            for (int mt = 0; mt < 4; mt++)
#pragma unroll
                for (int nt = 0; nt < 4; nt++)
                    mma_f16(acc[mt][nt][0], acc[mt][nt][1], acc[mt][nt][2], acc[mt][nt][3],
                            af[mt][0], af[mt][1], af[mt][2], af[mt][3],
                            bf[nt][0], bf[nt][1]);
        }
        __syncthreads();
        if (c + 3 < 32) issue(c + 3, st);
        st = (st == 2) ? 0 : st + 1;
    }

#pragma unroll
    for (int mt = 0; mt < 4; mt++) {
        const int row0 = rowBase + warpM * 64 + mt * 16 + gid;
        const int row1 = row0 + 8;
#pragma unroll
        for (int nt = 0; nt < 4; nt++) {
            const int gcol = colBase + warpN * 32 + nt * 8 + 2 * q;
            const float b0 = bias[gcol], b1 = bias[gcol + 1];
            if (mode == 0) {
                const int head = gcol >> 6, d0 = gcol & 63;
                __half* op = (__half*)out;
#pragma unroll
                for (int rr = 0; rr < 2; rr++) {
                    const int row = rr ? row1 : row0;
                    const int b_ = row >> 10, n_ = row & 1023;
                    __half2 v = __float22half2_rn(make_float2(
                        (acc[mt][nt][rr * 2 + 0] + b0) * alpha,
                        (acc[mt][nt][rr * 2 + 1] + b1) * alpha));
                    *(__half2*)(op + (((size_t)(b_ * NHEADS + head) * Nn + n_) * DHd + d0)) = v;
                }
            } else {
                float* op = (float*)out;
#pragma unroll
                for (int rr = 0; rr < 2; rr++) {
                    const int row = rr ? row1 : row0;
                    const float2 rv = *(const float2*)(resid + (size_t)row * 1024 + gcol);
                    float2 v;
                    v.x = acc[mt][nt][rr * 2 + 0] + b0 + rv.x;
                    v.y = acc[mt][nt][rr * 2 + 1] + b1 + rv.y;
                    *(float2*)(op + (size_t)row * 1024 + gcol) = v;
                }
            }
        }
    }
}

// ===========================================================================
// fp16 flash attention. 4 warps, q-tile 128 (warp = 32 q-rows, 2 m16 tiles).
// Q/K fragments via ldmatrix, V via ldmatrix.trans, P packed in-register
// (no shuffles, no smem round-trip), K/V cp.async double buffer, bit mask.
// ===========================================================================
#define QSTR 36          // words per row (= 72 fp16)
#define KSTG (64*QSTR)
#define VSTG (64*QSTR)
#define ATTN_SMEM ((128*QSTR + 2*KSTG + 2*VSTG)*4)   // 55296 B

__global__ void __launch_bounds__(128, 2) attn_mma(void)
{
    extern __shared__ uint32_t smu[];
    const uint32_t smb = smem_to_u32(smu);
    const uint32_t ksOff = (uint32_t)(128 * QSTR) * 4;
    const uint32_t vsOff = ksOff + (uint32_t)(2 * KSTG) * 4;

    const int bh = blockIdx.y;
    const int b = bh >> 4;
    const int h = bh & 15;
    const int qBase = blockIdx.x * 128;
    const int tid = threadIdx.x;
    const int lane = tid & 31, wid = tid >> 5;
    const int gid = lane >> 2, q = lane & 3;

    const __half* Qp = g_Q + (size_t)bh * Nn * DHd;
    const __half* Kp = g_K + (size_t)bh * Nn * DHd;
    const __half* Vp = g_V + (size_t)bh * Nn * DHd;
    const uint32_t* mb = g_MBITS + ((size_t)b << 15);

    auto issue_kv = [&](int kt, int s) {
#pragma unroll
        for (int i = 0; i < 4; i++) {
            int idx = tid + 128 * i;
            int r = idx >> 3, g = idx & 7;
            cp_async16(smb + ksOff + (uint32_t)(s * KSTG + r * QSTR) * 4 + g * 16,
                       Kp + (size_t)(kt + r) * DHd + g * 8);
            cp_async16(smb + vsOff + (uint32_t)(s * VSTG + r * QSTR) * 4 + g * 16,
                       Vp + (size_t)(kt + r) * DHd + g * 8);
        }
        CP_COMMIT();
    };

    // Load Q tile (128 x 64 fp16)
#pragma unroll
    for (int i = 0; i < 8; i++) {
        int idx = tid + 128 * i;
        int r = idx >> 3, g = idx & 7;
        float4 v = *(const float4*)(Qp + (size_t)(qBase + r) * DHd + g * 8);
        *(float4*)((char*)smu + (size_t)(r * QSTR) * 4 + g * 16) = v;
    }

    issue_kv(0, 0);
    issue_kv(64, 1);

    float mreg[4], lreg[4];
#pragma unroll
    for (int i = 0; i < 4; i++) { mreg[i] = -1e30f; lreg[i] = 0.f; }
    float o[2][8][4];
#pragma unroll
    for (int mt = 0; mt < 2; mt++)
#pragma unroll
        for (int nt = 0; nt < 8; nt++)
#pragma unroll
            for (int e = 0; e < 4; e++) o[mt][nt][e] = 0.f;

    // ldmatrix lane mappings
    const int arow = (lane & 7) + ((lane >> 3) & 1) * 8;     // A (Q)
    const int acolb = (lane >> 4) * 16;
    const int brow = (lane & 7) + ((lane >> 4) & 1) * 8;     // B (K)
    const int bcolb = ((lane >> 3) & 1) * 16;
    const int vrow = (lane & 7) + ((lane >> 3) & 1) * 8;     // B (V, trans)
    const int vcolb = ((lane >> 4) & 1) * 16;
    const uint32_t qB = smb + (uint32_t)((wid * 32 + arow) * QSTR) * 4 + acolb;

    for (int t = 0; t < 16; t++) {
        if (t < 15) asm volatile("cp.async.wait_group 1;");
        else        asm volatile("cp.async.wait_group 0;");
        __syncthreads();

        const uint32_t kB = smb + ksOff + (uint32_t)((t & 1) * KSTG + brow * QSTR) * 4 + bcolb;
        const uint32_t vB = smb + vsOff + (uint32_t)((t & 1) * VSTG + vrow * QSTR) * 4 + vcolb;

        // mask words
        uint2 mw[4];
#pragma unroll
        for (int mt = 0; mt < 2; mt++) {
            const int rloc = wid * 32 + mt * 16 + gid;
            mw[mt * 2 + 0] = *(const uint2*)(mb + (size_t)(qBase + rloc) * 32 + t * 2);
            mw[mt * 2 + 1] = *(const uint2*)(mb + (size_t)(qBase + rloc + 8) * 32 + t * 2);
        }

        // ---- S = Q K^T ----
        float s[2][8][4];
#pragma unroll
        for (int mt = 0; mt < 2; mt++)
#pragma unroll
            for (int nt = 0; nt < 8; nt++)
#pragma unroll
                for (int e = 0; e < 4; e++) s[mt][nt][e] = 0.f;

#pragma unroll
        for (int ks = 0; ks < 4; ks++) {
            uint32_t a[2][4];
#pragma unroll
            for (int mt = 0; mt < 2; mt++)
                ldsm_x4(a[mt][0], a[mt][1], a[mt][2], a[mt][3],
                        qB + mt * 16 * (QSTR * 4) + ks * 32);
#pragma unroll
            for (int ntp = 0; ntp < 4; ntp++) {
                uint32_t b0, b1, b2, b3;
                ldsm_x4(b0, b1, b2, b3, kB + ntp * 16 * (QSTR * 4) + ks * 32);
                mma_f16(s[0][2*ntp][0], s[0][2*ntp][1], s[0][2*ntp][2], s[0][2*ntp][3],
                        a[0][0], a[0][1], a[0][2], a[0][3], b0, b1);
                mma_f16(s[1][2*ntp][0], s[1][2*ntp][1], s[1][2*ntp][2], s[1][2*ntp][3],
                        a[1][0], a[1][1], a[1][2], a[1][3], b0, b1);
                mma_f16(s[0][2*ntp+1][0], s[0][2*ntp+1][1], s[0][2*ntp+1][2], s[0][2*ntp+1][3],
                        a[0][0], a[0][1], a[0][2], a[0][3], b2, b3);
                mma_f16(s[1][2*ntp+1][0], s[1][2*ntp+1][1], s[1][2*ntp+1][2], s[1][2*ntp+1][3],
                        a[1][0], a[1][1], a[1][2], a[1][3], b2, b3);
            }
        }

        // ---- mask + online softmax ----
#pragma unroll
        for (int mt = 0; mt < 2; mt++) {
            const uint2 w0 = mw[mt * 2 + 0];
            const uint2 w1 = mw[mt * 2 + 1];
            float mx0 = -1e30f, mx1 = -1e30f;
#pragma unroll
            for (int nt = 0; nt < 8; nt++) {
                const int sh = (nt & 3) * 8 + 2 * q;
                const uint32_t wa = (nt < 4) ? w0.x : w0.y;
                const uint32_t wb = (nt < 4) ? w1.x : w1.y;
                s[mt][nt][0] = ((wa >> sh) & 1u)       ? s[mt][nt][0] : -1e9f;
                s[mt][nt][1] = ((wa >> (sh + 1)) & 1u) ? s[mt][nt][1] : -1e9f;
                s[mt][nt][2] = ((wb >> sh) & 1u)       ? s[mt][nt][2] : -1e9f;
                s[mt][nt][3] = ((wb >> (sh + 1)) & 1u) ? s[mt][nt][3] : -1e9f;
                mx0 = fmaxf(mx0, fmaxf(s[mt][nt][0], s[mt][nt][1]));
                mx1 = fmaxf(mx1, fmaxf(s[mt][nt][2], s[mt][nt][3]));
            }
            mx0 = fmaxf(mx0, __shfl_xor_sync(0xffffffffu, mx0, 1));
            mx0 = fmaxf(mx0, __shfl_xor_sync(0xffffffffu, mx0, 2));
            mx1 = fmaxf(mx1, __shfl_xor_sync(0xffffffffu, mx1, 1));
            mx1 = fmaxf(mx1, __shfl_xor_sync(0xffffffffu, mx1, 2));
            const float mn0 = fmaxf(mreg[mt * 2 + 0], mx0);
            const float mn1 = fmaxf(mreg[mt * 2 + 1], mx1);
            const float corr0 = __expf(mreg[mt * 2 + 0] - mn0);
            const float corr1 = __expf(mreg[mt * 2 + 1] - mn1);

            float rs0 = 0.f, rs1 = 0.f;
#pragma unroll
            for (int nt = 0; nt < 8; nt++) {
                s[mt][nt][0] = __expf(s[mt][nt][0] - mn0);
                s[mt][nt][1] = __expf(s[mt][nt][1] - mn0);
                s[mt][nt][2] = __expf(s[mt][nt][2] - mn1);
                s[mt][nt][3] = __expf(s[mt][nt][3] - mn1);
                rs0 += s[mt][nt][0] + s[mt][nt][1];
                rs1 += s[mt][nt][2] + s[mt][nt][3];
            }
            rs0 += __shfl_xor_sync(0xffffffffu, rs0, 1);
            rs0 += __shfl_xor_sync(0xffffffffu, rs0, 2);
            rs1 += __shfl_xor_sync(0xffffffffu, rs1, 1);
            rs1 += __shfl_xor_sync(0xffffffffu, rs1, 2);
            lreg[mt * 2 + 0] = lreg[mt * 2 + 0] * corr0 + rs0;
            lreg[mt * 2 + 1] = lreg[mt * 2 + 1] * corr1 + rs1;
            mreg[mt * 2 + 0] = mn0;
            mreg[mt * 2 + 1] = mn1;
#pragma unroll
            for (int nt = 0; nt < 8; nt++) {
                o[mt][nt][0] *= corr0; o[mt][nt][1] *= corr0;
                o[mt][nt][2] *= corr1; o[mt][nt][3] *= corr1;
            }
        }

        // ---- O += P V : P A-frags are the lane's own s values, packed ----
#pragma unroll
        for (int ks = 0; ks < 4; ks++) {
            uint32_t a[2][4];
#pragma unroll
            for (int mt = 0; mt < 2; mt++) {
                a[mt][0] = packh2(s[mt][2*ks][0],   s[mt][2*ks][1]);
                a[mt][1] = packh2(s[mt][2*ks][2],   s[mt][2*ks][3]);
                a[mt][2] = packh2(s[mt][2*ks+1][0], s[mt][2*ks+1][1]);
                a[mt][3] = packh2(s[mt][2*ks+1][2], s[mt][2*ks+1][3]);
            }
#pragma unroll
            for (int ntp = 0; ntp < 4; ntp++) {
                uint32_t b0, b1, b2, b3;
                ldsm_x4t(b0, b1, b2, b3, vB + ks * 16 * (QSTR * 4) + ntp * 32);
                mma_f16(o[0][2*ntp][0], o[0][2*ntp][1], o[0][2*ntp][2], o[0][2*ntp][3],
                        a[0][0], a[0][1], a[0][2], a[0][3], b0, b1);
                mma_f16(o[1][2*ntp][0], o[1][2*ntp][1], o[1][2*ntp][2], o[1][2*ntp][3],
                        a[1][0], a[1][1], a[1][2], a[1][3], b0, b1);
                mma_f16(o[0][2*ntp+1][0], o[0][2*ntp+1][1], o[0][2*ntp+1][2], o[0][2*ntp+1][3],
                        a[0][0], a[0][1], a[0][2], a[0][3], b2, b3);
                mma_f16(o[1][2*ntp+1][0], o[1][2*ntp+1][1], o[1][2*ntp+1][2], o[1][2*ntp+1][3],
                        a[1][0], a[1][1], a[1][2], a[1][3], b2, b3);
            }
        }

        __syncthreads();
        if (t + 2 < 16) issue_kv((t + 2) * 64, t & 1);
    }

    // normalize + store fp16 CTX [b][n][h*64+d]
    __half* cbase = g_CTX + ((size_t)(b * Nn + qBase) * Hh) + h * DHd;
#pragma unroll
    for (int mt = 0; mt < 2; mt++) {
        const int r0 = wid * 32 + mt * 16 + gid;
        const int r1 = r0 + 8;
        const float inv0 = 1.f / lreg[mt * 2 + 0];
        const float inv1 = 1.f / lreg[mt * 2 + 1];
#pragma unroll
        for (int nt = 0; nt < 8; nt++) {
            const int d0 = nt * 8 + 2 * q;
            *(__half2*)(cbase + (size_t)r0 * Hh + d0) =
                __float22half2_rn(make_float2(o[mt][nt][0] * inv0, o[mt][nt][1] * inv0));
            *(__half2*)(cbase + (size_t)r1 * Hh + d0) =
                __float22half2_rn(make_float2(o[mt][nt][2] * inv1, o[mt][nt][3] * inv1));
        }
    }
}

// ---------------------------------------------------------------------------
// LayerNorm (eps=1e-12) over g_Y rows + gather the two per-batch rows.
// ---------------------------------------------------------------------------
__global__ void __launch_bounds__(256) ln_kernel(
    const float* __restrict__ gamma, const float* __restrict__ beta,
    const int* __restrict__ conv_len, float* __restrict__ out)
{
    const int row = blockIdx.x;
    const int tid = threadIdx.x;
    const float* yr = g_Y + (size_t)row * Hh;
    float4 x = *(const float4*)(yr + (tid << 2));

    __shared__ float red[8];
    __shared__ float mu_sh, rstd_sh;

    float s1 = x.x + x.y + x.z + x.w;
#pragma unroll
    for (int off = 16; off; off >>= 1) s1 += __shfl_xor_sync(0xffffffffu, s1, off);
    int w = tid >> 5, lane = tid & 31;
    if (lane == 0) red[w] = s1;
    __syncthreads();
    if (tid == 0) {
        float t = 0.f;
#pragma unroll
        for (int i = 0; i < 8; i++) t += red[i];
        mu_sh = t * (1.f / 1024.f);
    }
    __syncthreads();
    float mu = mu_sh;
    float d0 = x.x - mu, d1 = x.y - mu, d2 = x.z - mu, d3 = x.w - mu;
    float s2 = d0 * d0 + d1 * d1 + d2 * d2 + d3 * d3;
#pragma unroll
    for (int off = 16; off; off >>= 1) s2 += __shfl_xor_sync(0xffffffffu, s2, off);
    if (lane == 0) red[w] = s2;
    __syncthreads();
    if (tid == 0) {
        float t = 0.f;
#pragma unroll
        for (int i = 0; i < 8; i++) t += red[i];
        rstd_sh = rsqrtf(t * (1.f / 1024.f) + 1e-12f);
    }
    __syncthreads();
    float rstd = rstd_sh;

    float4 g = *(const float4*)(gamma + (tid << 2));
    float4 be = *(const float4*)(beta + (tid << 2));
    float4 r;
    r.x = d0 * rstd * g.x + be.x;
    r.y = d1 * rstd * g.y + be.y;
    r.z = d2 * rstd * g.z + be.z;
    r.w = d3 * rstd * g.w + be.w;
    *(float4*)(out + (size_t)row * Hh + (tid << 2)) = r;

    int b_ = row >> 10, n_ = row & 1023;
    int base = 6 * conv_len[b_];
    if (n_ == base + 3)
        *(float4*)(out + (size_t)Mm * Hh + (size_t)b_ * Hh + (tid << 2)) = r;
    if (n_ == base + 2)
        *(float4*)(out + (size_t)Mm * Hh + (size_t)Bb * Hh + (size_t)b_ * Hh + (tid << 2)) = r;
}

// ---------------------------------------------------------------------------
extern "C" void kernel_launch(void* const* d_in, const int* in_sizes, int n_in,
                              void* d_out, int out_size)
{
    const float* hidden    = (const float*)d_in[0];
    const int*   role_mask = (const int*)d_in[1];
    const int*   conv_len  = (const int*)d_in[2];
    const float* Wq = (const float*)d_in[3];
    const float* bq = (const float*)d_in[4];
    const float* Wk = (const float*)d_in[5];
    const float* bk = (const float*)d_in[6];
    const float* Wv = (const float*)d_in[7];
    const float* bv = (const float*)d_in[8];
    const float* Wo = (const float*)d_in[9];
    const float* bo = (const float*)d_in[10];
    const float* gamma = (const float*)d_in[11];
    const float* beta  = (const float*)d_in[12];
    float* out = (float*)d_out;

    __half *H16p, *WqTp, *WkTp, *WvTp, *WoTp, *Qp, *Kp, *Vp, *Cp;
    float *Yp;
    cudaGetSymbolAddress((void**)&H16p, g_H16);
    cudaGetSymbolAddress((void**)&WqTp, g_WqT);
    cudaGetSymbolAddress((void**)&WkTp, g_WkT);
    cudaGetSymbolAddress((void**)&WvTp, g_WvT);
    cudaGetSymbolAddress((void**)&WoTp, g_WoT);
    cudaGetSymbolAddress((void**)&Qp, g_Q);
    cudaGetSymbolAddress((void**)&Kp, g_K);
    cudaGetSymbolAddress((void**)&Vp, g_V);
    cudaGetSymbolAddress((void**)&Cp, g_CTX);
    cudaGetSymbolAddress((void**)&Yp, g_Y);

    cudaFuncSetAttribute(f16_gemm, cudaFuncAttributeMaxDynamicSharedMemorySize, GEMM_SMEM);
    cudaFuncSetAttribute(attn_mma, cudaFuncAttributeMaxDynamicSharedMemorySize, ATTN_SMEM);

    pack_mask<<<32768, 256>>>(role_mask);
    conv_hidden<<<4096, 256>>>(hidden);
    convT_w<<<dim3(32, 32, 4), dim3(32, 8)>>>(Wq, Wk, Wv, Wo);

    // fused QKV (z selects weight/bias/output)
    f16_gemm<<<dim3(8, 64, 3), 256, GEMM_SMEM>>>(
        H16p, WqTp, WkTp, WvTp, bq, bk, bv, Qp, Kp, Vp, nullptr, 0);

    attn_mma<<<dim3(Nn / 128, Bb * NHEADS), 128, ATTN_SMEM>>>();

    f16_gemm<<<dim3(8, 64, 1), 256, GEMM_SMEM>>>(
        Cp, WoTp, WoTp, WoTp, bo, bo, bo, Yp, Yp, Yp, hidden, 1);

    ln_kernel<<<Mm, 256>>>(gamma, beta, conv_len, out);
}

// round 16
// speedup vs baseline: 5.7125x; 1.1972x over previous
#include <cuda_runtime.h>
#include <cuda_fp16.h>
#include <math.h>
#include <stdint.h>

#define Bb 8
#define Nn 1024
#define Hh 1024
#define NHEADS 16
#define DHd 64
#define Mm (Bb*Nn)   // 8192

// Scratch (device globals: allocation-free rule)
__device__ __half g_H16[(size_t)Mm*Hh];          // hidden fp16
__device__ __half g_WqT[(size_t)Hh*Hh];          // W^T fp16 [n][k]
__device__ __half g_WkT[(size_t)Hh*Hh];
__device__ __half g_WvT[(size_t)Hh*Hh];
__device__ __half g_WoT[(size_t)Hh*Hh];
__device__ __half g_Q[(size_t)Bb*NHEADS*Nn*DHd];
__device__ __half g_K[(size_t)Bb*NHEADS*Nn*DHd];
__device__ __half g_V[(size_t)Bb*NHEADS*Nn*DHd];
__device__ __half g_CTX[(size_t)Mm*Hh];
__device__ float  g_Y[(size_t)Mm*Hh];
__device__ uint32_t g_MBITS[(size_t)Bb*Nn*32];   // bit-packed role_mask

// ===========================================================================
// helpers (arch-suffix-free PTX)
// ===========================================================================
__device__ __forceinline__ uint32_t smem_to_u32(const void* p) {
    uint32_t a;
    asm("{ .reg .u64 t; cvta.to.shared.u64 t, %1; cvt.u32.u64 %0, t; }"
        : "=r"(a) : "l"(p));
    return a;
}
__device__ __forceinline__ void cp_async16(uint32_t dst, const void* src) {
    asm volatile("cp.async.ca.shared.global [%0], [%1], 16;" :: "r"(dst), "l"(src));
}
#define CP_COMMIT() asm volatile("cp.async.commit_group;")

__device__ __forceinline__ void ldsm_x4(uint32_t& r0, uint32_t& r1,
                                        uint32_t& r2, uint32_t& r3, uint32_t addr)
{
    asm volatile("ldmatrix.sync.aligned.m8n8.x4.shared.b16 {%0,%1,%2,%3}, [%4];"
        : "=r"(r0), "=r"(r1), "=r"(r2), "=r"(r3) : "r"(addr));
}
__device__ __forceinline__ void ldsm_x4t(uint32_t& r0, uint32_t& r1,
                                         uint32_t& r2, uint32_t& r3, uint32_t addr)
{
    asm volatile("ldmatrix.sync.aligned.m8n8.x4.trans.shared.b16 {%0,%1,%2,%3}, [%4];"
        : "=r"(r0), "=r"(r1), "=r"(r2), "=r"(r3) : "r"(addr));
}

// fp16 mma, fp32 accumulate: m16n8k16
__device__ __forceinline__ void mma_f16(
    float& c0, float& c1, float& c2, float& c3,
    uint32_t a0, uint32_t a1, uint32_t a2, uint32_t a3,
    uint32_t b0, uint32_t b1)
{
    asm volatile(
        "mma.sync.aligned.m16n8k16.row.col.f32.f16.f16.f32 "
        "{%0,%1,%2,%3}, {%4,%5,%6,%7}, {%8,%9}, {%0,%1,%2,%3};"
        : "+f"(c0), "+f"(c1), "+f"(c2), "+f"(c3)
        : "r"(a0), "r"(a1), "r"(a2), "r"(a3), "r"(b0), "r"(b1));
}
__device__ __forceinline__ uint32_t packh2(float x, float y) {
    __half2 h = __float22half2_rn(make_float2(x, y));
    return *(uint32_t*)&h;
}

// ===========================================================================
// Pre-pass kernels
// ===========================================================================
__global__ void __launch_bounds__(256) pack_mask(const int* __restrict__ mask)
{
    const int lane = threadIdx.x & 31;
    const size_t task = (size_t)blockIdx.x * 8 + (threadIdx.x >> 5);
    const size_t row = task >> 5;
    const int wcol = (int)(task & 31);
    int v = mask[row * 1024 + wcol * 32 + lane];
    uint32_t bits = __ballot_sync(0xffffffffu, v != 0);
    if (lane == 0) g_MBITS[row * 32 + wcol] = bits;
}

__global__ void __launch_bounds__(256) conv_hidden(const float* __restrict__ in)
{
    size_t i = ((size_t)blockIdx.x * 256 + threadIdx.x) * 8;
    float4 a = *(const float4*)(in + i);
    float4 b = *(const float4*)(in + i + 4);
    __half2 h[4];
    h[0] = __float22half2_rn(make_float2(a.x, a.y));
    h[1] = __float22half2_rn(make_float2(a.z, a.w));
    h[2] = __float22half2_rn(make_float2(b.x, b.y));
    h[3] = __float22half2_rn(make_float2(b.z, b.w));
    *(float4*)(g_H16 + i) = *(float4*)h;
}

// transpose + convert: Wt[n][k] = (half)W[k][n]; z selects which W
__global__ void __launch_bounds__(256) convT_w(
    const float* __restrict__ W0, const float* __restrict__ W1,
    const float* __restrict__ W2, const float* __restrict__ W3)
{
    __shared__ float t[32][33];
    const float* in;
    __half* out;
    if (blockIdx.z == 0)      { in = W0; out = g_WqT; }
    else if (blockIdx.z == 1) { in = W1; out = g_WkT; }
    else if (blockIdx.z == 2) { in = W2; out = g_WvT; }
    else                      { in = W3; out = g_WoT; }
    int tx = threadIdx.x, ty = threadIdx.y;
    int xi = blockIdx.x * 32 + tx;
    int y0 = blockIdx.y * 32;
#pragma unroll
    for (int i = ty; i < 32; i += 8)
        t[i][tx] = in[(size_t)(y0 + i) * 1024 + xi];
    __syncthreads();
    int xo = y0 + tx;
    int yo0 = blockIdx.x * 32;
#pragma unroll
    for (int i = ty; i < 32; i += 8)
        out[(size_t)(yo0 + i) * 1024 + xo] = __float2half(t[tx][i]);
}

// ===========================================================================
// fp16 mma GEMM: out = A[8192,1024] @ Wt^T (+bias, +resid)
// A fp16 [m][k], B fp16 [n][k] (pre-transposed). CTA 128x128, BK=32,
// 8 warps (warp tile 64x32). 3-stage cp.async. All fragments via ldmatrix.
// __launch_bounds__(256,2): cap 128 regs -> 2 CTAs/SM (16 warps).
// ===========================================================================
#define SMS 20          // smem row stride in words (= 40 fp16 = 80 B)
#define A_STAGE (128*SMS)
#define B_STAGE (128*SMS)
#define NSTAGE 3
#define GEMM_SMEM (NSTAGE*(A_STAGE + B_STAGE)*4)   // 61440 B

__global__ void __launch_bounds__(256, 2) f16_gemm(
    const __half* __restrict__ A,
    const __half* __restrict__ Wta, const __half* __restrict__ Wtb, const __half* __restrict__ Wtc,
    const float* __restrict__ ba, const float* __restrict__ bb, const float* __restrict__ bc,
    void* __restrict__ oa, void* __restrict__ ob, void* __restrict__ oc,
    const float* __restrict__ resid, int mode)
{
    extern __shared__ uint32_t gsm[];
    const uint32_t smb = smem_to_u32(gsm);

    const int tid = threadIdx.x;
    const int lane = tid & 31, wid = tid >> 5;
    const int warpM = wid & 1;
    const int warpN = wid >> 1;
    const int gid = lane >> 2;
    const int q = lane & 3;
    const int rowBase = blockIdx.y * 128;
    const int colBase = blockIdx.x * 128;

    const __half* Wt; const float* bias; void* out; float alpha;
    if (mode == 0) {
        if (blockIdx.z == 0)      { Wt = Wta; bias = ba; out = oa; alpha = 0.125f; }
        else if (blockIdx.z == 1) { Wt = Wtb; bias = bb; out = ob; alpha = 1.0f; }
        else                      { Wt = Wtc; bias = bc; out = oc; alpha = 1.0f; }
    } else { Wt = Wta; bias = ba; out = oa; alpha = 1.0f; }

    const __half* Abase = A + (size_t)rowBase * 1024;
    const __half* Bbase = Wt + (size_t)colBase * 1024;

    auto issue = [&](int c, int s) {
#pragma unroll
        for (int i = 0; i < 2; i++) {
            int idx = tid + 256 * i;
            int r = idx >> 2, g = idx & 3;
            cp_async16(smb + (uint32_t)(s * A_STAGE + r * SMS) * 4 + g * 16,
                       Abase + (size_t)r * 1024 + c * 32 + g * 8);
        }
#pragma unroll
        for (int i = 0; i < 2; i++) {
            int idx = tid + 256 * i;
            int r = idx >> 2, g = idx & 3;
            cp_async16(smb + (uint32_t)(NSTAGE * A_STAGE + s * B_STAGE + r * SMS) * 4 + g * 16,
                       Bbase + (size_t)r * 1024 + c * 32 + g * 8);
        }
        CP_COMMIT();
    };

    float acc[4][4][4];
#pragma unroll
    for (int mt = 0; mt < 4; mt++)
#pragma unroll
        for (int nt = 0; nt < 4; nt++)
#pragma unroll
            for (int e = 0; e < 4; e++) acc[mt][nt][e] = 0.f;

    issue(0, 0);
    issue(1, 1);
    issue(2, 2);

    const int arow = (lane & 7) + ((lane >> 3) & 1) * 8;
    const int acolb = (lane >> 4) * 16;
    const int brow = (lane & 7) + ((lane >> 4) & 1) * 8;
    const int bcolb = ((lane >> 3) & 1) * 16;

    int st = 0;
    for (int c = 0; c < 32; c++) {
        if (c < 30)       asm volatile("cp.async.wait_group 2;");
        else if (c == 30) asm volatile("cp.async.wait_group 1;");
        else              asm volatile("cp.async.wait_group 0;");
        __syncthreads();

        const uint32_t aB = smb + (uint32_t)(st * A_STAGE + (warpM * 64 + arow) * SMS) * 4 + acolb;
        const uint32_t bB = smb + (uint32_t)(NSTAGE * A_STAGE + st * B_STAGE
                                             + (warpN * 32 + brow) * SMS) * 4 + bcolb;

#pragma unroll
        for (int ks = 0; ks < 2; ks++) {
            uint32_t af[4][4];
#pragma unroll
            for (int mt = 0; mt < 4; mt++)
                ldsm_x4(af[mt][0], af[mt][1], af[mt][2], af[mt][3],
                        aB + mt * 16 * (SMS * 4) + ks * 32);
            uint32_t bf[4][2];
#pragma unroll
            for (int ntp = 0; ntp < 2; ntp++)
                ldsm_x4(bf[2 * ntp][0], bf[2 * ntp][1], bf[2 * ntp + 1][0], bf[2 * ntp + 1][1],
                        bB + ntp * 16 * (SMS * 4) + ks * 32);
#pragma unroll
            for (int mt = 0; mt < 4; mt++)
#pragma unroll
                for (int nt = 0; nt < 4; nt++)
                    mma_f16(acc[mt][nt][0], acc[mt][nt][1], acc[mt][nt][2], acc[mt][nt][3],
                            af[mt][0], af[mt][1], af[mt][2], af[mt][3],
                            bf[nt][0], bf[nt][1]);
        }
        __syncthreads();
        if (c + 3 < 32) issue(c + 3, st);
        st = (st == 2) ? 0 : st + 1;
    }

#pragma unroll
    for (int mt = 0; mt < 4; mt++) {
        const int row0 = rowBase + warpM * 64 + mt * 16 + gid;
        const int row1 = row0 + 8;
#pragma unroll
        for (int nt = 0; nt < 4; nt++) {
            const int gcol = colBase + warpN * 32 + nt * 8 + 2 * q;
            const float b0 = bias[gcol], b1 = bias[gcol + 1];
            if (mode == 0) {
                const int head = gcol >> 6, d0 = gcol & 63;
                __half* op = (__half*)out;
#pragma unroll
                for (int rr = 0; rr < 2; rr++) {
                    const int row = rr ? row1 : row0;
                    const int b_ = row >> 10, n_ = row & 1023;
                    __half2 v = __float22half2_rn(make_float2(
                        (acc[mt][nt][rr * 2 + 0] + b0) * alpha,
                        (acc[mt][nt][rr * 2 + 1] + b1) * alpha));
                    *(__half2*)(op + (((size_t)(b_ * NHEADS + head) * Nn + n_) * DHd + d0)) = v;
                }
            } else {
                float* op = (float*)out;
#pragma unroll
                for (int rr = 0; rr < 2; rr++) {
                    const int row = rr ? row1 : row0;
                    const float2 rv = *(const float2*)(resid + (size_t)row * 1024 + gcol);
                    float2 v;
                    v.x = acc[mt][nt][rr * 2 + 0] + b0 + rv.x;
                    v.y = acc[mt][nt][rr * 2 + 1] + b1 + rv.y;
                    *(float2*)(op + (size_t)row * 1024 + gcol) = v;
                }
            }
        }
    }
}

// ===========================================================================
// fp16 flash attention. 4 warps, q-tile 128 (warp = 32 q-rows, 2 m16 tiles).
// __launch_bounds__(128,3): 3 CTAs/SM (12 warps).
// ===========================================================================
#define QSTR 36          // words per row (= 72 fp16)
#define KSTG (64*QSTR)
#define VSTG (64*QSTR)
#define ATTN_SMEM ((128*QSTR + 2*KSTG + 2*VSTG)*4)   // 55296 B

__global__ void __launch_bounds__(128, 3) attn_mma(void)
{
    extern __shared__ uint32_t smu[];
    const uint32_t smb = smem_to_u32(smu);
    const uint32_t ksOff = (uint32_t)(128 * QSTR) * 4;
    const uint32_t vsOff = ksOff + (uint32_t)(2 * KSTG) * 4;

    const int bh = blockIdx.y;
    const int b = bh >> 4;
    const int h = bh & 15;
    const int qBase = blockIdx.x * 128;
    const int tid = threadIdx.x;
    const int lane = tid & 31, wid = tid >> 5;
    const int gid = lane >> 2, q = lane & 3;

    const __half* Qp = g_Q + (size_t)bh * Nn * DHd;
    const __half* Kp = g_K + (size_t)bh * Nn * DHd;
    const __half* Vp = g_V + (size_t)bh * Nn * DHd;
    const uint32_t* mb = g_MBITS + ((size_t)b << 15);

    auto issue_kv = [&](int kt, int s) {
#pragma unroll
        for (int i = 0; i < 4; i++) {
            int idx = tid + 128 * i;
            int r = idx >> 3, g = idx & 7;
            cp_async16(smb + ksOff + (uint32_t)(s * KSTG + r * QSTR) * 4 + g * 16,
                       Kp + (size_t)(kt + r) * DHd + g * 8);
            cp_async16(smb + vsOff + (uint32_t)(s * VSTG + r * QSTR) * 4 + g * 16,
                       Vp + (size_t)(kt + r) * DHd + g * 8);
        }
        CP_COMMIT();
    };

    // Load Q tile (128 x 64 fp16)
#pragma unroll
    for (int i = 0; i < 8; i++) {
        int idx = tid + 128 * i;
        int r = idx >> 3, g = idx & 7;
        float4 v = *(const float4*)(Qp + (size_t)(qBase + r) * DHd + g * 8);
        *(float4*)((char*)smu + (size_t)(r * QSTR) * 4 + g * 16) = v;
    }

    issue_kv(0, 0);
    issue_kv(64, 1);

    float mreg[4], lreg[4];
#pragma unroll
    for (int i = 0; i < 4; i++) { mreg[i] = -1e30f; lreg[i] = 0.f; }
    float o[2][8][4];
#pragma unroll
    for (int mt = 0; mt < 2; mt++)
#pragma unroll
        for (int nt = 0; nt < 8; nt++)
#pragma unroll
            for (int e = 0; e < 4; e++) o[mt][nt][e] = 0.f;

    const int arow = (lane & 7) + ((lane >> 3) & 1) * 8;     // A (Q)
    const int acolb = (lane >> 4) * 16;
    const int brow = (lane & 7) + ((lane >> 4) & 1) * 8;     // B (K)
    const int bcolb = ((lane >> 3) & 1) * 16;
    const int vrow = (lane & 7) + ((lane >> 3) & 1) * 8;     // B (V, trans)
    const int vcolb = ((lane >> 4) & 1) * 16;
    const uint32_t qB = smb + (uint32_t)((wid * 32 + arow) * QSTR) * 4 + acolb;

    for (int t = 0; t < 16; t++) {
        if (t < 15) asm volatile("cp.async.wait_group 1;");
        else        asm volatile("cp.async.wait_group 0;");
        __syncthreads();

        const uint32_t kB = smb + ksOff + (uint32_t)((t & 1) * KSTG + brow * QSTR) * 4 + bcolb;
        const uint32_t vB = smb + vsOff + (uint32_t)((t & 1) * VSTG + vrow * QSTR) * 4 + vcolb;

        uint2 mw[4];
#pragma unroll
        for (int mt = 0; mt < 2; mt++) {
            const int rloc = wid * 32 + mt * 16 + gid;
            mw[mt * 2 + 0] = *(const uint2*)(mb + (size_t)(qBase + rloc) * 32 + t * 2);
            mw[mt * 2 + 1] = *(const uint2*)(mb + (size_t)(qBase + rloc + 8) * 32 + t * 2);
        }

        // ---- S = Q K^T ----
        float s[2][8][4];
#pragma unroll
        for (int mt = 0; mt < 2; mt++)
#pragma unroll
            for (int nt = 0; nt < 8; nt++)
#pragma unroll
                for (int e = 0; e < 4; e++) s[mt][nt][e] = 0.f;

#pragma unroll
        for (int ks = 0; ks < 4; ks++) {
            uint32_t a[2][4];
#pragma unroll
            for (int mt = 0; mt < 2; mt++)
                ldsm_x4(a[mt][0], a[mt][1], a[mt][2], a[mt][3],
                        qB + mt * 16 * (QSTR * 4) + ks * 32);
#pragma unroll
            for (int ntp = 0; ntp < 4; ntp++) {
                uint32_t b0, b1, b2, b3;
                ldsm_x4(b0, b1, b2, b3, kB + ntp * 16 * (QSTR * 4) + ks * 32);
                mma_f16(s[0][2*ntp][0], s[0][2*ntp][1], s[0][2*ntp][2], s[0][2*ntp][3],
                        a[0][0], a[0][1], a[0][2], a[0][3], b0, b1);
                mma_f16(s[1][2*ntp][0], s[1][2*ntp][1], s[1][2*ntp][2], s[1][2*ntp][3],
                        a[1][0], a[1][1], a[1][2], a[1][3], b0, b1);
                mma_f16(s[0][2*ntp+1][0], s[0][2*ntp+1][1], s[0][2*ntp+1][2], s[0][2*ntp+1][3],
                        a[0][0], a[0][1], a[0][2], a[0][3], b2, b3);
                mma_f16(s[1][2*ntp+1][0], s[1][2*ntp+1][1], s[1][2*ntp+1][2], s[1][2*ntp+1][3],
                        a[1][0], a[1][1], a[1][2], a[1][3], b2, b3);
            }
        }

        // ---- mask + online softmax ----
#pragma unroll
        for (int mt = 0; mt < 2; mt++) {
            const uint2 w0 = mw[mt * 2 + 0];
            const uint2 w1 = mw[mt * 2 + 1];
            float mx0 = -1e30f, mx1 = -1e30f;
#pragma unroll
            for (int nt = 0; nt < 8; nt++) {
                const int sh = (nt & 3) * 8 + 2 * q;
                const uint32_t wa = (nt < 4) ? w0.x : w0.y;
                const uint32_t wb = (nt < 4) ? w1.x : w1.y;
                s[mt][nt][0] = ((wa >> sh) & 1u)       ? s[mt][nt][0] : -1e9f;
                s[mt][nt][1] = ((wa >> (sh + 1)) & 1u) ? s[mt][nt][1] : -1e9f;
                s[mt][nt][2] = ((wb >> sh) & 1u)       ? s[mt][nt][2] : -1e9f;
                s[mt][nt][3] = ((wb >> (sh + 1)) & 1u) ? s[mt][nt][3] : -1e9f;
                mx0 = fmaxf(mx0, fmaxf(s[mt][nt][0], s[mt][nt][1]));
                mx1 = fmaxf(mx1, fmaxf(s[mt][nt][2], s[mt][nt][3]));
            }
            mx0 = fmaxf(mx0, __shfl_xor_sync(0xffffffffu, mx0, 1));
            mx0 = fmaxf(mx0, __shfl_xor_sync(0xffffffffu, mx0, 2));
            mx1 = fmaxf(mx1, __shfl_xor_sync(0xffffffffu, mx1, 1));
            mx1 = fmaxf(mx1, __shfl_xor_sync(0xffffffffu, mx1, 2));
            const float mn0 = fmaxf(mreg[mt * 2 + 0], mx0);
            const float mn1 = fmaxf(mreg[mt * 2 + 1], mx1);
            const float corr0 = __expf(mreg[mt * 2 + 0] - mn0);
            const float corr1 = __expf(mreg[mt * 2 + 1] - mn1);

            float rs0 = 0.f, rs1 = 0.f;
#pragma unroll
            for (int nt = 0; nt < 8; nt++) {
                s[mt][nt][0] = __expf(s[mt][nt][0] - mn0);
                s[mt][nt][1] = __expf(s[mt][nt][1] - mn0);
                s[mt][nt][2] = __expf(s[mt][nt][2] - mn1);
                s[mt][nt][3] = __expf(s[mt][nt][3] - mn1);
                rs0 += s[mt][nt][0] + s[mt][nt][1];
                rs1 += s[mt][nt][2] + s[mt][nt][3];
            }
            rs0 += __shfl_xor_sync(0xffffffffu, rs0, 1);
            rs0 += __shfl_xor_sync(0xffffffffu, rs0, 2);
            rs1 += __shfl_xor_sync(0xffffffffu, rs1, 1);
            rs1 += __shfl_xor_sync(0xffffffffu, rs1, 2);
            lreg[mt * 2 + 0] = lreg[mt * 2 + 0] * corr0 + rs0;
            lreg[mt * 2 + 1] = lreg[mt * 2 + 1] * corr1 + rs1;
            mreg[mt * 2 + 0] = mn0;
            mreg[mt * 2 + 1] = mn1;
#pragma unroll
            for (int nt = 0; nt < 8; nt++) {
                o[mt][nt][0] *= corr0; o[mt][nt][1] *= corr0;
                o[mt][nt][2] *= corr1; o[mt][nt][3] *= corr1;
            }
        }

        // ---- O += P V : P A-frags are the lane's own s values, packed ----
#pragma unroll
        for (int ks = 0; ks < 4; ks++) {
            uint32_t a[2][4];
#pragma unroll
            for (int mt = 0; mt < 2; mt++) {
                a[mt][0] = packh2(s[mt][2*ks][0],   s[mt][2*ks][1]);
                a[mt][1] = packh2(s[mt][2*ks][2],   s[mt][2*ks][3]);
                a[mt][2] = packh2(s[mt][2*ks+1][0], s[mt][2*ks+1][1]);
                a[mt][3] = packh2(s[mt][2*ks+1][2], s[mt][2*ks+1][3]);
            }
#pragma unroll
            for (int ntp = 0; ntp < 4; ntp++) {
                uint32_t b0, b1, b2, b3;
                ldsm_x4t(b0, b1, b2, b3, vB + ks * 16 * (QSTR * 4) + ntp * 32);
                mma_f16(o[0][2*ntp][0], o[0][2*ntp][1], o[0][2*ntp][2], o[0][2*ntp][3],
                        a[0][0], a[0][1], a[0][2], a[0][3], b0, b1);
                mma_f16(o[1][2*ntp][0], o[1][2*ntp][1], o[1][2*ntp][2], o[1][2*ntp][3],
                        a[1][0], a[1][1], a[1][2], a[1][3], b0, b1);
                mma_f16(o[0][2*ntp+1][0], o[0][2*ntp+1][1], o[0][2*ntp+1][2], o[0][2*ntp+1][3],
                        a[0][0], a[0][1], a[0][2], a[0][3], b2, b3);
                mma_f16(o[1][2*ntp+1][0], o[1][2*ntp+1][1], o[1][2*ntp+1][2], o[1][2*ntp+1][3],
                        a[1][0], a[1][1], a[1][2], a[1][3], b2, b3);
            }
        }

        __syncthreads();
        if (t + 2 < 16) issue_kv((t + 2) * 64, t & 1);
    }

    // normalize + store fp16 CTX [b][n][h*64+d]
    __half* cbase = g_CTX + ((size_t)(b * Nn + qBase) * Hh) + h * DHd;
#pragma unroll
    for (int mt = 0; mt < 2; mt++) {
        const int r0 = wid * 32 + mt * 16 + gid;
        const int r1 = r0 + 8;
        const float inv0 = 1.f / lreg[mt * 2 + 0];
        const float inv1 = 1.f / lreg[mt * 2 + 1];
#pragma unroll
        for (int nt = 0; nt < 8; nt++) {
            const int d0 = nt * 8 + 2 * q;
            *(__half2*)(cbase + (size_t)r0 * Hh + d0) =
                __float22half2_rn(make_float2(o[mt][nt][0] * inv0, o[mt][nt][1] * inv0));
            *(__half2*)(cbase + (size_t)r1 * Hh + d0) =
                __float22half2_rn(make_float2(o[mt][nt][2] * inv1, o[mt][nt][3] * inv1));
        }
    }
}

// ---------------------------------------------------------------------------
// LayerNorm (eps=1e-12) over g_Y rows + gather the two per-batch rows.
// ---------------------------------------------------------------------------
__global__ void __launch_bounds__(256) ln_kernel(
    const float* __restrict__ gamma, const float* __restrict__ beta,
    const int* __restrict__ conv_len, float* __restrict__ out)
{
    const int row = blockIdx.x;
    const int tid = threadIdx.x;
    const float* yr = g_Y + (size_t)row * Hh;
    float4 x = *(const float4*)(yr + (tid << 2));

    __shared__ float red[8];
    __shared__ float mu_sh, rstd_sh;

    float s1 = x.x + x.y + x.z + x.w;
#pragma unroll
    for (int off = 16; off; off >>= 1) s1 += __shfl_xor_sync(0xffffffffu, s1, off);
    int w = tid >> 5, lane = tid & 31;
    if (lane == 0) red[w] = s1;
    __syncthreads();
    if (tid == 0) {
        float t = 0.f;
#pragma unroll
        for (int i = 0; i < 8; i++) t += red[i];
        mu_sh = t * (1.f / 1024.f);
    }
    __syncthreads();
    float mu = mu_sh;
    float d0 = x.x - mu, d1 = x.y - mu, d2 = x.z - mu, d3 = x.w - mu;
    float s2 = d0 * d0 + d1 * d1 + d2 * d2 + d3 * d3;
#pragma unroll
    for (int off = 16; off; off >>= 1) s2 += __shfl_xor_sync(0xffffffffu, s2, off);
    if (lane == 0) red[w] = s2;
    __syncthreads();
    if (tid == 0) {
        float t = 0.f;
#pragma unroll
        for (int i = 0; i < 8; i++) t += red[i];
        rstd_sh = rsqrtf(t * (1.f / 1024.f) + 1e-12f);
    }
    __syncthreads();
    float rstd = rstd_sh;

    float4 g = *(const float4*)(gamma + (tid << 2));
    float4 be = *(const float4*)(beta + (tid << 2));
    float4 r;
    r.x = d0 * rstd * g.x + be.x;
    r.y = d1 * rstd * g.y + be.y;
    r.z = d2 * rstd * g.z + be.z;
    r.w = d3 * rstd * g.w + be.w;
    *(float4*)(out + (size_t)row * Hh + (tid << 2)) = r;

    int b_ = row >> 10, n_ = row & 1023;
    int base = 6 * conv_len[b_];
    if (n_ == base + 3)
        *(float4*)(out + (size_t)Mm * Hh + (size_t)b_ * Hh + (tid << 2)) = r;
    if (n_ == base + 2)
        *(float4*)(out + (size_t)Mm * Hh + (size_t)Bb * Hh + (size_t)b_ * Hh + (tid << 2)) = r;
}

// ---------------------------------------------------------------------------
extern "C" void kernel_launch(void* const* d_in, const int* in_sizes, int n_in,
                              void* d_out, int out_size)
{
    const float* hidden    = (const float*)d_in[0];
    const int*   role_mask = (const int*)d_in[1];
    const int*   conv_len  = (const int*)d_in[2];
    const float* Wq = (const float*)d_in[3];
    const float* bq = (const float*)d_in[4];
    const float* Wk = (const float*)d_in[5];
    const float* bk = (const float*)d_in[6];
    const float* Wv = (const float*)d_in[7];
    const float* bv = (const float*)d_in[8];
    const float* Wo = (const float*)d_in[9];
    const float* bo = (const float*)d_in[10];
    const float* gamma = (const float*)d_in[11];
    const float* beta  = (const float*)d_in[12];
    float* out = (float*)d_out;

    __half *H16p, *WqTp, *WkTp, *WvTp, *WoTp, *Qp, *Kp, *Vp, *Cp;
    float *Yp;
    cudaGetSymbolAddress((void**)&H16p, g_H16);
    cudaGetSymbolAddress((void**)&WqTp, g_WqT);
    cudaGetSymbolAddress((void**)&WkTp, g_WkT);
    cudaGetSymbolAddress((void**)&WvTp, g_WvT);
    cudaGetSymbolAddress((void**)&WoTp, g_WoT);
    cudaGetSymbolAddress((void**)&Qp, g_Q);
    cudaGetSymbolAddress((void**)&Kp, g_K);
    cudaGetSymbolAddress((void**)&Vp, g_V);
    cudaGetSymbolAddress((void**)&Cp, g_CTX);
    cudaGetSymbolAddress((void**)&Yp, g_Y);

    cudaFuncSetAttribute(f16_gemm, cudaFuncAttributeMaxDynamicSharedMemorySize, GEMM_SMEM);
    cudaFuncSetAttribute(attn_mma, cudaFuncAttributeMaxDynamicSharedMemorySize, ATTN_SMEM);

    pack_mask<<<32768, 256>>>(role_mask);
    conv_hidden<<<4096, 256>>>(hidden);
    convT_w<<<dim3(32, 32, 4), dim3(32, 8)>>>(Wq, Wk, Wv, Wo);

    // fused QKV (z selects weight/bias/output)
    f16_gemm<<<dim3(8, 64, 3), 256, GEMM_SMEM>>>(
        H16p, WqTp, WkTp, WvTp, bq, bk, bv, Qp, Kp, Vp, nullptr, 0);

    attn_mma<<<dim3(Nn / 128, Bb * NHEADS), 128, ATTN_SMEM>>>();

    f16_gemm<<<dim3(8, 64, 1), 256, GEMM_SMEM>>>(
        Cp, WoTp, WoTp, WoTp, bo, bo, bo, Yp, Yp, Yp, hidden, 1);

    ln_kernel<<<Mm, 256>>>(gamma, beta, conv_len, out);
}